// round 6
// baseline (speedup 1.0000x reference)
#include <cuda_runtime.h>
#include <math.h>

#define NTOK 2048
#define DM   1024
#define NH   16
#define NKV  4
#define DHD  64
#define NEXP 8
#define FF   2048
#define CHN  64
#define EPSV 1e-6f

// ---------------- scratch (device globals; no allocation allowed) ----------------
__device__ float g_h1[NTOK * DM];
__device__ float g_q[NTOK * NH * DHD];
__device__ float g_k[NTOK * NKV * DHD];
__device__ float g_v[NTOK * NKV * DHD];
__device__ float g_oh[NTOK * NH * DHD];
__device__ float g_o[NTOK * DM];
__device__ float g_ctrl[NTOK * CHN];
__device__ float g_co[NTOK * 3 * DM];
__device__ float g_x2[NTOK * DM];
__device__ float g_mid[NTOK * FF];
__device__ int   g_cnt[NEXP];
__device__ int   g_toklist[NEXP * NTOK];

// ---------------- rmsnorm over D=1024 ----------------
__global__ void rmsnorm_kernel(const float* __restrict__ x, const float* __restrict__ w,
                               float* __restrict__ out) {
    int n = blockIdx.x;
    int t = threadIdx.x;  // 256 threads, 4 floats each
    const float4* xr = reinterpret_cast<const float4*>(x + (size_t)n * DM);
    float4 v = xr[t];
    __shared__ float red[256];
    red[t] = v.x * v.x + v.y * v.y + v.z * v.z + v.w * v.w;
    __syncthreads();
    for (int s = 128; s > 0; s >>= 1) {
        if (t < s) red[t] += red[t + s];
        __syncthreads();
    }
    float sc = rsqrtf(red[0] * (1.0f / DM) + EPSV);
    float4 wv = reinterpret_cast<const float4*>(w)[t];
    float4 o = make_float4(v.x * sc * wv.x, v.y * sc * wv.y, v.z * sc * wv.z, v.w * sc * wv.w);
    reinterpret_cast<float4*>(out + (size_t)n * DM)[t] = o;
}

// ---------------- generic tiled GEMM: C = A1@B1 (+ A2@B2) [+ bias] [silu] ----------------
// A: (rows x Kd) row-major, B: (Kd x Nc) row-major, C: (rows x Nc).
// Tiles: 64x64x16, 256 threads, 4x4 per thread. epi: 0 none, 1 +bias, 2 +bias then silu
__global__ __launch_bounds__(256) void gemm_kernel(
    const float* __restrict__ A1, const float* __restrict__ A2,
    const float* __restrict__ B1, const float* __restrict__ B2,
    const float* __restrict__ bias, float* __restrict__ C,
    int Kd, int Nc, int epi) {
    __shared__ __align__(16) float As[16 * 68];
    __shared__ __align__(16) float Bs[16 * 64];
    int m0 = blockIdx.y * 64, n0 = blockIdx.x * 64;
    int tid = threadIdx.x;
    int tx = tid & 15, ty = tid >> 4;
    float acc[4][4];
#pragma unroll
    for (int i = 0; i < 4; i++)
#pragma unroll
        for (int j = 0; j < 4; j++) acc[i][j] = 0.f;

    int nparts = (A2 != nullptr) ? 2 : 1;
    for (int part = 0; part < nparts; ++part) {
        const float* A = part ? A2 : A1;
        const float* B = part ? B2 : B1;
        for (int kk = 0; kk < Kd; kk += 16) {
            int idx = tid * 4;
            int arow = idx >> 4, ak = idx & 15;
            float4 av = *reinterpret_cast<const float4*>(A + (size_t)(m0 + arow) * Kd + kk + ak);
            As[(ak + 0) * 68 + arow] = av.x;
            As[(ak + 1) * 68 + arow] = av.y;
            As[(ak + 2) * 68 + arow] = av.z;
            As[(ak + 3) * 68 + arow] = av.w;
            int bk = idx >> 6, bn = idx & 63;
            *reinterpret_cast<float4*>(&Bs[bk * 64 + bn]) =
                *reinterpret_cast<const float4*>(B + (size_t)(kk + bk) * Nc + n0 + bn);
            __syncthreads();
#pragma unroll
            for (int k = 0; k < 16; k++) {
                float4 a = *reinterpret_cast<const float4*>(&As[k * 68 + ty * 4]);
                float4 b = *reinterpret_cast<const float4*>(&Bs[k * 64 + tx * 4]);
                float ar[4] = {a.x, a.y, a.z, a.w};
                float br[4] = {b.x, b.y, b.z, b.w};
#pragma unroll
                for (int i = 0; i < 4; i++)
#pragma unroll
                    for (int j = 0; j < 4; j++) acc[i][j] += ar[i] * br[j];
            }
            __syncthreads();
        }
    }
#pragma unroll
    for (int i = 0; i < 4; i++) {
        int row = m0 + ty * 4 + i;
#pragma unroll
        for (int j = 0; j < 4; j++) {
            int col = n0 + tx * 4 + j;
            float v = acc[i][j];
            if (epi >= 1) v += bias[col];
            if (epi == 2) v = v / (1.f + __expf(-v));  // silu
            C[(size_t)row * Nc + col] = v;
        }
    }
}

// ---------------- per-(token,head) rmsnorm + RoPE for q and k ----------------
__global__ void qknorm_rope_kernel(const int* __restrict__ positions,
                                   const float* __restrict__ qw, const float* __restrict__ kw) {
    int n = blockIdx.x;
    int hh = blockIdx.y;  // 0..NH-1 => q, NH..NH+NKV-1 => k
    int d = threadIdx.x;  // 0..63
    float* ptr;
    const float* w;
    if (hh < NH) { ptr = g_q + (size_t)n * (NH * DHD) + hh * DHD; w = qw; }
    else         { ptr = g_k + (size_t)n * (NKV * DHD) + (hh - NH) * DHD; w = kw; }
    float x = ptr[d];
    __shared__ float sh[64];
    __shared__ float xs[64];
    sh[d] = x * x;
    __syncthreads();
    for (int s = 32; s > 0; s >>= 1) {
        if (d < s) sh[d] += sh[d + s];
        __syncthreads();
    }
    float sc = rsqrtf(sh[0] * (1.0f / DHD) + EPSV);
    float xn = x * sc * w[d];
    xs[d] = xn;
    __syncthreads();
    float pos = (float)positions[n];
    int i = d & 31;
    // inv_freq = 10000^(-2i/64) computed in double, rounded to fp32 (matches XLA to ~1 ulp)
    float inv = (float)exp(-((double)(2 * i) / 64.0) * log(10000.0));
    float ang = pos * inv;
    float c = cosf(ang), s = sinf(ang);
    // first half:  x1*c - x2*s ; second half: x2*c + x1*s  (BUG FIX: was x1*c + x2*s)
    float out = (d < 32) ? (xn * c - xs[d + 32] * s) : (xn * c + xs[d - 32] * s);
    ptr[d] = out;
}

// ---------------- flash attention (non-causal, GQA H=16 over KV=4) ----------------
__global__ __launch_bounds__(128) void attn_kernel() {
    int h = blockIdx.y;
    int qi = blockIdx.x * 128 + threadIdx.x;
    int kvh = h >> 2;  // groups = 4
    __shared__ __align__(16) float ks[64 * 64];
    __shared__ __align__(16) float vs[64 * 64];
    float q[64], acc[64];
    const float* qrow = g_q + (size_t)qi * (NH * DHD) + h * DHD;
#pragma unroll
    for (int d = 0; d < 64; d += 4) {
        float4 t = *reinterpret_cast<const float4*>(qrow + d);
        q[d] = t.x * 0.125f; q[d + 1] = t.y * 0.125f;
        q[d + 2] = t.z * 0.125f; q[d + 3] = t.w * 0.125f;
        acc[d] = 0.f; acc[d + 1] = 0.f; acc[d + 2] = 0.f; acc[d + 3] = 0.f;
    }
    float mrun = -1e30f, lrun = 0.f;
    for (int kt = 0; kt < NTOK; kt += 64) {
#pragma unroll
        for (int i = 0; i < 8; i++) {
            int idx = threadIdx.x + i * 128;  // float4 index within 64x64 tile
            int m = idx >> 4;
            int dc = (idx & 15) << 2;
            *reinterpret_cast<float4*>(&ks[m * 64 + dc]) =
                *reinterpret_cast<const float4*>(g_k + (size_t)(kt + m) * (NKV * DHD) + kvh * DHD + dc);
            *reinterpret_cast<float4*>(&vs[m * 64 + dc]) =
                *reinterpret_cast<const float4*>(g_v + (size_t)(kt + m) * (NKV * DHD) + kvh * DHD + dc);
        }
        __syncthreads();
#pragma unroll 1
        for (int m = 0; m < 64; m++) {
            const float4* kr = reinterpret_cast<const float4*>(&ks[m * 64]);
            float s0 = 0.f, s1 = 0.f, s2 = 0.f, s3 = 0.f;
#pragma unroll
            for (int d4 = 0; d4 < 16; d4++) {
                float4 kv = kr[d4];
                s0 += q[d4 * 4 + 0] * kv.x; s1 += q[d4 * 4 + 1] * kv.y;
                s2 += q[d4 * 4 + 2] * kv.z; s3 += q[d4 * 4 + 3] * kv.w;
            }
            float s = (s0 + s1) + (s2 + s3);
            if (s > mrun) {
                float corr = __expf(mrun - s);
                lrun *= corr;
#pragma unroll
                for (int d = 0; d < 64; d++) acc[d] *= corr;
                mrun = s;
            }
            float p = __expf(s - mrun);
            lrun += p;
            const float4* vr = reinterpret_cast<const float4*>(&vs[m * 64]);
#pragma unroll
            for (int d4 = 0; d4 < 16; d4++) {
                float4 vv = vr[d4];
                acc[d4 * 4 + 0] += p * vv.x; acc[d4 * 4 + 1] += p * vv.y;
                acc[d4 * 4 + 2] += p * vv.z; acc[d4 * 4 + 3] += p * vv.w;
            }
        }
        __syncthreads();
    }
    float rl = 1.f / lrun;
    float* orow = g_oh + (size_t)qi * (NH * DHD) + h * DHD;
#pragma unroll
    for (int d = 0; d < 64; d += 4) {
        float4 o = make_float4(acc[d] * rl, acc[d + 1] * rl, acc[d + 2] * rl, acc[d + 3] * rl);
        *reinterpret_cast<float4*>(orow + d) = o;
    }
}

// ---------------- control dynamics elementwise ----------------
__global__ void dynamics_kernel(const float* __restrict__ hidden, const float* __restrict__ velocity,
                                const float* __restrict__ mu, float* __restrict__ out_h2,
                                float* __restrict__ out_vn) {
    int idx = blockIdx.x * 256 + threadIdx.x;
    int n = idx >> 10;
    int d = idx & 1023;
    const float* co = g_co + (size_t)n * 3 * DM;
    float ar = co[d], br = co[DM + d], gr = co[2 * DM + d];
    float alpha = 1.f / (1.f + expf(-ar));
    float sp = fmaxf(br, 0.f) + log1pf(expf(-fabsf(br)));  // stable softplus
    float beta = fminf(sp, 2.f);
    float gate = 1.f / (1.f + expf(-gr));
    float o = g_o[idx], mv = mu[idx], vel = velocity[idx];
    float vn = alpha * vel - beta * (o - mv);
    vn = fminf(fmaxf(vn, -10.f), 10.f);
    out_h2[idx] = hidden[idx] + o + 0.1f * gate * vn;
    out_vn[idx] = vn;
}

// ---------------- router: mu_logits + one-hot(base)*10, argmax, token lists ----------------
__global__ void zero_cnt_kernel() {
    if (threadIdx.x < NEXP) g_cnt[threadIdx.x] = 0;
}

__global__ void router_kernel(const float* __restrict__ mu, const int* __restrict__ token_ids,
                              const float* __restrict__ Wr) {
    int tid = threadIdx.x;       // 256 = 32 tokens x 8 experts
    int tl = tid >> 3, e = tid & 7;
    int n = blockIdx.x * 32 + tl;
    const float* mr = mu + (size_t)n * DM;
    float s = 0.f;
    for (int d = 0; d < DM; d++) s += mr[d] * Wr[d * NEXP + e];
    __shared__ float lg[32][8];
    lg[tl][e] = s;
    __syncthreads();
    if (e == 0) {
        int base = token_ids[n] % NEXP;
        float best = -1e30f;
        int bi = 0;
#pragma unroll
        for (int j = 0; j < 8; j++) {
            float c = lg[tl][j] + (j == base ? 10.0f : 0.0f);
            if (c > best) { best = c; bi = j; }  // strict > => first-max tie rule
        }
        int slot = atomicAdd(&g_cnt[bi], 1);
        g_toklist[bi * NTOK + slot] = n;
    }
}

// ---------------- MoE stage A: mid = silu(X@Wg[e]) * (X@Wu[e]), grouped by expert ----------------
__global__ __launch_bounds__(256) void moe_gateup_kernel(const float* __restrict__ X,
                                                         const float* __restrict__ Wg,
                                                         const float* __restrict__ Wu) {
    int e = blockIdx.z;
    int count = g_cnt[e];
    int m0 = blockIdx.y * 64;
    if (m0 >= count) return;
    int f0 = blockIdx.x * 64;
    __shared__ int toks[64];
    __shared__ __align__(16) float Xs[16 * 68];
    __shared__ __align__(16) float Gs[16 * 64];
    __shared__ __align__(16) float Us[16 * 64];
    int tid = threadIdx.x;
    if (tid < 64) toks[tid] = (m0 + tid < count) ? g_toklist[e * NTOK + m0 + tid] : -1;
    __syncthreads();
    const float* WgE = Wg + (size_t)e * DM * FF;
    const float* WuE = Wu + (size_t)e * DM * FF;
    int tx = tid & 15, ty = tid >> 4;
    float ag[4][4], au[4][4];
#pragma unroll
    for (int i = 0; i < 4; i++)
#pragma unroll
        for (int j = 0; j < 4; j++) { ag[i][j] = 0.f; au[i][j] = 0.f; }

    for (int kk = 0; kk < DM; kk += 16) {
        int idx = tid * 4;
        int arow = idx >> 4, ak = idx & 15;
        int t = toks[arow];
        float4 xv = make_float4(0.f, 0.f, 0.f, 0.f);
        if (t >= 0) xv = *reinterpret_cast<const float4*>(X + (size_t)t * DM + kk + ak);
        Xs[(ak + 0) * 68 + arow] = xv.x;
        Xs[(ak + 1) * 68 + arow] = xv.y;
        Xs[(ak + 2) * 68 + arow] = xv.z;
        Xs[(ak + 3) * 68 + arow] = xv.w;
        int bk = idx >> 6, bn = idx & 63;
        *reinterpret_cast<float4*>(&Gs[bk * 64 + bn]) =
            *reinterpret_cast<const float4*>(WgE + (size_t)(kk + bk) * FF + f0 + bn);
        *reinterpret_cast<float4*>(&Us[bk * 64 + bn]) =
            *reinterpret_cast<const float4*>(WuE + (size_t)(kk + bk) * FF + f0 + bn);
        __syncthreads();
#pragma unroll
        for (int k = 0; k < 16; k++) {
            float4 a = *reinterpret_cast<const float4*>(&Xs[k * 68 + ty * 4]);
            float4 g = *reinterpret_cast<const float4*>(&Gs[k * 64 + tx * 4]);
            float4 u = *reinterpret_cast<const float4*>(&Us[k * 64 + tx * 4]);
            float arr[4] = {a.x, a.y, a.z, a.w};
            float grr[4] = {g.x, g.y, g.z, g.w};
            float urr[4] = {u.x, u.y, u.z, u.w};
#pragma unroll
            for (int i = 0; i < 4; i++)
#pragma unroll
                for (int j = 0; j < 4; j++) {
                    ag[i][j] += arr[i] * grr[j];
                    au[i][j] += arr[i] * urr[j];
                }
        }
        __syncthreads();
    }
#pragma unroll
    for (int i = 0; i < 4; i++) {
        int t = toks[ty * 4 + i];
        if (t < 0) continue;
#pragma unroll
        for (int j = 0; j < 4; j++) {
            float g = ag[i][j], u = au[i][j];
            float m = (g / (1.f + __expf(-g))) * u;
            g_mid[(size_t)t * FF + f0 + tx * 4 + j] = m;
        }
    }
}

// ---------------- MoE stage B: out[tok] += mid[tok] @ Wd[e] ----------------
__global__ __launch_bounds__(256) void moe_down_kernel(const float* __restrict__ Wd,
                                                       float* __restrict__ out) {
    int e = blockIdx.z;
    int count = g_cnt[e];
    int m0 = blockIdx.y * 64;
    if (m0 >= count) return;
    int d0 = blockIdx.x * 64;
    __shared__ int toks[64];
    __shared__ __align__(16) float Ms[16 * 68];
    __shared__ __align__(16) float Bs[16 * 64];
    int tid = threadIdx.x;
    if (tid < 64) toks[tid] = (m0 + tid < count) ? g_toklist[e * NTOK + m0 + tid] : -1;
    __syncthreads();
    const float* W = Wd + (size_t)e * FF * DM;
    int tx = tid & 15, ty = tid >> 4;
    float acc[4][4];
#pragma unroll
    for (int i = 0; i < 4; i++)
#pragma unroll
        for (int j = 0; j < 4; j++) acc[i][j] = 0.f;

    for (int kk = 0; kk < FF; kk += 16) {
        int idx = tid * 4;
        int arow = idx >> 4, ak = idx & 15;
        int t = toks[arow];
        float4 mv = make_float4(0.f, 0.f, 0.f, 0.f);
        if (t >= 0) mv = *reinterpret_cast<const float4*>(g_mid + (size_t)t * FF + kk + ak);
        Ms[(ak + 0) * 68 + arow] = mv.x;
        Ms[(ak + 1) * 68 + arow] = mv.y;
        Ms[(ak + 2) * 68 + arow] = mv.z;
        Ms[(ak + 3) * 68 + arow] = mv.w;
        int bk = idx >> 6, bn = idx & 63;
        *reinterpret_cast<float4*>(&Bs[bk * 64 + bn]) =
            *reinterpret_cast<const float4*>(W + (size_t)(kk + bk) * DM + d0 + bn);
        __syncthreads();
#pragma unroll
        for (int k = 0; k < 16; k++) {
            float4 a = *reinterpret_cast<const float4*>(&Ms[k * 68 + ty * 4]);
            float4 b = *reinterpret_cast<const float4*>(&Bs[k * 64 + tx * 4]);
            float ar[4] = {a.x, a.y, a.z, a.w};
            float br[4] = {b.x, b.y, b.z, b.w};
#pragma unroll
            for (int i = 0; i < 4; i++)
#pragma unroll
                for (int j = 0; j < 4; j++) acc[i][j] += ar[i] * br[j];
        }
        __syncthreads();
    }
#pragma unroll
    for (int i = 0; i < 4; i++) {
        int t = toks[ty * 4 + i];
        if (t < 0) continue;
#pragma unroll
        for (int j = 0; j < 4; j++) {
            out[(size_t)t * DM + d0 + tx * 4 + j] += acc[i][j];  // residual2 already stored
        }
    }
}

// ---------------- host orchestration ----------------
extern "C" void kernel_launch(void* const* d_in, const int* in_sizes, int n_in,
                              void* d_out, int out_size) {
    const float* hidden     = (const float*)d_in[0];
    const int*   positions  = (const int*)d_in[1];
    const float* velocity   = (const float*)d_in[2];
    const int*   token_ids  = (const int*)d_in[3];
    const float* mu_prev    = (const float*)d_in[4];
    const float* ln1_w      = (const float*)d_in[5];
    const float* ln2_w      = (const float*)d_in[6];
    const float* wq         = (const float*)d_in[7];
    const float* wk         = (const float*)d_in[8];
    const float* wv         = (const float*)d_in[9];
    const float* wo_w       = (const float*)d_in[10];
    const float* w_mu_q     = (const float*)d_in[11];
    const float* w_mu_k     = (const float*)d_in[12];
    const float* w_mu_v     = (const float*)d_in[13];
    const float* qnorm_w    = (const float*)d_in[14];
    const float* knorm_w    = (const float*)d_in[15];
    const float* dyn_mu     = (const float*)d_in[16];
    const float* dyn_proj   = (const float*)d_in[17];
    const float* ctrl_in_w  = (const float*)d_in[18];
    const float* ctrl_in_b  = (const float*)d_in[19];
    const float* ctrl_out_w = (const float*)d_in[20];
    const float* ctrl_out_b = (const float*)d_in[21];
    const float* mu_router  = (const float*)d_in[22];
    const float* w_gate     = (const float*)d_in[23];
    const float* w_up       = (const float*)d_in[24];
    const float* w_down     = (const float*)d_in[25];

    float* out    = (float*)d_out;
    float* out_h  = out;                          // hidden
    float* out_vn = out + (size_t)NTOK * DM;      // v_next
    float* out_mu = out + 2 * (size_t)NTOK * DM;  // mu_cur

    float *p_h1, *p_q, *p_k, *p_v, *p_oh, *p_o, *p_ctrl, *p_co, *p_x2;
    cudaGetSymbolAddress((void**)&p_h1, g_h1);
    cudaGetSymbolAddress((void**)&p_q, g_q);
    cudaGetSymbolAddress((void**)&p_k, g_k);
    cudaGetSymbolAddress((void**)&p_v, g_v);
    cudaGetSymbolAddress((void**)&p_oh, g_oh);
    cudaGetSymbolAddress((void**)&p_o, g_o);
    cudaGetSymbolAddress((void**)&p_ctrl, g_ctrl);
    cudaGetSymbolAddress((void**)&p_co, g_co);
    cudaGetSymbolAddress((void**)&p_x2, g_x2);

    // 1. h = rmsnorm(hidden, ln1_w)
    rmsnorm_kernel<<<NTOK, 256>>>(hidden, ln1_w, p_h1);

    // 2. q/k/v = h@W* + mu_prev@W_mu* (dual-A GEMMs)
    gemm_kernel<<<dim3((NH * DHD) / 64, NTOK / 64), 256>>>(p_h1, mu_prev, wq, w_mu_q, nullptr,
                                                           p_q, DM, NH * DHD, 0);
    gemm_kernel<<<dim3((NKV * DHD) / 64, NTOK / 64), 256>>>(p_h1, mu_prev, wk, w_mu_k, nullptr,
                                                            p_k, DM, NKV * DHD, 0);
    gemm_kernel<<<dim3((NKV * DHD) / 64, NTOK / 64), 256>>>(p_h1, mu_prev, wv, w_mu_v, nullptr,
                                                            p_v, DM, NKV * DHD, 0);

    // 3. per-head rmsnorm + RoPE on q, k
    qknorm_rope_kernel<<<dim3(NTOK, NH + NKV), 64>>>(positions, qnorm_w, knorm_w);

    // 4. flash attention -> g_oh
    attn_kernel<<<dim3(NTOK / 128, NH), 128>>>();

    // 5. o = oh @ wo
    gemm_kernel<<<dim3(DM / 64, NTOK / 64), 256>>>(p_oh, nullptr, wo_w, nullptr, nullptr,
                                                   p_o, NH * DHD, DM, 0);

    // 6. mu_cur = dyn_mu + o @ dyn_mu_proj_w  (written straight into d_out section 3)
    gemm_kernel<<<dim3(DM / 64, NTOK / 64), 256>>>(p_o, nullptr, dyn_proj, nullptr, dyn_mu,
                                                   out_mu, DM, DM, 1);

    // 7. ctrl = silu([o | velocity] @ ctrl_in_w + b)  (dual-A, silu epilogue)
    gemm_kernel<<<dim3(CHN / 64, NTOK / 64), 256>>>(p_o, velocity, ctrl_in_w,
                                                    ctrl_in_w + (size_t)DM * CHN, ctrl_in_b,
                                                    p_ctrl, DM, CHN, 2);

    // 8. co = ctrl @ ctrl_out_w + ctrl_out_b
    gemm_kernel<<<dim3((3 * DM) / 64, NTOK / 64), 256>>>(p_ctrl, nullptr, ctrl_out_w, nullptr,
                                                         ctrl_out_b, p_co, CHN, 3 * DM, 1);

    // 9. dynamics: v_next, hidden2 (hidden2 stored in d_out section 1, MoE adds y later)
    dynamics_kernel<<<(NTOK * DM) / 256, 256>>>(hidden, velocity, out_mu, out_h, out_vn);

    // 10. x = rmsnorm(hidden2, ln2_w)
    rmsnorm_kernel<<<NTOK, 256>>>(out_h, ln2_w, p_x2);

    // 11. routing: expert per token, grouped lists
    zero_cnt_kernel<<<1, 32>>>();
    router_kernel<<<NTOK / 32, 256>>>(out_mu, token_ids, mu_router);

    // 12. MoE (only selected expert per token — 8x fewer FLOPs than reference einsum)
    moe_gateup_kernel<<<dim3(FF / 64, NTOK / 64, NEXP), 256>>>(p_x2, w_gate, w_up);
    moe_down_kernel<<<dim3(DM / 64, NTOK / 64, NEXP), 256>>>(w_down, out_h);
}

// round 8
// speedup vs baseline: 1.2192x; 1.2192x over previous
#include <cuda_runtime.h>
#include <math.h>

#define NTOK 2048
#define DM   1024
#define NH   16
#define NKV  4
#define DHD  64
#define NEXP 8
#define FF   2048
#define CHN  64
#define EPSV 1e-6f

// ---------------- scratch (device globals; no allocation allowed) ----------------
__device__ float g_h1[NTOK * DM];
__device__ float g_q[NTOK * NH * DHD];
__device__ float g_k[NTOK * NKV * DHD];
__device__ float g_v[NTOK * NKV * DHD];
__device__ float g_oh[NTOK * NH * DHD];
__device__ float g_o[NTOK * DM];
__device__ float g_ctrl[NTOK * CHN];
__device__ float g_co[NTOK * 3 * DM];
__device__ float g_x2[NTOK * DM];
__device__ float g_mid[NTOK * FF];
__device__ int   g_cnt[NEXP];
__device__ int   g_toklist[NEXP * NTOK];

// ---------------- tf32 helpers ----------------
__device__ __forceinline__ unsigned f2tf(float f) {
    unsigned u;
    asm("cvt.rna.tf32.f32 %0, %1;" : "=r"(u) : "f"(f));
    return u;
}
__device__ __forceinline__ void mma_tf32(float& c0, float& c1, float& c2, float& c3,
                                         unsigned a0, unsigned a1, unsigned a2, unsigned a3,
                                         unsigned b0, unsigned b1) {
    asm("mma.sync.aligned.m16n8k8.row.col.f32.tf32.tf32.f32 "
        "{%0,%1,%2,%3},{%4,%5,%6,%7},{%8,%9},{%0,%1,%2,%3};"
        : "+f"(c0), "+f"(c1), "+f"(c2), "+f"(c3)
        : "r"(a0), "r"(a1), "r"(a2), "r"(a3), "r"(b0), "r"(b1));
}

// ---------------- rmsnorm over D=1024 ----------------
__global__ void rmsnorm_kernel(const float* __restrict__ x, const float* __restrict__ w,
                               float* __restrict__ out) {
    int n = blockIdx.x;
    int t = threadIdx.x;  // 256 threads, 4 floats each
    const float4* xr = reinterpret_cast<const float4*>(x + (size_t)n * DM);
    float4 v = xr[t];
    __shared__ float red[256];
    red[t] = v.x * v.x + v.y * v.y + v.z * v.z + v.w * v.w;
    __syncthreads();
    for (int s = 128; s > 0; s >>= 1) {
        if (t < s) red[t] += red[t + s];
        __syncthreads();
    }
    float sc = rsqrtf(red[0] * (1.0f / DM) + EPSV);
    float4 wv = reinterpret_cast<const float4*>(w)[t];
    float4 o = make_float4(v.x * sc * wv.x, v.y * sc * wv.y, v.z * sc * wv.z, v.w * sc * wv.w);
    reinterpret_cast<float4*>(out + (size_t)n * DM)[t] = o;
}

// ---------------- generic tiled GEMM: C = A1@B1 (+ A2@B2) [+ bias] [silu] (fp32) ----------
__global__ __launch_bounds__(256) void gemm_kernel(
    const float* __restrict__ A1, const float* __restrict__ A2,
    const float* __restrict__ B1, const float* __restrict__ B2,
    const float* __restrict__ bias, float* __restrict__ C,
    int Kd, int Nc, int epi) {
    __shared__ __align__(16) float As[16 * 68];
    __shared__ __align__(16) float Bs[16 * 64];
    int m0 = blockIdx.y * 64, n0 = blockIdx.x * 64;
    int tid = threadIdx.x;
    int tx = tid & 15, ty = tid >> 4;
    float acc[4][4];
#pragma unroll
    for (int i = 0; i < 4; i++)
#pragma unroll
        for (int j = 0; j < 4; j++) acc[i][j] = 0.f;

    int nparts = (A2 != nullptr) ? 2 : 1;
    for (int part = 0; part < nparts; ++part) {
        const float* A = part ? A2 : A1;
        const float* B = part ? B2 : B1;
        for (int kk = 0; kk < Kd; kk += 16) {
            int idx = tid * 4;
            int arow = idx >> 4, ak = idx & 15;
            float4 av = *reinterpret_cast<const float4*>(A + (size_t)(m0 + arow) * Kd + kk + ak);
            As[(ak + 0) * 68 + arow] = av.x;
            As[(ak + 1) * 68 + arow] = av.y;
            As[(ak + 2) * 68 + arow] = av.z;
            As[(ak + 3) * 68 + arow] = av.w;
            int bk = idx >> 6, bn = idx & 63;
            *reinterpret_cast<float4*>(&Bs[bk * 64 + bn]) =
                *reinterpret_cast<const float4*>(B + (size_t)(kk + bk) * Nc + n0 + bn);
            __syncthreads();
#pragma unroll
            for (int k = 0; k < 16; k++) {
                float4 a = *reinterpret_cast<const float4*>(&As[k * 68 + ty * 4]);
                float4 b = *reinterpret_cast<const float4*>(&Bs[k * 64 + tx * 4]);
                float ar[4] = {a.x, a.y, a.z, a.w};
                float br[4] = {b.x, b.y, b.z, b.w};
#pragma unroll
                for (int i = 0; i < 4; i++)
#pragma unroll
                    for (int j = 0; j < 4; j++) acc[i][j] += ar[i] * br[j];
            }
            __syncthreads();
        }
    }
#pragma unroll
    for (int i = 0; i < 4; i++) {
        int row = m0 + ty * 4 + i;
#pragma unroll
        for (int j = 0; j < 4; j++) {
            int col = n0 + tx * 4 + j;
            float v = acc[i][j];
            if (epi >= 1) v += bias[col];
            if (epi == 2) v = v / (1.f + __expf(-v));  // silu
            C[(size_t)row * Nc + col] = v;
        }
    }
}

// ---------------- fused qkv GEMM: one launch over all 1536 output cols (fp32) -----------
// n-tile 0..15 -> q (wq/w_mu_q, Nc=1024), 16..19 -> k, 20..23 -> v
__global__ __launch_bounds__(256) void qkv_kernel(
    const float* __restrict__ A1, const float* __restrict__ A2,
    const float* __restrict__ wq, const float* __restrict__ wmq,
    const float* __restrict__ wk, const float* __restrict__ wmk,
    const float* __restrict__ wv, const float* __restrict__ wmv) {
    __shared__ __align__(16) float As[16 * 68];
    __shared__ __align__(16) float Bs[16 * 64];
    int nt = blockIdx.x;
    int m0 = blockIdx.y * 64;
    const float *B1, *B2;
    float* C;
    int Nc, n0;
    if (nt < 16)      { B1 = wq; B2 = wmq; C = g_q; Nc = NH * DHD;  n0 = nt * 64; }
    else if (nt < 20) { B1 = wk; B2 = wmk; C = g_k; Nc = NKV * DHD; n0 = (nt - 16) * 64; }
    else              { B1 = wv; B2 = wmv; C = g_v; Nc = NKV * DHD; n0 = (nt - 20) * 64; }

    int tid = threadIdx.x;
    int tx = tid & 15, ty = tid >> 4;
    float acc[4][4];
#pragma unroll
    for (int i = 0; i < 4; i++)
#pragma unroll
        for (int j = 0; j < 4; j++) acc[i][j] = 0.f;

    for (int part = 0; part < 2; ++part) {
        const float* A = part ? A2 : A1;
        const float* B = part ? B2 : B1;
        for (int kk = 0; kk < DM; kk += 16) {
            int idx = tid * 4;
            int arow = idx >> 4, ak = idx & 15;
            float4 av = *reinterpret_cast<const float4*>(A + (size_t)(m0 + arow) * DM + kk + ak);
            As[(ak + 0) * 68 + arow] = av.x;
            As[(ak + 1) * 68 + arow] = av.y;
            As[(ak + 2) * 68 + arow] = av.z;
            As[(ak + 3) * 68 + arow] = av.w;
            int bk = idx >> 6, bn = idx & 63;
            *reinterpret_cast<float4*>(&Bs[bk * 64 + bn]) =
                *reinterpret_cast<const float4*>(B + (size_t)(kk + bk) * Nc + n0 + bn);
            __syncthreads();
#pragma unroll
            for (int k = 0; k < 16; k++) {
                float4 a = *reinterpret_cast<const float4*>(&As[k * 68 + ty * 4]);
                float4 b = *reinterpret_cast<const float4*>(&Bs[k * 64 + tx * 4]);
                float ar[4] = {a.x, a.y, a.z, a.w};
                float br[4] = {b.x, b.y, b.z, b.w};
#pragma unroll
                for (int i = 0; i < 4; i++)
#pragma unroll
                    for (int j = 0; j < 4; j++) acc[i][j] += ar[i] * br[j];
            }
            __syncthreads();
        }
    }
#pragma unroll
    for (int i = 0; i < 4; i++) {
        int row = m0 + ty * 4 + i;
#pragma unroll
        for (int j = 0; j < 4; j++) {
            C[(size_t)row * Nc + n0 + tx * 4 + j] = acc[i][j];
        }
    }
}

// ---------------- per-(token,head) rmsnorm + RoPE for q and k ----------------
__global__ void qknorm_rope_kernel(const int* __restrict__ positions,
                                   const float* __restrict__ qw, const float* __restrict__ kw) {
    int n = blockIdx.x;
    int hh = blockIdx.y;  // 0..NH-1 => q, NH..NH+NKV-1 => k
    int d = threadIdx.x;  // 0..63
    float* ptr;
    const float* w;
    if (hh < NH) { ptr = g_q + (size_t)n * (NH * DHD) + hh * DHD; w = qw; }
    else         { ptr = g_k + (size_t)n * (NKV * DHD) + (hh - NH) * DHD; w = kw; }
    float x = ptr[d];
    __shared__ float sh[64];
    __shared__ float xs[64];
    sh[d] = x * x;
    __syncthreads();
    for (int s = 32; s > 0; s >>= 1) {
        if (d < s) sh[d] += sh[d + s];
        __syncthreads();
    }
    float sc = rsqrtf(sh[0] * (1.0f / DHD) + EPSV);
    float xn = x * sc * w[d];
    xs[d] = xn;
    __syncthreads();
    float pos = (float)positions[n];
    int i = d & 31;
    float inv = (float)exp(-((double)(2 * i) / 64.0) * log(10000.0));
    float ang = pos * inv;
    float c = cosf(ang), s = sinf(ang);
    float out = (d < 32) ? (xn * c - xs[d + 32] * s) : (xn * c + xs[d - 32] * s);
    ptr[d] = out;
}

// ---------------- flash attention (non-causal, GQA H=16 over KV=4) ----------------
__global__ __launch_bounds__(128) void attn_kernel() {
    int h = blockIdx.y;
    int qi = blockIdx.x * 128 + threadIdx.x;
    int kvh = h >> 2;  // groups = 4
    __shared__ __align__(16) float ks[64 * 64];
    __shared__ __align__(16) float vs[64 * 64];
    float q[64], acc[64];
    const float* qrow = g_q + (size_t)qi * (NH * DHD) + h * DHD;
#pragma unroll
    for (int d = 0; d < 64; d += 4) {
        float4 t = *reinterpret_cast<const float4*>(qrow + d);
        q[d] = t.x * 0.125f; q[d + 1] = t.y * 0.125f;
        q[d + 2] = t.z * 0.125f; q[d + 3] = t.w * 0.125f;
        acc[d] = 0.f; acc[d + 1] = 0.f; acc[d + 2] = 0.f; acc[d + 3] = 0.f;
    }
    float mrun = -1e30f, lrun = 0.f;
    for (int kt = 0; kt < NTOK; kt += 64) {
#pragma unroll
        for (int i = 0; i < 8; i++) {
            int idx = threadIdx.x + i * 128;
            int m = idx >> 4;
            int dc = (idx & 15) << 2;
            *reinterpret_cast<float4*>(&ks[m * 64 + dc]) =
                *reinterpret_cast<const float4*>(g_k + (size_t)(kt + m) * (NKV * DHD) + kvh * DHD + dc);
            *reinterpret_cast<float4*>(&vs[m * 64 + dc]) =
                *reinterpret_cast<const float4*>(g_v + (size_t)(kt + m) * (NKV * DHD) + kvh * DHD + dc);
        }
        __syncthreads();
#pragma unroll 1
        for (int m = 0; m < 64; m++) {
            const float4* kr = reinterpret_cast<const float4*>(&ks[m * 64]);
            float s0 = 0.f, s1 = 0.f, s2 = 0.f, s3 = 0.f;
#pragma unroll
            for (int d4 = 0; d4 < 16; d4++) {
                float4 kv = kr[d4];
                s0 += q[d4 * 4 + 0] * kv.x; s1 += q[d4 * 4 + 1] * kv.y;
                s2 += q[d4 * 4 + 2] * kv.z; s3 += q[d4 * 4 + 3] * kv.w;
            }
            float s = (s0 + s1) + (s2 + s3);
            if (s > mrun) {
                float corr = __expf(mrun - s);
                lrun *= corr;
#pragma unroll
                for (int d = 0; d < 64; d++) acc[d] *= corr;
                mrun = s;
            }
            float p = __expf(s - mrun);
            lrun += p;
            const float4* vr = reinterpret_cast<const float4*>(&vs[m * 64]);
#pragma unroll
            for (int d4 = 0; d4 < 16; d4++) {
                float4 vv = vr[d4];
                acc[d4 * 4 + 0] += p * vv.x; acc[d4 * 4 + 1] += p * vv.y;
                acc[d4 * 4 + 2] += p * vv.z; acc[d4 * 4 + 3] += p * vv.w;
            }
        }
        __syncthreads();
    }
    float rl = 1.f / lrun;
    float* orow = g_oh + (size_t)qi * (NH * DHD) + h * DHD;
#pragma unroll
    for (int d = 0; d < 64; d += 4) {
        float4 o = make_float4(acc[d] * rl, acc[d + 1] * rl, acc[d + 2] * rl, acc[d + 3] * rl);
        *reinterpret_cast<float4*>(orow + d) = o;
    }
}

// ---------------- control dynamics elementwise ----------------
__global__ void dynamics_kernel(const float* __restrict__ hidden, const float* __restrict__ velocity,
                                const float* __restrict__ mu, float* __restrict__ out_h2,
                                float* __restrict__ out_vn) {
    int idx = blockIdx.x * 256 + threadIdx.x;
    int n = idx >> 10;
    int d = idx & 1023;
    const float* co = g_co + (size_t)n * 3 * DM;
    float ar = co[d], br = co[DM + d], gr = co[2 * DM + d];
    float alpha = 1.f / (1.f + expf(-ar));
    float sp = fmaxf(br, 0.f) + log1pf(expf(-fabsf(br)));
    float beta = fminf(sp, 2.f);
    float gate = 1.f / (1.f + expf(-gr));
    float o = g_o[idx], mv = mu[idx], vel = velocity[idx];
    float vn = alpha * vel - beta * (o - mv);
    vn = fminf(fmaxf(vn, -10.f), 10.f);
    out_h2[idx] = hidden[idx] + o + 0.1f * gate * vn;
    out_vn[idx] = vn;
}

// ---------------- router ----------------
__global__ void zero_cnt_kernel() {
    if (threadIdx.x < NEXP) g_cnt[threadIdx.x] = 0;
}

__global__ void router_kernel(const float* __restrict__ mu, const int* __restrict__ token_ids,
                              const float* __restrict__ Wr) {
    int tid = threadIdx.x;
    int tl = tid >> 3, e = tid & 7;
    int n = blockIdx.x * 32 + tl;
    const float* mr = mu + (size_t)n * DM;
    float s = 0.f;
    for (int d = 0; d < DM; d++) s += mr[d] * Wr[d * NEXP + e];
    __shared__ float lg[32][8];
    lg[tl][e] = s;
    __syncthreads();
    if (e == 0) {
        int base = token_ids[n] % NEXP;
        float best = -1e30f;
        int bi = 0;
#pragma unroll
        for (int j = 0; j < 8; j++) {
            float c = lg[tl][j] + (j == base ? 10.0f : 0.0f);
            if (c > best) { best = c; bi = j; }
        }
        int slot = atomicAdd(&g_cnt[bi], 1);
        g_toklist[bi * NTOK + slot] = n;
    }
}

// ================= tf32 tensor-core MoE =================
// Block tile: 128 tokens x 64 cols. 8 warps, each 32x32 (2 m-frags x 4 n-frags).
// As: row-major [128][36] (pad 36 -> conflict-free frag loads: bank = 4g+c+const).
// B : n-major  [64][36]  (b frag = Bs[n][k], same conflict-free property).

// ---- stage A: mid = silu(X@Wg[e]) * (X@Wu[e]) ----
__global__ __launch_bounds__(256) void moe_gateup_tc(const float* __restrict__ X,
                                                     const float* __restrict__ Wg,
                                                     const float* __restrict__ Wu) {
    int e = blockIdx.z;
    int count = g_cnt[e];
    int m0 = blockIdx.y * 128;
    if (m0 >= count) return;
    int f0 = blockIdx.x * 64;

    __shared__ int toks[128];
    __shared__ unsigned As[128 * 36];
    __shared__ unsigned Bg[64 * 36];
    __shared__ unsigned Bu[64 * 36];

    int tid = threadIdx.x;
    int lane = tid & 31, w = tid >> 5;
    int wm = w & 3, wn = w >> 2;        // wm: 4 row groups of 32, wn: 2 col groups of 32
    int g = lane >> 2, c = lane & 3;

    if (tid < 128) toks[tid] = (m0 + tid < count) ? g_toklist[e * NTOK + m0 + tid] : -1;
    __syncthreads();

    const float* WgE = Wg + (size_t)e * DM * FF;
    const float* WuE = Wu + (size_t)e * DM * FF;

    // loader indices
    int arow = tid >> 1, akc = (tid & 1) * 16;   // A: 128 rows x 32 k, 16 floats/thread
    int bn = tid & 63, bk0 = (tid >> 6) * 8;     // B: 64 n x 32 k, 8 floats/thread
    int tokA = toks[arow];
    const float* Aptr = (tokA >= 0) ? X + (size_t)tokA * DM + akc : X;

    float acg[2][4][4], acu[2][4][4];
#pragma unroll
    for (int mf = 0; mf < 2; mf++)
#pragma unroll
        for (int nt = 0; nt < 4; nt++)
#pragma unroll
            for (int r = 0; r < 4; r++) { acg[mf][nt][r] = 0.f; acu[mf][nt][r] = 0.f; }

    for (int kk = 0; kk < DM; kk += 32) {
        // global fetch
        float a[16];
        if (tokA >= 0) {
#pragma unroll
            for (int j = 0; j < 16; j += 4) {
                float4 t = *reinterpret_cast<const float4*>(Aptr + kk + j);
                a[j] = t.x; a[j + 1] = t.y; a[j + 2] = t.z; a[j + 3] = t.w;
            }
        } else {
#pragma unroll
            for (int j = 0; j < 16; j++) a[j] = 0.f;
        }
        float bg[8], bu[8];
        const float* bgp = WgE + (size_t)(kk + bk0) * FF + f0 + bn;
        const float* bup = WuE + (size_t)(kk + bk0) * FF + f0 + bn;
#pragma unroll
        for (int j = 0; j < 8; j++) { bg[j] = bgp[(size_t)j * FF]; bu[j] = bup[(size_t)j * FF]; }

        __syncthreads();  // previous compute finished
        unsigned* ap = &As[arow * 36 + akc];
#pragma unroll
        for (int j = 0; j < 16; j++) ap[j] = f2tf(a[j]);
        unsigned* gp = &Bg[bn * 36 + bk0];
        unsigned* up = &Bu[bn * 36 + bk0];
#pragma unroll
        for (int j = 0; j < 8; j++) { gp[j] = f2tf(bg[j]); up[j] = f2tf(bu[j]); }
        __syncthreads();

#pragma unroll
        for (int k8 = 0; k8 < 4; k8++) {
            int k0 = k8 * 8;
            unsigned af[2][4];
#pragma unroll
            for (int mf = 0; mf < 2; mf++) {
                int rb = wm * 32 + mf * 16;
                af[mf][0] = As[(rb + g) * 36 + k0 + c];
                af[mf][1] = As[(rb + g + 8) * 36 + k0 + c];
                af[mf][2] = As[(rb + g) * 36 + k0 + c + 4];
                af[mf][3] = As[(rb + g + 8) * 36 + k0 + c + 4];
            }
#pragma unroll
            for (int nt = 0; nt < 4; nt++) {
                int nb = (wn * 32 + nt * 8 + g) * 36 + k0 + c;
                unsigned b0 = Bg[nb], b1 = Bg[nb + 4];
                mma_tf32(acg[0][nt][0], acg[0][nt][1], acg[0][nt][2], acg[0][nt][3],
                         af[0][0], af[0][1], af[0][2], af[0][3], b0, b1);
                mma_tf32(acg[1][nt][0], acg[1][nt][1], acg[1][nt][2], acg[1][nt][3],
                         af[1][0], af[1][1], af[1][2], af[1][3], b0, b1);
                unsigned u0 = Bu[nb], u1 = Bu[nb + 4];
                mma_tf32(acu[0][nt][0], acu[0][nt][1], acu[0][nt][2], acu[0][nt][3],
                         af[0][0], af[0][1], af[0][2], af[0][3], u0, u1);
                mma_tf32(acu[1][nt][0], acu[1][nt][1], acu[1][nt][2], acu[1][nt][3],
                         af[1][0], af[1][1], af[1][2], af[1][3], u0, u1);
            }
        }
    }

    // epilogue: mid = silu(g)*u
#pragma unroll
    for (int mf = 0; mf < 2; mf++) {
        int r0 = wm * 32 + mf * 16 + g;
        int t0 = toks[r0], t1 = toks[r0 + 8];
#pragma unroll
        for (int nt = 0; nt < 4; nt++) {
            int col = f0 + wn * 32 + nt * 8 + 2 * c;
            if (t0 >= 0) {
                float gv = acg[mf][nt][0], uv = acu[mf][nt][0];
                g_mid[(size_t)t0 * FF + col] = (gv / (1.f + __expf(-gv))) * uv;
                gv = acg[mf][nt][1]; uv = acu[mf][nt][1];
                g_mid[(size_t)t0 * FF + col + 1] = (gv / (1.f + __expf(-gv))) * uv;
            }
            if (t1 >= 0) {
                float gv = acg[mf][nt][2], uv = acu[mf][nt][2];
                g_mid[(size_t)t1 * FF + col] = (gv / (1.f + __expf(-gv))) * uv;
                gv = acg[mf][nt][3]; uv = acu[mf][nt][3];
                g_mid[(size_t)t1 * FF + col + 1] = (gv / (1.f + __expf(-gv))) * uv;
            }
        }
    }
}

// ---- stage B: out[tok] += mid[tok] @ Wd[e] ----
__global__ __launch_bounds__(256) void moe_down_tc(const float* __restrict__ Wd,
                                                   float* __restrict__ out) {
    int e = blockIdx.z;
    int count = g_cnt[e];
    int m0 = blockIdx.y * 128;
    if (m0 >= count) return;
    int d0 = blockIdx.x * 64;

    __shared__ int toks[128];
    __shared__ unsigned As[128 * 36];
    __shared__ unsigned Bs[64 * 36];

    int tid = threadIdx.x;
    int lane = tid & 31, w = tid >> 5;
    int wm = w & 3, wn = w >> 2;
    int g = lane >> 2, c = lane & 3;

    if (tid < 128) toks[tid] = (m0 + tid < count) ? g_toklist[e * NTOK + m0 + tid] : -1;
    __syncthreads();

    const float* WdE = Wd + (size_t)e * FF * DM;
    int arow = tid >> 1, akc = (tid & 1) * 16;
    int bn = tid & 63, bk0 = (tid >> 6) * 8;
    int tokA = toks[arow];
    const float* Aptr = (tokA >= 0) ? g_mid + (size_t)tokA * FF + akc : g_mid;

    float acc[2][4][4];
#pragma unroll
    for (int mf = 0; mf < 2; mf++)
#pragma unroll
        for (int nt = 0; nt < 4; nt++)
#pragma unroll
            for (int r = 0; r < 4; r++) acc[mf][nt][r] = 0.f;

    for (int kk = 0; kk < FF; kk += 32) {
        float a[16];
        if (tokA >= 0) {
#pragma unroll
            for (int j = 0; j < 16; j += 4) {
                float4 t = *reinterpret_cast<const float4*>(Aptr + kk + j);
                a[j] = t.x; a[j + 1] = t.y; a[j + 2] = t.z; a[j + 3] = t.w;
            }
        } else {
#pragma unroll
            for (int j = 0; j < 16; j++) a[j] = 0.f;
        }
        float b[8];
        const float* bp = WdE + (size_t)(kk + bk0) * DM + d0 + bn;
#pragma unroll
        for (int j = 0; j < 8; j++) b[j] = bp[(size_t)j * DM];

        __syncthreads();
        unsigned* ap = &As[arow * 36 + akc];
#pragma unroll
        for (int j = 0; j < 16; j++) ap[j] = f2tf(a[j]);
        unsigned* bpp = &Bs[bn * 36 + bk0];
#pragma unroll
        for (int j = 0; j < 8; j++) bpp[j] = f2tf(b[j]);
        __syncthreads();

#pragma unroll
        for (int k8 = 0; k8 < 4; k8++) {
            int k0 = k8 * 8;
            unsigned af[2][4];
#pragma unroll
            for (int mf = 0; mf < 2; mf++) {
                int rb = wm * 32 + mf * 16;
                af[mf][0] = As[(rb + g) * 36 + k0 + c];
                af[mf][1] = As[(rb + g + 8) * 36 + k0 + c];
                af[mf][2] = As[(rb + g) * 36 + k0 + c + 4];
                af[mf][3] = As[(rb + g + 8) * 36 + k0 + c + 4];
            }
#pragma unroll
            for (int nt = 0; nt < 4; nt++) {
                int nb = (wn * 32 + nt * 8 + g) * 36 + k0 + c;
                unsigned b0 = Bs[nb], b1 = Bs[nb + 4];
                mma_tf32(acc[0][nt][0], acc[0][nt][1], acc[0][nt][2], acc[0][nt][3],
                         af[0][0], af[0][1], af[0][2], af[0][3], b0, b1);
                mma_tf32(acc[1][nt][0], acc[1][nt][1], acc[1][nt][2], acc[1][nt][3],
                         af[1][0], af[1][1], af[1][2], af[1][3], b0, b1);
            }
        }
    }

#pragma unroll
    for (int mf = 0; mf < 2; mf++) {
        int r0 = wm * 32 + mf * 16 + g;
        int t0 = toks[r0], t1 = toks[r0 + 8];
#pragma unroll
        for (int nt = 0; nt < 4; nt++) {
            int col = d0 + wn * 32 + nt * 8 + 2 * c;
            if (t0 >= 0) {
                out[(size_t)t0 * DM + col]     += acc[mf][nt][0];
                out[(size_t)t0 * DM + col + 1] += acc[mf][nt][1];
            }
            if (t1 >= 0) {
                out[(size_t)t1 * DM + col]     += acc[mf][nt][2];
                out[(size_t)t1 * DM + col + 1] += acc[mf][nt][3];
            }
        }
    }
}

// ---------------- host orchestration ----------------
extern "C" void kernel_launch(void* const* d_in, const int* in_sizes, int n_in,
                              void* d_out, int out_size) {
    const float* hidden     = (const float*)d_in[0];
    const int*   positions  = (const int*)d_in[1];
    const float* velocity   = (const float*)d_in[2];
    const int*   token_ids  = (const int*)d_in[3];
    const float* mu_prev    = (const float*)d_in[4];
    const float* ln1_w      = (const float*)d_in[5];
    const float* ln2_w      = (const float*)d_in[6];
    const float* wq         = (const float*)d_in[7];
    const float* wk         = (const float*)d_in[8];
    const float* wv         = (const float*)d_in[9];
    const float* wo_w       = (const float*)d_in[10];
    const float* w_mu_q     = (const float*)d_in[11];
    const float* w_mu_k     = (const float*)d_in[12];
    const float* w_mu_v     = (const float*)d_in[13];
    const float* qnorm_w    = (const float*)d_in[14];
    const float* knorm_w    = (const float*)d_in[15];
    const float* dyn_mu     = (const float*)d_in[16];
    const float* dyn_proj   = (const float*)d_in[17];
    const float* ctrl_in_w  = (const float*)d_in[18];
    const float* ctrl_in_b  = (const float*)d_in[19];
    const float* ctrl_out_w = (const float*)d_in[20];
    const float* ctrl_out_b = (const float*)d_in[21];
    const float* mu_router  = (const float*)d_in[22];
    const float* w_gate     = (const float*)d_in[23];
    const float* w_up       = (const float*)d_in[24];
    const float* w_down     = (const float*)d_in[25];

    float* out    = (float*)d_out;
    float* out_h  = out;                          // hidden
    float* out_vn = out + (size_t)NTOK * DM;      // v_next
    float* out_mu = out + 2 * (size_t)NTOK * DM;  // mu_cur

    float *p_h1, *p_oh, *p_o, *p_ctrl, *p_co, *p_x2;
    cudaGetSymbolAddress((void**)&p_h1, g_h1);
    cudaGetSymbolAddress((void**)&p_oh, g_oh);
    cudaGetSymbolAddress((void**)&p_o, g_o);
    cudaGetSymbolAddress((void**)&p_ctrl, g_ctrl);
    cudaGetSymbolAddress((void**)&p_co, g_co);
    cudaGetSymbolAddress((void**)&p_x2, g_x2);

    // 1. h = rmsnorm(hidden, ln1_w)
    rmsnorm_kernel<<<NTOK, 256>>>(hidden, ln1_w, p_h1);

    // 2. fused q/k/v = h@W* + mu_prev@W_mu* (one launch, 768 blocks)
    qkv_kernel<<<dim3(24, NTOK / 64), 256>>>(p_h1, mu_prev, wq, w_mu_q, wk, w_mu_k, wv, w_mu_v);

    // 3. per-head rmsnorm + RoPE on q, k
    qknorm_rope_kernel<<<dim3(NTOK, NH + NKV), 64>>>(positions, qnorm_w, knorm_w);

    // 4. flash attention -> g_oh
    attn_kernel<<<dim3(NTOK / 128, NH), 128>>>();

    // 5. o = oh @ wo   (fp32 — o-path precision-critical for mu_cur)
    gemm_kernel<<<dim3(DM / 64, NTOK / 64), 256>>>(p_oh, nullptr, wo_w, nullptr, nullptr,
                                                   p_o, NH * DHD, DM, 0);

    // 6. mu_cur = dyn_mu + o @ dyn_mu_proj_w  (fp32)
    gemm_kernel<<<dim3(DM / 64, NTOK / 64), 256>>>(p_o, nullptr, dyn_proj, nullptr, dyn_mu,
                                                   out_mu, DM, DM, 1);

    // 7. ctrl = silu([o | velocity] @ ctrl_in_w + b)
    gemm_kernel<<<dim3(CHN / 64, NTOK / 64), 256>>>(p_o, velocity, ctrl_in_w,
                                                    ctrl_in_w + (size_t)DM * CHN, ctrl_in_b,
                                                    p_ctrl, DM, CHN, 2);

    // 8. co = ctrl @ ctrl_out_w + ctrl_out_b
    gemm_kernel<<<dim3((3 * DM) / 64, NTOK / 64), 256>>>(p_ctrl, nullptr, ctrl_out_w, nullptr,
                                                         ctrl_out_b, p_co, CHN, 3 * DM, 1);

    // 9. dynamics
    dynamics_kernel<<<(NTOK * DM) / 256, 256>>>(hidden, velocity, out_mu, out_h, out_vn);

    // 10. x = rmsnorm(hidden2, ln2_w)
    rmsnorm_kernel<<<NTOK, 256>>>(out_h, ln2_w, p_x2);

    // 11. routing
    zero_cnt_kernel<<<1, 32>>>();
    router_kernel<<<NTOK / 32, 256>>>(out_mu, token_ids, mu_router);

    // 12. MoE on tf32 tensor cores (error-tolerant path: y diluted ~0.36x into hidden)
    moe_gateup_tc<<<dim3(FF / 64, NTOK / 128, NEXP), 256>>>(p_x2, w_gate, w_up);
    moe_down_tc<<<dim3(DM / 64, NTOK / 128, NEXP), 256>>>(w_down, out_h);
}

// round 10
// speedup vs baseline: 1.3416x; 1.1004x over previous
#include <cuda_runtime.h>
#include <math.h>

#define NTOK 2048
#define DM   1024
#define NH   16
#define NKV  4
#define DHD  64
#define NEXP 8
#define FF   2048
#define CHN  64
#define EPSV 1e-6f
#define ASPLIT 4
#define KEYS_PER_SPLIT (NTOK / ASPLIT)

// ---------------- scratch (device globals; no allocation allowed) ----------------
__device__ float g_h1[NTOK * DM];
__device__ float g_q[NTOK * NH * DHD];
__device__ float g_k[NTOK * NKV * DHD];
__device__ float g_v[NTOK * NKV * DHD];
__device__ float g_oh[NTOK * NH * DHD];
__device__ float g_o[NTOK * DM];
__device__ float g_ctrl[NTOK * CHN];
__device__ float g_co[NTOK * 3 * DM];
__device__ float g_x2[NTOK * DM];
__device__ float g_mid[NTOK * FF];
__device__ int   g_cnt[NEXP];
__device__ int   g_toklist[NEXP * NTOK];
// attention split-K partials
__device__ float g_am[ASPLIT * NTOK * NH];
__device__ float g_al[ASPLIT * NTOK * NH];
__device__ float g_aacc[(size_t)ASPLIT * NTOK * NH * DHD];

// ---------------- tf32 helpers ----------------
__device__ __forceinline__ unsigned f2tf(float f) {
    unsigned u;
    asm("cvt.rna.tf32.f32 %0, %1;" : "=r"(u) : "f"(f));
    return u;
}
__device__ __forceinline__ void split_tf(float x, unsigned& hi, unsigned& lo) {
    hi = f2tf(x);
    float r = x - __uint_as_float(hi);
    lo = f2tf(r);
}
__device__ __forceinline__ void mma_tf32(float& c0, float& c1, float& c2, float& c3,
                                         unsigned a0, unsigned a1, unsigned a2, unsigned a3,
                                         unsigned b0, unsigned b1) {
    asm("mma.sync.aligned.m16n8k8.row.col.f32.tf32.tf32.f32 "
        "{%0,%1,%2,%3},{%4,%5,%6,%7},{%8,%9},{%0,%1,%2,%3};"
        : "+f"(c0), "+f"(c1), "+f"(c2), "+f"(c3)
        : "r"(a0), "r"(a1), "r"(a2), "r"(a3), "r"(b0), "r"(b1));
}

// ---------------- rmsnorm over D=1024 ----------------
__global__ void rmsnorm_kernel(const float* __restrict__ x, const float* __restrict__ w,
                               float* __restrict__ out) {
    int n = blockIdx.x;
    int t = threadIdx.x;
    const float4* xr = reinterpret_cast<const float4*>(x + (size_t)n * DM);
    float4 v = xr[t];
    __shared__ float red[256];
    red[t] = v.x * v.x + v.y * v.y + v.z * v.z + v.w * v.w;
    __syncthreads();
    for (int s = 128; s > 0; s >>= 1) {
        if (t < s) red[t] += red[t + s];
        __syncthreads();
    }
    float sc = rsqrtf(red[0] * (1.0f / DM) + EPSV);
    float4 wv = reinterpret_cast<const float4*>(w)[t];
    float4 o = make_float4(v.x * sc * wv.x, v.y * sc * wv.y, v.z * sc * wv.z, v.w * sc * wv.w);
    reinterpret_cast<float4*>(out + (size_t)n * DM)[t] = o;
}

// ---------------- fp32 SIMT GEMM (kept for small ctrl GEMMs) ----------------
__global__ __launch_bounds__(256) void gemm_kernel(
    const float* __restrict__ A1, const float* __restrict__ A2,
    const float* __restrict__ B1, const float* __restrict__ B2,
    const float* __restrict__ bias, float* __restrict__ C,
    int Kd, int Nc, int epi) {
    __shared__ __align__(16) float As[16 * 68];
    __shared__ __align__(16) float Bs[16 * 64];
    int m0 = blockIdx.y * 64, n0 = blockIdx.x * 64;
    int tid = threadIdx.x;
    int tx = tid & 15, ty = tid >> 4;
    float acc[4][4];
#pragma unroll
    for (int i = 0; i < 4; i++)
#pragma unroll
        for (int j = 0; j < 4; j++) acc[i][j] = 0.f;

    int nparts = (A2 != nullptr) ? 2 : 1;
    for (int part = 0; part < nparts; ++part) {
        const float* A = part ? A2 : A1;
        const float* B = part ? B2 : B1;
        for (int kk = 0; kk < Kd; kk += 16) {
            int idx = tid * 4;
            int arow = idx >> 4, ak = idx & 15;
            float4 av = *reinterpret_cast<const float4*>(A + (size_t)(m0 + arow) * Kd + kk + ak);
            As[(ak + 0) * 68 + arow] = av.x;
            As[(ak + 1) * 68 + arow] = av.y;
            As[(ak + 2) * 68 + arow] = av.z;
            As[(ak + 3) * 68 + arow] = av.w;
            int bk = idx >> 6, bn = idx & 63;
            *reinterpret_cast<float4*>(&Bs[bk * 64 + bn]) =
                *reinterpret_cast<const float4*>(B + (size_t)(kk + bk) * Nc + n0 + bn);
            __syncthreads();
#pragma unroll
            for (int k = 0; k < 16; k++) {
                float4 a = *reinterpret_cast<const float4*>(&As[k * 68 + ty * 4]);
                float4 b = *reinterpret_cast<const float4*>(&Bs[k * 64 + tx * 4]);
                float ar[4] = {a.x, a.y, a.z, a.w};
                float br[4] = {b.x, b.y, b.z, b.w};
#pragma unroll
                for (int i = 0; i < 4; i++)
#pragma unroll
                    for (int j = 0; j < 4; j++) acc[i][j] += ar[i] * br[j];
            }
            __syncthreads();
        }
    }
#pragma unroll
    for (int i = 0; i < 4; i++) {
        int row = m0 + ty * 4 + i;
#pragma unroll
        for (int j = 0; j < 4; j++) {
            int col = n0 + tx * 4 + j;
            float v = acc[i][j];
            if (epi >= 1) v += bias[col];
            if (epi == 2) v = v / (1.f + __expf(-v));
            C[(size_t)row * Nc + col] = v;
        }
    }
}

// ================= 3xTF32 tensor-core GEMM (fp32-class precision) =================
// Tile 128x64, 256 threads, 8 warps (wm = w&3 row-groups of 32, wn = w>>2 col-groups of 32).
// k-chunk 16, smem stride 20 (conflict-free: (g*20+c) mod 32 spans all banks).
// acc += Ahi*Bhi + Ahi*Blo + Alo*Bhi  -> residual ~2^-22 (fp32-class).

struct TcTile {
    unsigned Ah[128 * 20];
    unsigned Al[128 * 20];
    unsigned Bh[64 * 20];
    unsigned Bl[64 * 20];
};

__device__ __forceinline__ void tc3_chunk(TcTile* s, int wm, int wn, int g, int c,
                                          float acc[2][4][4]) {
#pragma unroll
    for (int k8 = 0; k8 < 2; k8++) {
        int k0 = k8 * 8;
        unsigned ah[2][4], al[2][4];
#pragma unroll
        for (int mf = 0; mf < 2; mf++) {
            int rb = wm * 32 + mf * 16;
            ah[mf][0] = s->Ah[(rb + g) * 20 + k0 + c];
            ah[mf][1] = s->Ah[(rb + g + 8) * 20 + k0 + c];
            ah[mf][2] = s->Ah[(rb + g) * 20 + k0 + c + 4];
            ah[mf][3] = s->Ah[(rb + g + 8) * 20 + k0 + c + 4];
            al[mf][0] = s->Al[(rb + g) * 20 + k0 + c];
            al[mf][1] = s->Al[(rb + g + 8) * 20 + k0 + c];
            al[mf][2] = s->Al[(rb + g) * 20 + k0 + c + 4];
            al[mf][3] = s->Al[(rb + g + 8) * 20 + k0 + c + 4];
        }
#pragma unroll
        for (int nt = 0; nt < 4; nt++) {
            int nb = (wn * 32 + nt * 8 + g) * 20 + k0 + c;
            unsigned bh0 = s->Bh[nb], bh1 = s->Bh[nb + 4];
            unsigned bl0 = s->Bl[nb], bl1 = s->Bl[nb + 4];
#pragma unroll
            for (int mf = 0; mf < 2; mf++) {
                mma_tf32(acc[mf][nt][0], acc[mf][nt][1], acc[mf][nt][2], acc[mf][nt][3],
                         ah[mf][0], ah[mf][1], ah[mf][2], ah[mf][3], bh0, bh1);
                mma_tf32(acc[mf][nt][0], acc[mf][nt][1], acc[mf][nt][2], acc[mf][nt][3],
                         ah[mf][0], ah[mf][1], ah[mf][2], ah[mf][3], bl0, bl1);
                mma_tf32(acc[mf][nt][0], acc[mf][nt][1], acc[mf][nt][2], acc[mf][nt][3],
                         al[mf][0], al[mf][1], al[mf][2], al[mf][3], bh0, bh1);
            }
        }
    }
}

__device__ __forceinline__ void tc3_load(TcTile* s, const float* __restrict__ A,
                                         const float* __restrict__ B, int Kd, int Nc,
                                         int m0, int n0, int kk, int tid) {
    // A: 128 rows x 16 k. 256 threads x 8 floats.
    int arow = tid >> 1, akc = (tid & 1) * 8;
    const float* ap = A + (size_t)(m0 + arow) * Kd + kk + akc;
    float a[8];
#pragma unroll
    for (int j = 0; j < 8; j += 4) {
        float4 t = *reinterpret_cast<const float4*>(ap + j);
        a[j] = t.x; a[j + 1] = t.y; a[j + 2] = t.z; a[j + 3] = t.w;
    }
    // B: 64 n x 16 k. 256 threads x 4 floats (strided rows).
    int bn = tid & 63, bk0 = (tid >> 6) * 4;
    const float* bp = B + (size_t)(kk + bk0) * Nc + n0 + bn;
    float b[4];
#pragma unroll
    for (int j = 0; j < 4; j++) b[j] = bp[(size_t)j * Nc];

    __syncthreads();
    unsigned* ah = &s->Ah[arow * 20 + akc];
    unsigned* al = &s->Al[arow * 20 + akc];
#pragma unroll
    for (int j = 0; j < 8; j++) split_tf(a[j], ah[j], al[j]);
    unsigned* bh = &s->Bh[bn * 20 + bk0];
    unsigned* bl = &s->Bl[bn * 20 + bk0];
#pragma unroll
    for (int j = 0; j < 4; j++) split_tf(b[j], bh[j], bl[j]);
    __syncthreads();
}

// dense 3xTF32 GEMM: C = A@B [+bias], grid (Nc/64, rows/128)
__global__ __launch_bounds__(256) void gemm3_tc(const float* __restrict__ A,
                                                const float* __restrict__ B,
                                                const float* __restrict__ bias,
                                                float* __restrict__ C, int Kd, int Nc, int epi) {
    __shared__ TcTile s;
    int m0 = blockIdx.y * 128, n0 = blockIdx.x * 64;
    int tid = threadIdx.x;
    int lane = tid & 31, w = tid >> 5;
    int wm = w & 3, wn = w >> 2;
    int g = lane >> 2, c = lane & 3;

    float acc[2][4][4];
#pragma unroll
    for (int mf = 0; mf < 2; mf++)
#pragma unroll
        for (int nt = 0; nt < 4; nt++)
#pragma unroll
            for (int r = 0; r < 4; r++) acc[mf][nt][r] = 0.f;

    for (int kk = 0; kk < Kd; kk += 16) {
        tc3_load(&s, A, B, Kd, Nc, m0, n0, kk, tid);
        tc3_chunk(&s, wm, wn, g, c, acc);
    }

#pragma unroll
    for (int mf = 0; mf < 2; mf++) {
        int r0 = m0 + wm * 32 + mf * 16 + g;
#pragma unroll
        for (int nt = 0; nt < 4; nt++) {
            int col = n0 + wn * 32 + nt * 8 + 2 * c;
#pragma unroll
            for (int half = 0; half < 2; half++) {
                int row = r0 + half * 8;
                float v0 = acc[mf][nt][half * 2 + 0];
                float v1 = acc[mf][nt][half * 2 + 1];
                if (epi >= 1) { v0 += bias[col]; v1 += bias[col + 1]; }
                C[(size_t)row * Nc + col]     = v0;
                C[(size_t)row * Nc + col + 1] = v1;
            }
        }
    }
}

// fused qkv 3xTF32: nt 0..15 -> q, 16..19 -> k, 20..23 -> v; dual-A (h@W + mu_prev@Wmu)
__global__ __launch_bounds__(256) void qkv3_tc(
    const float* __restrict__ A1, const float* __restrict__ A2,
    const float* __restrict__ wq, const float* __restrict__ wmq,
    const float* __restrict__ wk, const float* __restrict__ wmk,
    const float* __restrict__ wv, const float* __restrict__ wmv) {
    __shared__ TcTile s;
    int ntile = blockIdx.x;
    int m0 = blockIdx.y * 128;
    const float *B1, *B2;
    float* C;
    int Nc, n0;
    if (ntile < 16)      { B1 = wq; B2 = wmq; C = g_q; Nc = NH * DHD;  n0 = ntile * 64; }
    else if (ntile < 20) { B1 = wk; B2 = wmk; C = g_k; Nc = NKV * DHD; n0 = (ntile - 16) * 64; }
    else                 { B1 = wv; B2 = wmv; C = g_v; Nc = NKV * DHD; n0 = (ntile - 20) * 64; }

    int tid = threadIdx.x;
    int lane = tid & 31, w = tid >> 5;
    int wm = w & 3, wn = w >> 2;
    int g = lane >> 2, c = lane & 3;

    float acc[2][4][4];
#pragma unroll
    for (int mf = 0; mf < 2; mf++)
#pragma unroll
        for (int nt = 0; nt < 4; nt++)
#pragma unroll
            for (int r = 0; r < 4; r++) acc[mf][nt][r] = 0.f;

    for (int part = 0; part < 2; ++part) {
        const float* A = part ? A2 : A1;
        const float* B = part ? B2 : B1;
        for (int kk = 0; kk < DM; kk += 16) {
            tc3_load(&s, A, B, DM, Nc, m0, n0, kk, tid);
            tc3_chunk(&s, wm, wn, g, c, acc);
        }
    }

#pragma unroll
    for (int mf = 0; mf < 2; mf++) {
        int r0 = m0 + wm * 32 + mf * 16 + g;
#pragma unroll
        for (int nt = 0; nt < 4; nt++) {
            int col = n0 + wn * 32 + nt * 8 + 2 * c;
#pragma unroll
            for (int half = 0; half < 2; half++) {
                int row = r0 + half * 8;
                C[(size_t)row * Nc + col]     = acc[mf][nt][half * 2 + 0];
                C[(size_t)row * Nc + col + 1] = acc[mf][nt][half * 2 + 1];
            }
        }
    }
}

// ---------------- per-(token,head) rmsnorm + RoPE for q and k ----------------
__global__ void qknorm_rope_kernel(const int* __restrict__ positions,
                                   const float* __restrict__ qw, const float* __restrict__ kw) {
    int n = blockIdx.x;
    int hh = blockIdx.y;
    int d = threadIdx.x;
    float* ptr;
    const float* w;
    if (hh < NH) { ptr = g_q + (size_t)n * (NH * DHD) + hh * DHD; w = qw; }
    else         { ptr = g_k + (size_t)n * (NKV * DHD) + (hh - NH) * DHD; w = kw; }
    float x = ptr[d];
    __shared__ float sh[64];
    __shared__ float xs[64];
    sh[d] = x * x;
    __syncthreads();
    for (int s = 32; s > 0; s >>= 1) {
        if (d < s) sh[d] += sh[d + s];
        __syncthreads();
    }
    float sc = rsqrtf(sh[0] * (1.0f / DHD) + EPSV);
    float xn = x * sc * w[d];
    xs[d] = xn;
    __syncthreads();
    float pos = (float)positions[n];
    int i = d & 31;
    float inv = (float)exp(-((double)(2 * i) / 64.0) * log(10000.0));
    float ang = pos * inv;
    float c = cosf(ang), s = sinf(ang);
    float out = (d < 32) ? (xn * c - xs[d + 32] * s) : (xn * c + xs[d - 32] * s);
    ptr[d] = out;
}

// ---------------- split-K flash attention: each block handles 512 keys ----------------
__global__ __launch_bounds__(128) void attn_split_kernel() {
    int h = blockIdx.y;
    int qi = blockIdx.x * 128 + threadIdx.x;
    int sp = blockIdx.z;
    int kvh = h >> 2;
    __shared__ __align__(16) float ks[64 * 64];
    __shared__ __align__(16) float vs[64 * 64];
    float q[64], acc[64];
    const float* qrow = g_q + (size_t)qi * (NH * DHD) + h * DHD;
#pragma unroll
    for (int d = 0; d < 64; d += 4) {
        float4 t = *reinterpret_cast<const float4*>(qrow + d);
        q[d] = t.x * 0.125f; q[d + 1] = t.y * 0.125f;
        q[d + 2] = t.z * 0.125f; q[d + 3] = t.w * 0.125f;
        acc[d] = 0.f; acc[d + 1] = 0.f; acc[d + 2] = 0.f; acc[d + 3] = 0.f;
    }
    float mrun = -1e30f, lrun = 0.f;
    int kbeg = sp * KEYS_PER_SPLIT;
    for (int kt = kbeg; kt < kbeg + KEYS_PER_SPLIT; kt += 64) {
#pragma unroll
        for (int i = 0; i < 8; i++) {
            int idx = threadIdx.x + i * 128;
            int m = idx >> 4;
            int dc = (idx & 15) << 2;
            *reinterpret_cast<float4*>(&ks[m * 64 + dc]) =
                *reinterpret_cast<const float4*>(g_k + (size_t)(kt + m) * (NKV * DHD) + kvh * DHD + dc);
            *reinterpret_cast<float4*>(&vs[m * 64 + dc]) =
                *reinterpret_cast<const float4*>(g_v + (size_t)(kt + m) * (NKV * DHD) + kvh * DHD + dc);
        }
        __syncthreads();
#pragma unroll 1
        for (int m = 0; m < 64; m++) {
            const float4* kr = reinterpret_cast<const float4*>(&ks[m * 64]);
            float s0 = 0.f, s1 = 0.f, s2 = 0.f, s3 = 0.f;
#pragma unroll
            for (int d4 = 0; d4 < 16; d4++) {
                float4 kv = kr[d4];
                s0 += q[d4 * 4 + 0] * kv.x; s1 += q[d4 * 4 + 1] * kv.y;
                s2 += q[d4 * 4 + 2] * kv.z; s3 += q[d4 * 4 + 3] * kv.w;
            }
            float s = (s0 + s1) + (s2 + s3);
            if (s > mrun) {
                float corr = __expf(mrun - s);
                lrun *= corr;
#pragma unroll
                for (int d = 0; d < 64; d++) acc[d] *= corr;
                mrun = s;
            }
            float p = __expf(s - mrun);
            lrun += p;
            const float4* vr = reinterpret_cast<const float4*>(&vs[m * 64]);
#pragma unroll
            for (int d4 = 0; d4 < 16; d4++) {
                float4 vv = vr[d4];
                acc[d4 * 4 + 0] += p * vv.x; acc[d4 * 4 + 1] += p * vv.y;
                acc[d4 * 4 + 2] += p * vv.z; acc[d4 * 4 + 3] += p * vv.w;
            }
        }
        __syncthreads();
    }
    size_t part = ((size_t)sp * NTOK + qi) * NH + h;
    g_am[part] = mrun;
    g_al[part] = lrun;
    float* arow = g_aacc + part * DHD;
#pragma unroll
    for (int d = 0; d < 64; d += 4) {
        *reinterpret_cast<float4*>(arow + d) = make_float4(acc[d], acc[d + 1], acc[d + 2], acc[d + 3]);
    }
}

// combine split-K partials -> g_oh
__global__ void attn_combine_kernel() {
    int idx = blockIdx.x * 256 + threadIdx.x;  // over NTOK*NH*64
    int d = idx & 63;
    int rest = idx >> 6;
    int h = rest & (NH - 1);
    int qi = rest >> 4;
    float m[ASPLIT], l[ASPLIT];
    float M = -1e30f;
#pragma unroll
    for (int s = 0; s < ASPLIT; s++) {
        size_t part = ((size_t)s * NTOK + qi) * NH + h;
        m[s] = g_am[part];
        l[s] = g_al[part];
        M = fmaxf(M, m[s]);
    }
    float L = 0.f, o = 0.f;
#pragma unroll
    for (int s = 0; s < ASPLIT; s++) {
        float wgt = __expf(m[s] - M);
        L += l[s] * wgt;
        size_t part = ((size_t)s * NTOK + qi) * NH + h;
        o += wgt * g_aacc[part * DHD + d];
    }
    g_oh[((size_t)qi * NH + h) * DHD + d] = o / L;
}

// ---------------- control dynamics elementwise ----------------
__global__ void dynamics_kernel(const float* __restrict__ hidden, const float* __restrict__ velocity,
                                const float* __restrict__ mu, float* __restrict__ out_h2,
                                float* __restrict__ out_vn) {
    int idx = blockIdx.x * 256 + threadIdx.x;
    int n = idx >> 10;
    int d = idx & 1023;
    const float* co = g_co + (size_t)n * 3 * DM;
    float ar = co[d], br = co[DM + d], gr = co[2 * DM + d];
    float alpha = 1.f / (1.f + expf(-ar));
    float sp = fmaxf(br, 0.f) + log1pf(expf(-fabsf(br)));
    float beta = fminf(sp, 2.f);
    float gate = 1.f / (1.f + expf(-gr));
    float o = g_o[idx], mv = mu[idx], vel = velocity[idx];
    float vn = alpha * vel - beta * (o - mv);
    vn = fminf(fmaxf(vn, -10.f), 10.f);
    out_h2[idx] = hidden[idx] + o + 0.1f * gate * vn;
    out_vn[idx] = vn;
}

// ---------------- router ----------------
__global__ void zero_cnt_kernel() {
    if (threadIdx.x < NEXP) g_cnt[threadIdx.x] = 0;
}

__global__ void router_kernel(const float* __restrict__ mu, const int* __restrict__ token_ids,
                              const float* __restrict__ Wr) {
    int tid = threadIdx.x;
    int tl = tid >> 3, e = tid & 7;
    int n = blockIdx.x * 32 + tl;
    const float* mr = mu + (size_t)n * DM;
    float s = 0.f;
    for (int d = 0; d < DM; d++) s += mr[d] * Wr[d * NEXP + e];
    __shared__ float lg[32][8];
    lg[tl][e] = s;
    __syncthreads();
    if (e == 0) {
        int base = token_ids[n] % NEXP;
        float best = -1e30f;
        int bi = 0;
#pragma unroll
        for (int j = 0; j < 8; j++) {
            float c = lg[tl][j] + (j == base ? 10.0f : 0.0f);
            if (c > best) { best = c; bi = j; }
        }
        int slot = atomicAdd(&g_cnt[bi], 1);
        g_toklist[bi * NTOK + slot] = n;
    }
}

// ================= 1x tf32 tensor-core MoE (error-tolerant path) =================
__global__ __launch_bounds__(256) void moe_gateup_tc(const float* __restrict__ X,
                                                     const float* __restrict__ Wg,
                                                     const float* __restrict__ Wu) {
    int e = blockIdx.z;
    int count = g_cnt[e];
    int m0 = blockIdx.y * 128;
    if (m0 >= count) return;
    int f0 = blockIdx.x * 64;

    __shared__ int toks[128];
    __shared__ unsigned As[128 * 36];
    __shared__ unsigned Bg[64 * 36];
    __shared__ unsigned Bu[64 * 36];

    int tid = threadIdx.x;
    int lane = tid & 31, w = tid >> 5;
    int wm = w & 3, wn = w >> 2;
    int g = lane >> 2, c = lane & 3;

    if (tid < 128) toks[tid] = (m0 + tid < count) ? g_toklist[e * NTOK + m0 + tid] : -1;
    __syncthreads();

    const float* WgE = Wg + (size_t)e * DM * FF;
    const float* WuE = Wu + (size_t)e * DM * FF;

    int arow = tid >> 1, akc = (tid & 1) * 16;
    int bn = tid & 63, bk0 = (tid >> 6) * 8;
    int tokA = toks[arow];
    const float* Aptr = (tokA >= 0) ? X + (size_t)tokA * DM + akc : X;

    float acg[2][4][4], acu[2][4][4];
#pragma unroll
    for (int mf = 0; mf < 2; mf++)
#pragma unroll
        for (int nt = 0; nt < 4; nt++)
#pragma unroll
            for (int r = 0; r < 4; r++) { acg[mf][nt][r] = 0.f; acu[mf][nt][r] = 0.f; }

    for (int kk = 0; kk < DM; kk += 32) {
        float a[16];
        if (tokA >= 0) {
#pragma unroll
            for (int j = 0; j < 16; j += 4) {
                float4 t = *reinterpret_cast<const float4*>(Aptr + kk + j);
                a[j] = t.x; a[j + 1] = t.y; a[j + 2] = t.z; a[j + 3] = t.w;
            }
        } else {
#pragma unroll
            for (int j = 0; j < 16; j++) a[j] = 0.f;
        }
        float bg[8], bu[8];
        const float* bgp = WgE + (size_t)(kk + bk0) * FF + f0 + bn;
        const float* bup = WuE + (size_t)(kk + bk0) * FF + f0 + bn;
#pragma unroll
        for (int j = 0; j < 8; j++) { bg[j] = bgp[(size_t)j * FF]; bu[j] = bup[(size_t)j * FF]; }

        __syncthreads();
        unsigned* ap = &As[arow * 36 + akc];
#pragma unroll
        for (int j = 0; j < 16; j++) ap[j] = f2tf(a[j]);
        unsigned* gp = &Bg[bn * 36 + bk0];
        unsigned* up = &Bu[bn * 36 + bk0];
#pragma unroll
        for (int j = 0; j < 8; j++) { gp[j] = f2tf(bg[j]); up[j] = f2tf(bu[j]); }
        __syncthreads();

#pragma unroll
        for (int k8 = 0; k8 < 4; k8++) {
            int k0 = k8 * 8;
            unsigned af[2][4];
#pragma unroll
            for (int mf = 0; mf < 2; mf++) {
                int rb = wm * 32 + mf * 16;
                af[mf][0] = As[(rb + g) * 36 + k0 + c];
                af[mf][1] = As[(rb + g + 8) * 36 + k0 + c];
                af[mf][2] = As[(rb + g) * 36 + k0 + c + 4];
                af[mf][3] = As[(rb + g + 8) * 36 + k0 + c + 4];
            }
#pragma unroll
            for (int nt = 0; nt < 4; nt++) {
                int nb = (wn * 32 + nt * 8 + g) * 36 + k0 + c;
                unsigned b0 = Bg[nb], b1 = Bg[nb + 4];
                mma_tf32(acg[0][nt][0], acg[0][nt][1], acg[0][nt][2], acg[0][nt][3],
                         af[0][0], af[0][1], af[0][2], af[0][3], b0, b1);
                mma_tf32(acg[1][nt][0], acg[1][nt][1], acg[1][nt][2], acg[1][nt][3],
                         af[1][0], af[1][1], af[1][2], af[1][3], b0, b1);
                unsigned u0 = Bu[nb], u1 = Bu[nb + 4];
                mma_tf32(acu[0][nt][0], acu[0][nt][1], acu[0][nt][2], acu[0][nt][3],
                         af[0][0], af[0][1], af[0][2], af[0][3], u0, u1);
                mma_tf32(acu[1][nt][0], acu[1][nt][1], acu[1][nt][2], acu[1][nt][3],
                         af[1][0], af[1][1], af[1][2], af[1][3], u0, u1);
            }
        }
    }

#pragma unroll
    for (int mf = 0; mf < 2; mf++) {
        int r0 = wm * 32 + mf * 16 + g;
        int t0 = toks[r0], t1 = toks[r0 + 8];
#pragma unroll
        for (int nt = 0; nt < 4; nt++) {
            int col = f0 + wn * 32 + nt * 8 + 2 * c;
            if (t0 >= 0) {
                float gv = acg[mf][nt][0], uv = acu[mf][nt][0];
                g_mid[(size_t)t0 * FF + col] = (gv / (1.f + __expf(-gv))) * uv;
                gv = acg[mf][nt][1]; uv = acu[mf][nt][1];
                g_mid[(size_t)t0 * FF + col + 1] = (gv / (1.f + __expf(-gv))) * uv;
            }
            if (t1 >= 0) {
                float gv = acg[mf][nt][2], uv = acu[mf][nt][2];
                g_mid[(size_t)t1 * FF + col] = (gv / (1.f + __expf(-gv))) * uv;
                gv = acg[mf][nt][3]; uv = acu[mf][nt][3];
                g_mid[(size_t)t1 * FF + col + 1] = (gv / (1.f + __expf(-gv))) * uv;
            }
        }
    }
}

__global__ __launch_bounds__(256) void moe_down_tc(const float* __restrict__ Wd,
                                                   float* __restrict__ out) {
    int e = blockIdx.z;
    int count = g_cnt[e];
    int m0 = blockIdx.y * 128;
    if (m0 >= count) return;
    int d0 = blockIdx.x * 64;

    __shared__ int toks[128];
    __shared__ unsigned As[128 * 36];
    __shared__ unsigned Bs[64 * 36];

    int tid = threadIdx.x;
    int lane = tid & 31, w = tid >> 5;
    int wm = w & 3, wn = w >> 2;
    int g = lane >> 2, c = lane & 3;

    if (tid < 128) toks[tid] = (m0 + tid < count) ? g_toklist[e * NTOK + m0 + tid] : -1;
    __syncthreads();

    const float* WdE = Wd + (size_t)e * FF * DM;
    int arow = tid >> 1, akc = (tid & 1) * 16;
    int bn = tid & 63, bk0 = (tid >> 6) * 8;
    int tokA = toks[arow];
    const float* Aptr = (tokA >= 0) ? g_mid + (size_t)tokA * FF + akc : g_mid;

    float acc[2][4][4];
#pragma unroll
    for (int mf = 0; mf < 2; mf++)
#pragma unroll
        for (int nt = 0; nt < 4; nt++)
#pragma unroll
            for (int r = 0; r < 4; r++) acc[mf][nt][r] = 0.f;

    for (int kk = 0; kk < FF; kk += 32) {
        float a[16];
        if (tokA >= 0) {
#pragma unroll
            for (int j = 0; j < 16; j += 4) {
                float4 t = *reinterpret_cast<const float4*>(Aptr + kk + j);
                a[j] = t.x; a[j + 1] = t.y; a[j + 2] = t.z; a[j + 3] = t.w;
            }
        } else {
#pragma unroll
            for (int j = 0; j < 16; j++) a[j] = 0.f;
        }
        float b[8];
        const float* bp = WdE + (size_t)(kk + bk0) * DM + d0 + bn;
#pragma unroll
        for (int j = 0; j < 8; j++) b[j] = bp[(size_t)j * DM];

        __syncthreads();
        unsigned* ap = &As[arow * 36 + akc];
#pragma unroll
        for (int j = 0; j < 16; j++) ap[j] = f2tf(a[j]);
        unsigned* bpp = &Bs[bn * 36 + bk0];
#pragma unroll
        for (int j = 0; j < 8; j++) bpp[j] = f2tf(b[j]);
        __syncthreads();

#pragma unroll
        for (int k8 = 0; k8 < 4; k8++) {
            int k0 = k8 * 8;
            unsigned af[2][4];
#pragma unroll
            for (int mf = 0; mf < 2; mf++) {
                int rb = wm * 32 + mf * 16;
                af[mf][0] = As[(rb + g) * 36 + k0 + c];
                af[mf][1] = As[(rb + g + 8) * 36 + k0 + c];
                af[mf][2] = As[(rb + g) * 36 + k0 + c + 4];
                af[mf][3] = As[(rb + g + 8) * 36 + k0 + c + 4];
            }
#pragma unroll
            for (int nt = 0; nt < 4; nt++) {
                int nb = (wn * 32 + nt * 8 + g) * 36 + k0 + c;
                unsigned b0 = Bs[nb], b1 = Bs[nb + 4];
                mma_tf32(acc[0][nt][0], acc[0][nt][1], acc[0][nt][2], acc[0][nt][3],
                         af[0][0], af[0][1], af[0][2], af[0][3], b0, b1);
                mma_tf32(acc[1][nt][0], acc[1][nt][1], acc[1][nt][2], acc[1][nt][3],
                         af[1][0], af[1][1], af[1][2], af[1][3], b0, b1);
            }
        }
    }

#pragma unroll
    for (int mf = 0; mf < 2; mf++) {
        int r0 = wm * 32 + mf * 16 + g;
        int t0 = toks[r0], t1 = toks[r0 + 8];
#pragma unroll
        for (int nt = 0; nt < 4; nt++) {
            int col = d0 + wn * 32 + nt * 8 + 2 * c;
            if (t0 >= 0) {
                out[(size_t)t0 * DM + col]     += acc[mf][nt][0];
                out[(size_t)t0 * DM + col + 1] += acc[mf][nt][1];
            }
            if (t1 >= 0) {
                out[(size_t)t1 * DM + col]     += acc[mf][nt][2];
                out[(size_t)t1 * DM + col + 1] += acc[mf][nt][3];
            }
        }
    }
}

// ---------------- host orchestration ----------------
extern "C" void kernel_launch(void* const* d_in, const int* in_sizes, int n_in,
                              void* d_out, int out_size) {
    const float* hidden     = (const float*)d_in[0];
    const int*   positions  = (const int*)d_in[1];
    const float* velocity   = (const float*)d_in[2];
    const int*   token_ids  = (const int*)d_in[3];
    const float* mu_prev    = (const float*)d_in[4];
    const float* ln1_w      = (const float*)d_in[5];
    const float* ln2_w      = (const float*)d_in[6];
    const float* wq         = (const float*)d_in[7];
    const float* wk         = (const float*)d_in[8];
    const float* wv         = (const float*)d_in[9];
    const float* wo_w       = (const float*)d_in[10];
    const float* w_mu_q     = (const float*)d_in[11];
    const float* w_mu_k     = (const float*)d_in[12];
    const float* w_mu_v     = (const float*)d_in[13];
    const float* qnorm_w    = (const float*)d_in[14];
    const float* knorm_w    = (const float*)d_in[15];
    const float* dyn_mu     = (const float*)d_in[16];
    const float* dyn_proj   = (const float*)d_in[17];
    const float* ctrl_in_w  = (const float*)d_in[18];
    const float* ctrl_in_b  = (const float*)d_in[19];
    const float* ctrl_out_w = (const float*)d_in[20];
    const float* ctrl_out_b = (const float*)d_in[21];
    const float* mu_router  = (const float*)d_in[22];
    const float* w_gate     = (const float*)d_in[23];
    const float* w_up       = (const float*)d_in[24];
    const float* w_down     = (const float*)d_in[25];

    float* out    = (float*)d_out;
    float* out_h  = out;
    float* out_vn = out + (size_t)NTOK * DM;
    float* out_mu = out + 2 * (size_t)NTOK * DM;

    float *p_h1, *p_oh, *p_o, *p_ctrl, *p_co, *p_x2;
    cudaGetSymbolAddress((void**)&p_h1, g_h1);
    cudaGetSymbolAddress((void**)&p_oh, g_oh);
    cudaGetSymbolAddress((void**)&p_o, g_o);
    cudaGetSymbolAddress((void**)&p_ctrl, g_ctrl);
    cudaGetSymbolAddress((void**)&p_co, g_co);
    cudaGetSymbolAddress((void**)&p_x2, g_x2);

    // 1. h = rmsnorm(hidden, ln1_w)
    rmsnorm_kernel<<<NTOK, 256>>>(hidden, ln1_w, p_h1);

    // 2. fused qkv, 3xTF32 tensor cores (fp32-class precision)
    qkv3_tc<<<dim3(24, NTOK / 128), 256>>>(p_h1, mu_prev, wq, w_mu_q, wk, w_mu_k, wv, w_mu_v);

    // 3. per-head rmsnorm + RoPE
    qknorm_rope_kernel<<<dim3(NTOK, NH + NKV), 64>>>(positions, qnorm_w, knorm_w);

    // 4. split-K flash attention + combine
    attn_split_kernel<<<dim3(NTOK / 128, NH, ASPLIT), 128>>>();
    attn_combine_kernel<<<(NTOK * NH * DHD) / 256, 256>>>();

    // 5. o = oh @ wo (3xTF32)
    gemm3_tc<<<dim3(DM / 64, NTOK / 128), 256>>>(p_oh, wo_w, nullptr, p_o, NH * DHD, DM, 0);

    // 6. mu_cur = dyn_mu + o @ dyn_mu_proj_w (3xTF32)
    gemm3_tc<<<dim3(DM / 64, NTOK / 128), 256>>>(p_o, dyn_proj, dyn_mu, out_mu, DM, DM, 1);

    // 7. ctrl = silu([o | velocity] @ ctrl_in_w + b)  (fp32 SIMT, small)
    gemm_kernel<<<dim3(CHN / 64, NTOK / 64), 256>>>(p_o, velocity, ctrl_in_w,
                                                    ctrl_in_w + (size_t)DM * CHN, ctrl_in_b,
                                                    p_ctrl, DM, CHN, 2);

    // 8. co = ctrl @ ctrl_out_w + ctrl_out_b (fp32 SIMT, small K)
    gemm_kernel<<<dim3((3 * DM) / 64, NTOK / 64), 256>>>(p_ctrl, nullptr, ctrl_out_w, nullptr,
                                                         ctrl_out_b, p_co, CHN, 3 * DM, 1);

    // 9. dynamics
    dynamics_kernel<<<(NTOK * DM) / 256, 256>>>(hidden, velocity, out_mu, out_h, out_vn);

    // 10. x = rmsnorm(hidden2, ln2_w)
    rmsnorm_kernel<<<NTOK, 256>>>(out_h, ln2_w, p_x2);

    // 11. routing
    zero_cnt_kernel<<<1, 32>>>();
    router_kernel<<<NTOK / 32, 256>>>(out_mu, token_ids, mu_router);

    // 12. MoE (1x tf32 tensor cores — diluted error path)
    moe_gateup_tc<<<dim3(FF / 64, NTOK / 128, NEXP), 256>>>(p_x2, w_gate, w_up);
    moe_down_tc<<<dim3(DM / 64, NTOK / 128, NEXP), 256>>>(w_down, out_h);
}

// round 11
// speedup vs baseline: 1.7471x; 1.3022x over previous
#include <cuda_runtime.h>
#include <math.h>

#define NTOK 2048
#define DM   1024
#define NH   16
#define NKV  4
#define DHD  64
#define NEXP 8
#define FF   2048
#define CHN  64
#define EPSV 1e-6f

// ---------------- scratch (device globals; no allocation allowed) ----------------
__device__ float g_h1[NTOK * DM];
__device__ float g_q[NTOK * NH * DHD];
__device__ float g_k[NTOK * NKV * DHD];
__device__ float g_v[NTOK * NKV * DHD];
__device__ float g_oh[NTOK * NH * DHD];
__device__ float g_o[NTOK * DM];
__device__ float g_ctrl[NTOK * CHN];
__device__ float g_co[NTOK * 3 * DM];
__device__ float g_x2[NTOK * DM];
__device__ float g_mid[NTOK * FF];
__device__ int   g_cnt[NEXP];
__device__ int   g_toklist[NEXP * NTOK];

// ---------------- tf32 helpers ----------------
__device__ __forceinline__ unsigned f2tf(float f) {
    unsigned u;
    asm("cvt.rna.tf32.f32 %0, %1;" : "=r"(u) : "f"(f));
    return u;
}
__device__ __forceinline__ void split_tf(float x, unsigned& hi, unsigned& lo) {
    hi = f2tf(x);
    float r = x - __uint_as_float(hi);
    lo = f2tf(r);
}
__device__ __forceinline__ void mma_tf32(float& c0, float& c1, float& c2, float& c3,
                                         unsigned a0, unsigned a1, unsigned a2, unsigned a3,
                                         unsigned b0, unsigned b1) {
    asm("mma.sync.aligned.m16n8k8.row.col.f32.tf32.tf32.f32 "
        "{%0,%1,%2,%3},{%4,%5,%6,%7},{%8,%9},{%0,%1,%2,%3};"
        : "+f"(c0), "+f"(c1), "+f"(c2), "+f"(c3)
        : "r"(a0), "r"(a1), "r"(a2), "r"(a3), "r"(b0), "r"(b1));
}

// ---------------- rmsnorm over D=1024 ----------------
__global__ void rmsnorm_kernel(const float* __restrict__ x, const float* __restrict__ w,
                               float* __restrict__ out) {
    int n = blockIdx.x;
    int t = threadIdx.x;
    const float4* xr = reinterpret_cast<const float4*>(x + (size_t)n * DM);
    float4 v = xr[t];
    __shared__ float red[256];
    red[t] = v.x * v.x + v.y * v.y + v.z * v.z + v.w * v.w;
    __syncthreads();
    for (int s = 128; s > 0; s >>= 1) {
        if (t < s) red[t] += red[t + s];
        __syncthreads();
    }
    float sc = rsqrtf(red[0] * (1.0f / DM) + EPSV);
    float4 wv = reinterpret_cast<const float4*>(w)[t];
    float4 o = make_float4(v.x * sc * wv.x, v.y * sc * wv.y, v.z * sc * wv.z, v.w * sc * wv.w);
    reinterpret_cast<float4*>(out + (size_t)n * DM)[t] = o;
}

// ---------------- fp32 SIMT GEMM (kept for small ctrl GEMMs) ----------------
__global__ __launch_bounds__(256) void gemm_kernel(
    const float* __restrict__ A1, const float* __restrict__ A2,
    const float* __restrict__ B1, const float* __restrict__ B2,
    const float* __restrict__ bias, float* __restrict__ C,
    int Kd, int Nc, int epi) {
    __shared__ __align__(16) float As[16 * 68];
    __shared__ __align__(16) float Bs[16 * 64];
    int m0 = blockIdx.y * 64, n0 = blockIdx.x * 64;
    int tid = threadIdx.x;
    int tx = tid & 15, ty = tid >> 4;
    float acc[4][4];
#pragma unroll
    for (int i = 0; i < 4; i++)
#pragma unroll
        for (int j = 0; j < 4; j++) acc[i][j] = 0.f;

    int nparts = (A2 != nullptr) ? 2 : 1;
    for (int part = 0; part < nparts; ++part) {
        const float* A = part ? A2 : A1;
        const float* B = part ? B2 : B1;
        for (int kk = 0; kk < Kd; kk += 16) {
            int idx = tid * 4;
            int arow = idx >> 4, ak = idx & 15;
            float4 av = *reinterpret_cast<const float4*>(A + (size_t)(m0 + arow) * Kd + kk + ak);
            As[(ak + 0) * 68 + arow] = av.x;
            As[(ak + 1) * 68 + arow] = av.y;
            As[(ak + 2) * 68 + arow] = av.z;
            As[(ak + 3) * 68 + arow] = av.w;
            int bk = idx >> 6, bn = idx & 63;
            *reinterpret_cast<float4*>(&Bs[bk * 64 + bn]) =
                *reinterpret_cast<const float4*>(B + (size_t)(kk + bk) * Nc + n0 + bn);
            __syncthreads();
#pragma unroll
            for (int k = 0; k < 16; k++) {
                float4 a = *reinterpret_cast<const float4*>(&As[k * 68 + ty * 4]);
                float4 b = *reinterpret_cast<const float4*>(&Bs[k * 64 + tx * 4]);
                float ar[4] = {a.x, a.y, a.z, a.w};
                float br[4] = {b.x, b.y, b.z, b.w};
#pragma unroll
                for (int i = 0; i < 4; i++)
#pragma unroll
                    for (int j = 0; j < 4; j++) acc[i][j] += ar[i] * br[j];
            }
            __syncthreads();
        }
    }
#pragma unroll
    for (int i = 0; i < 4; i++) {
        int row = m0 + ty * 4 + i;
#pragma unroll
        for (int j = 0; j < 4; j++) {
            int col = n0 + tx * 4 + j;
            float v = acc[i][j];
            if (epi >= 1) v += bias[col];
            if (epi == 2) v = v / (1.f + __expf(-v));
            C[(size_t)row * Nc + col] = v;
        }
    }
}

// ================= 3xTF32 tensor-core GEMM (fp32-class precision) =================
struct TcTile {
    unsigned Ah[128 * 20];
    unsigned Al[128 * 20];
    unsigned Bh[64 * 20];
    unsigned Bl[64 * 20];
};

__device__ __forceinline__ void tc3_chunk(TcTile* s, int wm, int wn, int g, int c,
                                          float acc[2][4][4]) {
#pragma unroll
    for (int k8 = 0; k8 < 2; k8++) {
        int k0 = k8 * 8;
        unsigned ah[2][4], al[2][4];
#pragma unroll
        for (int mf = 0; mf < 2; mf++) {
            int rb = wm * 32 + mf * 16;
            ah[mf][0] = s->Ah[(rb + g) * 20 + k0 + c];
            ah[mf][1] = s->Ah[(rb + g + 8) * 20 + k0 + c];
            ah[mf][2] = s->Ah[(rb + g) * 20 + k0 + c + 4];
            ah[mf][3] = s->Ah[(rb + g + 8) * 20 + k0 + c + 4];
            al[mf][0] = s->Al[(rb + g) * 20 + k0 + c];
            al[mf][1] = s->Al[(rb + g + 8) * 20 + k0 + c];
            al[mf][2] = s->Al[(rb + g) * 20 + k0 + c + 4];
            al[mf][3] = s->Al[(rb + g + 8) * 20 + k0 + c + 4];
        }
#pragma unroll
        for (int nt = 0; nt < 4; nt++) {
            int nb = (wn * 32 + nt * 8 + g) * 20 + k0 + c;
            unsigned bh0 = s->Bh[nb], bh1 = s->Bh[nb + 4];
            unsigned bl0 = s->Bl[nb], bl1 = s->Bl[nb + 4];
#pragma unroll
            for (int mf = 0; mf < 2; mf++) {
                mma_tf32(acc[mf][nt][0], acc[mf][nt][1], acc[mf][nt][2], acc[mf][nt][3],
                         ah[mf][0], ah[mf][1], ah[mf][2], ah[mf][3], bh0, bh1);
                mma_tf32(acc[mf][nt][0], acc[mf][nt][1], acc[mf][nt][2], acc[mf][nt][3],
                         ah[mf][0], ah[mf][1], ah[mf][2], ah[mf][3], bl0, bl1);
                mma_tf32(acc[mf][nt][0], acc[mf][nt][1], acc[mf][nt][2], acc[mf][nt][3],
                         al[mf][0], al[mf][1], al[mf][2], al[mf][3], bh0, bh1);
            }
        }
    }
}

__device__ __forceinline__ void tc3_load(TcTile* s, const float* __restrict__ A,
                                         const float* __restrict__ B, int Kd, int Nc,
                                         int m0, int n0, int kk, int tid) {
    int arow = tid >> 1, akc = (tid & 1) * 8;
    const float* ap = A + (size_t)(m0 + arow) * Kd + kk + akc;
    float a[8];
#pragma unroll
    for (int j = 0; j < 8; j += 4) {
        float4 t = *reinterpret_cast<const float4*>(ap + j);
        a[j] = t.x; a[j + 1] = t.y; a[j + 2] = t.z; a[j + 3] = t.w;
    }
    int bn = tid & 63, bk0 = (tid >> 6) * 4;
    const float* bp = B + (size_t)(kk + bk0) * Nc + n0 + bn;
    float b[4];
#pragma unroll
    for (int j = 0; j < 4; j++) b[j] = bp[(size_t)j * Nc];

    __syncthreads();
    unsigned* ah = &s->Ah[arow * 20 + akc];
    unsigned* al = &s->Al[arow * 20 + akc];
#pragma unroll
    for (int j = 0; j < 8; j++) split_tf(a[j], ah[j], al[j]);
    unsigned* bh = &s->Bh[bn * 20 + bk0];
    unsigned* bl = &s->Bl[bn * 20 + bk0];
#pragma unroll
    for (int j = 0; j < 4; j++) split_tf(b[j], bh[j], bl[j]);
    __syncthreads();
}

__global__ __launch_bounds__(256) void gemm3_tc(const float* __restrict__ A,
                                                const float* __restrict__ B,
                                                const float* __restrict__ bias,
                                                float* __restrict__ C, int Kd, int Nc, int epi) {
    __shared__ TcTile s;
    int m0 = blockIdx.y * 128, n0 = blockIdx.x * 64;
    int tid = threadIdx.x;
    int lane = tid & 31, w = tid >> 5;
    int wm = w & 3, wn = w >> 2;
    int g = lane >> 2, c = lane & 3;

    float acc[2][4][4];
#pragma unroll
    for (int mf = 0; mf < 2; mf++)
#pragma unroll
        for (int nt = 0; nt < 4; nt++)
#pragma unroll
            for (int r = 0; r < 4; r++) acc[mf][nt][r] = 0.f;

    for (int kk = 0; kk < Kd; kk += 16) {
        tc3_load(&s, A, B, Kd, Nc, m0, n0, kk, tid);
        tc3_chunk(&s, wm, wn, g, c, acc);
    }

#pragma unroll
    for (int mf = 0; mf < 2; mf++) {
        int r0 = m0 + wm * 32 + mf * 16 + g;
#pragma unroll
        for (int nt = 0; nt < 4; nt++) {
            int col = n0 + wn * 32 + nt * 8 + 2 * c;
#pragma unroll
            for (int half = 0; half < 2; half++) {
                int row = r0 + half * 8;
                float v0 = acc[mf][nt][half * 2 + 0];
                float v1 = acc[mf][nt][half * 2 + 1];
                if (epi >= 1) { v0 += bias[col]; v1 += bias[col + 1]; }
                C[(size_t)row * Nc + col]     = v0;
                C[(size_t)row * Nc + col + 1] = v1;
            }
        }
    }
}

// fused qkv 3xTF32
__global__ __launch_bounds__(256) void qkv3_tc(
    const float* __restrict__ A1, const float* __restrict__ A2,
    const float* __restrict__ wq, const float* __restrict__ wmq,
    const float* __restrict__ wk, const float* __restrict__ wmk,
    const float* __restrict__ wv, const float* __restrict__ wmv) {
    __shared__ TcTile s;
    int ntile = blockIdx.x;
    int m0 = blockIdx.y * 128;
    const float *B1, *B2;
    float* C;
    int Nc, n0;
    if (ntile < 16)      { B1 = wq; B2 = wmq; C = g_q; Nc = NH * DHD;  n0 = ntile * 64; }
    else if (ntile < 20) { B1 = wk; B2 = wmk; C = g_k; Nc = NKV * DHD; n0 = (ntile - 16) * 64; }
    else                 { B1 = wv; B2 = wmv; C = g_v; Nc = NKV * DHD; n0 = (ntile - 20) * 64; }

    int tid = threadIdx.x;
    int lane = tid & 31, w = tid >> 5;
    int wm = w & 3, wn = w >> 2;
    int g = lane >> 2, c = lane & 3;

    float acc[2][4][4];
#pragma unroll
    for (int mf = 0; mf < 2; mf++)
#pragma unroll
        for (int nt = 0; nt < 4; nt++)
#pragma unroll
            for (int r = 0; r < 4; r++) acc[mf][nt][r] = 0.f;

    for (int part = 0; part < 2; ++part) {
        const float* A = part ? A2 : A1;
        const float* B = part ? B2 : B1;
        for (int kk = 0; kk < DM; kk += 16) {
            tc3_load(&s, A, B, DM, Nc, m0, n0, kk, tid);
            tc3_chunk(&s, wm, wn, g, c, acc);
        }
    }

#pragma unroll
    for (int mf = 0; mf < 2; mf++) {
        int r0 = m0 + wm * 32 + mf * 16 + g;
#pragma unroll
        for (int nt = 0; nt < 4; nt++) {
            int col = n0 + wn * 32 + nt * 8 + 2 * c;
#pragma unroll
            for (int half = 0; half < 2; half++) {
                int row = r0 + half * 8;
                C[(size_t)row * Nc + col]     = acc[mf][nt][half * 2 + 0];
                C[(size_t)row * Nc + col + 1] = acc[mf][nt][half * 2 + 1];
            }
        }
    }
}

// ---------------- per-(token,head) rmsnorm + RoPE for q and k ----------------
__global__ void qknorm_rope_kernel(const int* __restrict__ positions,
                                   const float* __restrict__ qw, const float* __restrict__ kw) {
    int n = blockIdx.x;
    int hh = blockIdx.y;
    int d = threadIdx.x;
    float* ptr;
    const float* w;
    if (hh < NH) { ptr = g_q + (size_t)n * (NH * DHD) + hh * DHD; w = qw; }
    else         { ptr = g_k + (size_t)n * (NKV * DHD) + (hh - NH) * DHD; w = kw; }
    float x = ptr[d];
    __shared__ float sh[64];
    __shared__ float xs[64];
    sh[d] = x * x;
    __syncthreads();
    for (int s = 32; s > 0; s >>= 1) {
        if (d < s) sh[d] += sh[d + s];
        __syncthreads();
    }
    float sc = rsqrtf(sh[0] * (1.0f / DHD) + EPSV);
    float xn = x * sc * w[d];
    xs[d] = xn;
    __syncthreads();
    float pos = (float)positions[n];
    int i = d & 31;
    float inv = (float)exp(-((double)(2 * i) / 64.0) * log(10000.0));
    float ang = pos * inv;
    float c = cosf(ang), s = sinf(ang);
    float out = (d < 32) ? (xn * c - xs[d + 32] * s) : (xn * c + xs[d - 32] * s);
    ptr[d] = out;
}

// ================= tf32 tensor-core flash attention =================
// Block: 128 queries x 1 head. 8 warps; warp w owns rows w*16..w*16+15, ALL 64 cols
// (row softmax = intra-quad shfl only). Per 64-key tile:
//   S = Q@K^T (tf32 mma), fragment online softmax, P->smem tf32, O += P@V^T.
// smem (dynamic, 102KB): Qs[128][68], Ks[64][68] key-major, Vt[64][68] dim-major, Ps[128][68].
// stride 68 -> frag-access bank = (4g+c) mod 32: conflict-free.
#define ATTN_SMEM ((128 * 68 + 64 * 68 + 64 * 68 + 128 * 68) * 4)

__global__ __launch_bounds__(256) void attn_tc_kernel() {
    extern __shared__ unsigned asm_u[];
    unsigned* Qs = asm_u;                    // [128][68] tf32 (pre-scaled by 0.125)
    unsigned* Ks = Qs + 128 * 68;            // [64][68]  K[key][dim]
    unsigned* Vt = Ks + 64 * 68;             // [64][68]  V^T[dim][key]
    unsigned* Ps = Vt + 64 * 68;             // [128][68] P[row][key]

    int h = blockIdx.y;
    int q0 = blockIdx.x * 128;
    int kvh = h >> 2;
    int tid = threadIdx.x;
    int lane = tid & 31, w = tid >> 5;
    int g = lane >> 2, c = lane & 3;
    int qbase = w * 16;

    // stage Q once (scaled)
    {
        int row = tid >> 1;
        int d0 = (tid & 1) * 32;
        const float* qp = g_q + ((size_t)(q0 + row) * NH + h) * DHD + d0;
        unsigned* dst = Qs + row * 68 + d0;
#pragma unroll
        for (int j = 0; j < 32; j += 4) {
            float4 t = *reinterpret_cast<const float4*>(qp + j);
            dst[j]     = f2tf(t.x * 0.125f);
            dst[j + 1] = f2tf(t.y * 0.125f);
            dst[j + 2] = f2tf(t.z * 0.125f);
            dst[j + 3] = f2tf(t.w * 0.125f);
        }
    }

    float oacc[8][4];
#pragma unroll
    for (int nt = 0; nt < 8; nt++)
#pragma unroll
        for (int r = 0; r < 4; r++) oacc[nt][r] = 0.f;
    float mrun0 = -1e30f, mrun1 = -1e30f, lrun0 = 0.f, lrun1 = 0.f;

    const int krow = tid >> 2;          // 0..63 (key within tile)
    const int kd0 = (tid & 3) * 16;     // dim chunk

    for (int kt = 0; kt < NTOK; kt += 64) {
        // load K tile (key-major) and V tile transposed (dim-major)
        {
            const float* kp = g_k + ((size_t)(kt + krow) * NKV + kvh) * DHD + kd0;
            unsigned* dst = Ks + krow * 68 + kd0;
#pragma unroll
            for (int j = 0; j < 16; j += 4) {
                float4 t = *reinterpret_cast<const float4*>(kp + j);
                dst[j] = f2tf(t.x); dst[j + 1] = f2tf(t.y);
                dst[j + 2] = f2tf(t.z); dst[j + 3] = f2tf(t.w);
            }
            const float* vp = g_v + ((size_t)(kt + krow) * NKV + kvh) * DHD + kd0;
#pragma unroll
            for (int j = 0; j < 16; j += 4) {
                float4 t = *reinterpret_cast<const float4*>(vp + j);
                Vt[(kd0 + j)     * 68 + krow] = f2tf(t.x);
                Vt[(kd0 + j + 1) * 68 + krow] = f2tf(t.y);
                Vt[(kd0 + j + 2) * 68 + krow] = f2tf(t.z);
                Vt[(kd0 + j + 3) * 68 + krow] = f2tf(t.w);
            }
        }
        __syncthreads();

        // S = Q @ K^T  (16 rows x 64 keys per warp)
        float sacc[8][4];
#pragma unroll
        for (int nt = 0; nt < 8; nt++)
#pragma unroll
            for (int r = 0; r < 4; r++) sacc[nt][r] = 0.f;
#pragma unroll
        for (int k8 = 0; k8 < 8; k8++) {
            int k0 = k8 * 8;
            unsigned a0 = Qs[(qbase + g) * 68 + k0 + c];
            unsigned a1 = Qs[(qbase + g + 8) * 68 + k0 + c];
            unsigned a2 = Qs[(qbase + g) * 68 + k0 + c + 4];
            unsigned a3 = Qs[(qbase + g + 8) * 68 + k0 + c + 4];
#pragma unroll
            for (int nt = 0; nt < 8; nt++) {
                int nb = (nt * 8 + g) * 68 + k0 + c;
                mma_tf32(sacc[nt][0], sacc[nt][1], sacc[nt][2], sacc[nt][3],
                         a0, a1, a2, a3, Ks[nb], Ks[nb + 4]);
            }
        }

        // fragment online softmax (row g -> c0,c1 ; row g+8 -> c2,c3)
        float mx0 = -1e30f, mx1 = -1e30f;
#pragma unroll
        for (int nt = 0; nt < 8; nt++) {
            mx0 = fmaxf(mx0, fmaxf(sacc[nt][0], sacc[nt][1]));
            mx1 = fmaxf(mx1, fmaxf(sacc[nt][2], sacc[nt][3]));
        }
        mx0 = fmaxf(mx0, __shfl_xor_sync(0xffffffffu, mx0, 1));
        mx0 = fmaxf(mx0, __shfl_xor_sync(0xffffffffu, mx0, 2));
        mx1 = fmaxf(mx1, __shfl_xor_sync(0xffffffffu, mx1, 1));
        mx1 = fmaxf(mx1, __shfl_xor_sync(0xffffffffu, mx1, 2));
        float mn0 = fmaxf(mrun0, mx0);
        float mn1 = fmaxf(mrun1, mx1);
        float corr0 = __expf(mrun0 - mn0);
        float corr1 = __expf(mrun1 - mn1);
#pragma unroll
        for (int nt = 0; nt < 8; nt++) {
            oacc[nt][0] *= corr0; oacc[nt][1] *= corr0;
            oacc[nt][2] *= corr1; oacc[nt][3] *= corr1;
        }
        float ps0 = 0.f, ps1 = 0.f;
#pragma unroll
        for (int nt = 0; nt < 8; nt++) {
            float p00 = __expf(sacc[nt][0] - mn0);
            float p01 = __expf(sacc[nt][1] - mn0);
            float p10 = __expf(sacc[nt][2] - mn1);
            float p11 = __expf(sacc[nt][3] - mn1);
            ps0 += p00 + p01;
            ps1 += p10 + p11;
            int colb = nt * 8 + 2 * c;
            uint2 v0; v0.x = f2tf(p00); v0.y = f2tf(p01);
            uint2 v1; v1.x = f2tf(p10); v1.y = f2tf(p11);
            *reinterpret_cast<uint2*>(&Ps[(qbase + g) * 68 + colb])     = v0;
            *reinterpret_cast<uint2*>(&Ps[(qbase + g + 8) * 68 + colb]) = v1;
        }
        ps0 += __shfl_xor_sync(0xffffffffu, ps0, 1);
        ps0 += __shfl_xor_sync(0xffffffffu, ps0, 2);
        ps1 += __shfl_xor_sync(0xffffffffu, ps1, 1);
        ps1 += __shfl_xor_sync(0xffffffffu, ps1, 2);
        lrun0 = lrun0 * corr0 + ps0;
        lrun1 = lrun1 * corr1 + ps1;
        mrun0 = mn0;
        mrun1 = mn1;
        __syncwarp();  // P rows of this warp written before its own A-frag reads

        // O += P @ V^T  (k = keys, n = dims)
#pragma unroll
        for (int k8 = 0; k8 < 8; k8++) {
            int k0 = k8 * 8;
            unsigned a0 = Ps[(qbase + g) * 68 + k0 + c];
            unsigned a1 = Ps[(qbase + g + 8) * 68 + k0 + c];
            unsigned a2 = Ps[(qbase + g) * 68 + k0 + c + 4];
            unsigned a3 = Ps[(qbase + g + 8) * 68 + k0 + c + 4];
#pragma unroll
            for (int nt = 0; nt < 8; nt++) {
                int nb = (nt * 8 + g) * 68 + k0 + c;
                mma_tf32(oacc[nt][0], oacc[nt][1], oacc[nt][2], oacc[nt][3],
                         a0, a1, a2, a3, Vt[nb], Vt[nb + 4]);
            }
        }
        __syncthreads();  // all warps done with Ks/Vt before next tile overwrites
    }

    float rl0 = 1.f / lrun0;
    float rl1 = 1.f / lrun1;
    float* o0 = g_oh + ((size_t)(q0 + qbase + g) * NH + h) * DHD;
    float* o1 = g_oh + ((size_t)(q0 + qbase + g + 8) * NH + h) * DHD;
#pragma unroll
    for (int nt = 0; nt < 8; nt++) {
        int colb = nt * 8 + 2 * c;
        *reinterpret_cast<float2*>(o0 + colb) = make_float2(oacc[nt][0] * rl0, oacc[nt][1] * rl0);
        *reinterpret_cast<float2*>(o1 + colb) = make_float2(oacc[nt][2] * rl1, oacc[nt][3] * rl1);
    }
}

// ---------------- control dynamics elementwise ----------------
__global__ void dynamics_kernel(const float* __restrict__ hidden, const float* __restrict__ velocity,
                                const float* __restrict__ mu, float* __restrict__ out_h2,
                                float* __restrict__ out_vn) {
    int idx = blockIdx.x * 256 + threadIdx.x;
    int n = idx >> 10;
    int d = idx & 1023;
    const float* co = g_co + (size_t)n * 3 * DM;
    float ar = co[d], br = co[DM + d], gr = co[2 * DM + d];
    float alpha = 1.f / (1.f + expf(-ar));
    float sp = fmaxf(br, 0.f) + log1pf(expf(-fabsf(br)));
    float beta = fminf(sp, 2.f);
    float gate = 1.f / (1.f + expf(-gr));
    float o = g_o[idx], mv = mu[idx], vel = velocity[idx];
    float vn = alpha * vel - beta * (o - mv);
    vn = fminf(fmaxf(vn, -10.f), 10.f);
    out_h2[idx] = hidden[idx] + o + 0.1f * gate * vn;
    out_vn[idx] = vn;
}

// ---------------- router ----------------
__global__ void zero_cnt_kernel() {
    if (threadIdx.x < NEXP) g_cnt[threadIdx.x] = 0;
}

__global__ void router_kernel(const float* __restrict__ mu, const int* __restrict__ token_ids,
                              const float* __restrict__ Wr) {
    int tid = threadIdx.x;
    int tl = tid >> 3, e = tid & 7;
    int n = blockIdx.x * 32 + tl;
    const float* mr = mu + (size_t)n * DM;
    float s = 0.f;
    for (int d = 0; d < DM; d++) s += mr[d] * Wr[d * NEXP + e];
    __shared__ float lg[32][8];
    lg[tl][e] = s;
    __syncthreads();
    if (e == 0) {
        int base = token_ids[n] % NEXP;
        float best = -1e30f;
        int bi = 0;
#pragma unroll
        for (int j = 0; j < 8; j++) {
            float c = lg[tl][j] + (j == base ? 10.0f : 0.0f);
            if (c > best) { best = c; bi = j; }
        }
        int slot = atomicAdd(&g_cnt[bi], 1);
        g_toklist[bi * NTOK + slot] = n;
    }
}

// ================= 1x tf32 tensor-core MoE =================
__global__ __launch_bounds__(256) void moe_gateup_tc(const float* __restrict__ X,
                                                     const float* __restrict__ Wg,
                                                     const float* __restrict__ Wu) {
    int e = blockIdx.z;
    int count = g_cnt[e];
    int m0 = blockIdx.y * 128;
    if (m0 >= count) return;
    int f0 = blockIdx.x * 64;

    __shared__ int toks[128];
    __shared__ unsigned As[128 * 36];
    __shared__ unsigned Bg[64 * 36];
    __shared__ unsigned Bu[64 * 36];

    int tid = threadIdx.x;
    int lane = tid & 31, w = tid >> 5;
    int wm = w & 3, wn = w >> 2;
    int g = lane >> 2, c = lane & 3;

    if (tid < 128) toks[tid] = (m0 + tid < count) ? g_toklist[e * NTOK + m0 + tid] : -1;
    __syncthreads();

    const float* WgE = Wg + (size_t)e * DM * FF;
    const float* WuE = Wu + (size_t)e * DM * FF;

    int arow = tid >> 1, akc = (tid & 1) * 16;
    int bn = tid & 63, bk0 = (tid >> 6) * 8;
    int tokA = toks[arow];
    const float* Aptr = (tokA >= 0) ? X + (size_t)tokA * DM + akc : X;

    float acg[2][4][4], acu[2][4][4];
#pragma unroll
    for (int mf = 0; mf < 2; mf++)
#pragma unroll
        for (int nt = 0; nt < 4; nt++)
#pragma unroll
            for (int r = 0; r < 4; r++) { acg[mf][nt][r] = 0.f; acu[mf][nt][r] = 0.f; }

    for (int kk = 0; kk < DM; kk += 32) {
        float a[16];
        if (tokA >= 0) {
#pragma unroll
            for (int j = 0; j < 16; j += 4) {
                float4 t = *reinterpret_cast<const float4*>(Aptr + kk + j);
                a[j] = t.x; a[j + 1] = t.y; a[j + 2] = t.z; a[j + 3] = t.w;
            }
        } else {
#pragma unroll
            for (int j = 0; j < 16; j++) a[j] = 0.f;
        }
        float bg[8], bu[8];
        const float* bgp = WgE + (size_t)(kk + bk0) * FF + f0 + bn;
        const float* bup = WuE + (size_t)(kk + bk0) * FF + f0 + bn;
#pragma unroll
        for (int j = 0; j < 8; j++) { bg[j] = bgp[(size_t)j * FF]; bu[j] = bup[(size_t)j * FF]; }

        __syncthreads();
        unsigned* ap = &As[arow * 36 + akc];
#pragma unroll
        for (int j = 0; j < 16; j++) ap[j] = f2tf(a[j]);
        unsigned* gp = &Bg[bn * 36 + bk0];
        unsigned* up = &Bu[bn * 36 + bk0];
#pragma unroll
        for (int j = 0; j < 8; j++) { gp[j] = f2tf(bg[j]); up[j] = f2tf(bu[j]); }
        __syncthreads();

#pragma unroll
        for (int k8 = 0; k8 < 4; k8++) {
            int k0 = k8 * 8;
            unsigned af[2][4];
#pragma unroll
            for (int mf = 0; mf < 2; mf++) {
                int rb = wm * 32 + mf * 16;
                af[mf][0] = As[(rb + g) * 36 + k0 + c];
                af[mf][1] = As[(rb + g + 8) * 36 + k0 + c];
                af[mf][2] = As[(rb + g) * 36 + k0 + c + 4];
                af[mf][3] = As[(rb + g + 8) * 36 + k0 + c + 4];
            }
#pragma unroll
            for (int nt = 0; nt < 4; nt++) {
                int nb = (wn * 32 + nt * 8 + g) * 36 + k0 + c;
                unsigned b0 = Bg[nb], b1 = Bg[nb + 4];
                mma_tf32(acg[0][nt][0], acg[0][nt][1], acg[0][nt][2], acg[0][nt][3],
                         af[0][0], af[0][1], af[0][2], af[0][3], b0, b1);
                mma_tf32(acg[1][nt][0], acg[1][nt][1], acg[1][nt][2], acg[1][nt][3],
                         af[1][0], af[1][1], af[1][2], af[1][3], b0, b1);
                unsigned u0 = Bu[nb], u1 = Bu[nb + 4];
                mma_tf32(acu[0][nt][0], acu[0][nt][1], acu[0][nt][2], acu[0][nt][3],
                         af[0][0], af[0][1], af[0][2], af[0][3], u0, u1);
                mma_tf32(acu[1][nt][0], acu[1][nt][1], acu[1][nt][2], acu[1][nt][3],
                         af[1][0], af[1][1], af[1][2], af[1][3], u0, u1);
            }
        }
    }

#pragma unroll
    for (int mf = 0; mf < 2; mf++) {
        int r0 = wm * 32 + mf * 16 + g;
        int t0 = toks[r0], t1 = toks[r0 + 8];
#pragma unroll
        for (int nt = 0; nt < 4; nt++) {
            int col = f0 + wn * 32 + nt * 8 + 2 * c;
            if (t0 >= 0) {
                float gv = acg[mf][nt][0], uv = acu[mf][nt][0];
                g_mid[(size_t)t0 * FF + col] = (gv / (1.f + __expf(-gv))) * uv;
                gv = acg[mf][nt][1]; uv = acu[mf][nt][1];
                g_mid[(size_t)t0 * FF + col + 1] = (gv / (1.f + __expf(-gv))) * uv;
            }
            if (t1 >= 0) {
                float gv = acg[mf][nt][2], uv = acu[mf][nt][2];
                g_mid[(size_t)t1 * FF + col] = (gv / (1.f + __expf(-gv))) * uv;
                gv = acg[mf][nt][3]; uv = acu[mf][nt][3];
                g_mid[(size_t)t1 * FF + col + 1] = (gv / (1.f + __expf(-gv))) * uv;
            }
        }
    }
}

__global__ __launch_bounds__(256) void moe_down_tc(const float* __restrict__ Wd,
                                                   float* __restrict__ out) {
    int e = blockIdx.z;
    int count = g_cnt[e];
    int m0 = blockIdx.y * 128;
    if (m0 >= count) return;
    int d0 = blockIdx.x * 64;

    __shared__ int toks[128];
    __shared__ unsigned As[128 * 36];
    __shared__ unsigned Bs[64 * 36];

    int tid = threadIdx.x;
    int lane = tid & 31, w = tid >> 5;
    int wm = w & 3, wn = w >> 2;
    int g = lane >> 2, c = lane & 3;

    if (tid < 128) toks[tid] = (m0 + tid < count) ? g_toklist[e * NTOK + m0 + tid] : -1;
    __syncthreads();

    const float* WdE = Wd + (size_t)e * FF * DM;
    int arow = tid >> 1, akc = (tid & 1) * 16;
    int bn = tid & 63, bk0 = (tid >> 6) * 8;
    int tokA = toks[arow];
    const float* Aptr = (tokA >= 0) ? g_mid + (size_t)tokA * FF + akc : g_mid;

    float acc[2][4][4];
#pragma unroll
    for (int mf = 0; mf < 2; mf++)
#pragma unroll
        for (int nt = 0; nt < 4; nt++)
#pragma unroll
            for (int r = 0; r < 4; r++) acc[mf][nt][r] = 0.f;

    for (int kk = 0; kk < FF; kk += 32) {
        float a[16];
        if (tokA >= 0) {
#pragma unroll
            for (int j = 0; j < 16; j += 4) {
                float4 t = *reinterpret_cast<const float4*>(Aptr + kk + j);
                a[j] = t.x; a[j + 1] = t.y; a[j + 2] = t.z; a[j + 3] = t.w;
            }
        } else {
#pragma unroll
            for (int j = 0; j < 16; j++) a[j] = 0.f;
        }
        float b[8];
        const float* bp = WdE + (size_t)(kk + bk0) * DM + d0 + bn;
#pragma unroll
        for (int j = 0; j < 8; j++) b[j] = bp[(size_t)j * DM];

        __syncthreads();
        unsigned* ap = &As[arow * 36 + akc];
#pragma unroll
        for (int j = 0; j < 16; j++) ap[j] = f2tf(a[j]);
        unsigned* bpp = &Bs[bn * 36 + bk0];
#pragma unroll
        for (int j = 0; j < 8; j++) bpp[j] = f2tf(b[j]);
        __syncthreads();

#pragma unroll
        for (int k8 = 0; k8 < 4; k8++) {
            int k0 = k8 * 8;
            unsigned af[2][4];
#pragma unroll
            for (int mf = 0; mf < 2; mf++) {
                int rb = wm * 32 + mf * 16;
                af[mf][0] = As[(rb + g) * 36 + k0 + c];
                af[mf][1] = As[(rb + g + 8) * 36 + k0 + c];
                af[mf][2] = As[(rb + g) * 36 + k0 + c + 4];
                af[mf][3] = As[(rb + g + 8) * 36 + k0 + c + 4];
            }
#pragma unroll
            for (int nt = 0; nt < 4; nt++) {
                int nb = (wn * 32 + nt * 8 + g) * 36 + k0 + c;
                unsigned b0 = Bs[nb], b1 = Bs[nb + 4];
                mma_tf32(acc[0][nt][0], acc[0][nt][1], acc[0][nt][2], acc[0][nt][3],
                         af[0][0], af[0][1], af[0][2], af[0][3], b0, b1);
                mma_tf32(acc[1][nt][0], acc[1][nt][1], acc[1][nt][2], acc[1][nt][3],
                         af[1][0], af[1][1], af[1][2], af[1][3], b0, b1);
            }
        }
    }

#pragma unroll
    for (int mf = 0; mf < 2; mf++) {
        int r0 = wm * 32 + mf * 16 + g;
        int t0 = toks[r0], t1 = toks[r0 + 8];
#pragma unroll
        for (int nt = 0; nt < 4; nt++) {
            int col = d0 + wn * 32 + nt * 8 + 2 * c;
            if (t0 >= 0) {
                out[(size_t)t0 * DM + col]     += acc[mf][nt][0];
                out[(size_t)t0 * DM + col + 1] += acc[mf][nt][1];
            }
            if (t1 >= 0) {
                out[(size_t)t1 * DM + col]     += acc[mf][nt][2];
                out[(size_t)t1 * DM + col + 1] += acc[mf][nt][3];
            }
        }
    }
}

// ---------------- host orchestration ----------------
extern "C" void kernel_launch(void* const* d_in, const int* in_sizes, int n_in,
                              void* d_out, int out_size) {
    const float* hidden     = (const float*)d_in[0];
    const int*   positions  = (const int*)d_in[1];
    const float* velocity   = (const float*)d_in[2];
    const int*   token_ids  = (const int*)d_in[3];
    const float* mu_prev    = (const float*)d_in[4];
    const float* ln1_w      = (const float*)d_in[5];
    const float* ln2_w      = (const float*)d_in[6];
    const float* wq         = (const float*)d_in[7];
    const float* wk         = (const float*)d_in[8];
    const float* wv         = (const float*)d_in[9];
    const float* wo_w       = (const float*)d_in[10];
    const float* w_mu_q     = (const float*)d_in[11];
    const float* w_mu_k     = (const float*)d_in[12];
    const float* w_mu_v     = (const float*)d_in[13];
    const float* qnorm_w    = (const float*)d_in[14];
    const float* knorm_w    = (const float*)d_in[15];
    const float* dyn_mu     = (const float*)d_in[16];
    const float* dyn_proj   = (const float*)d_in[17];
    const float* ctrl_in_w  = (const float*)d_in[18];
    const float* ctrl_in_b  = (const float*)d_in[19];
    const float* ctrl_out_w = (const float*)d_in[20];
    const float* ctrl_out_b = (const float*)d_in[21];
    const float* mu_router  = (const float*)d_in[22];
    const float* w_gate     = (const float*)d_in[23];
    const float* w_up       = (const float*)d_in[24];
    const float* w_down     = (const float*)d_in[25];

    float* out    = (float*)d_out;
    float* out_h  = out;
    float* out_vn = out + (size_t)NTOK * DM;
    float* out_mu = out + 2 * (size_t)NTOK * DM;

    float *p_h1, *p_oh, *p_o, *p_ctrl, *p_co, *p_x2;
    cudaGetSymbolAddress((void**)&p_h1, g_h1);
    cudaGetSymbolAddress((void**)&p_oh, g_oh);
    cudaGetSymbolAddress((void**)&p_o, g_o);
    cudaGetSymbolAddress((void**)&p_ctrl, g_ctrl);
    cudaGetSymbolAddress((void**)&p_co, g_co);
    cudaGetSymbolAddress((void**)&p_x2, g_x2);

    // allow >48KB dynamic smem for the attention kernel (idempotent host call)
    cudaFuncSetAttribute(attn_tc_kernel, cudaFuncAttributeMaxDynamicSharedMemorySize, ATTN_SMEM);

    // 1. h = rmsnorm(hidden, ln1_w)
    rmsnorm_kernel<<<NTOK, 256>>>(hidden, ln1_w, p_h1);

    // 2. fused qkv, 3xTF32 tensor cores (fp32-class precision)
    qkv3_tc<<<dim3(24, NTOK / 128), 256>>>(p_h1, mu_prev, wq, w_mu_q, wk, w_mu_k, wv, w_mu_v);

    // 3. per-head rmsnorm + RoPE
    qknorm_rope_kernel<<<dim3(NTOK, NH + NKV), 64>>>(positions, qnorm_w, knorm_w);

    // 4. tensor-core flash attention
    attn_tc_kernel<<<dim3(NTOK / 128, NH), 256, ATTN_SMEM>>>();

    // 5. o = oh @ wo (3xTF32)
    gemm3_tc<<<dim3(DM / 64, NTOK / 128), 256>>>(p_oh, wo_w, nullptr, p_o, NH * DHD, DM, 0);

    // 6. mu_cur = dyn_mu + o @ dyn_mu_proj_w (3xTF32)
    gemm3_tc<<<dim3(DM / 64, NTOK / 128), 256>>>(p_o, dyn_proj, dyn_mu, out_mu, DM, DM, 1);

    // 7. ctrl = silu([o | velocity] @ ctrl_in_w + b)  (fp32 SIMT, small)
    gemm_kernel<<<dim3(CHN / 64, NTOK / 64), 256>>>(p_o, velocity, ctrl_in_w,
                                                    ctrl_in_w + (size_t)DM * CHN, ctrl_in_b,
                                                    p_ctrl, DM, CHN, 2);

    // 8. co = ctrl @ ctrl_out_w + ctrl_out_b (fp32 SIMT, small K)
    gemm_kernel<<<dim3((3 * DM) / 64, NTOK / 64), 256>>>(p_ctrl, nullptr, ctrl_out_w, nullptr,
                                                         ctrl_out_b, p_co, CHN, 3 * DM, 1);

    // 9. dynamics
    dynamics_kernel<<<(NTOK * DM) / 256, 256>>>(hidden, velocity, out_mu, out_h, out_vn);

    // 10. x = rmsnorm(hidden2, ln2_w)
    rmsnorm_kernel<<<NTOK, 256>>>(out_h, ln2_w, p_x2);

    // 11. routing
    zero_cnt_kernel<<<1, 32>>>();
    router_kernel<<<NTOK / 32, 256>>>(out_mu, token_ids, mu_router);

    // 12. MoE (1x tf32 tensor cores — diluted error path)
    moe_gateup_tc<<<dim3(FF / 64, NTOK / 128, NEXP), 256>>>(p_x2, w_gate, w_up);
    moe_down_tc<<<dim3(DM / 64, NTOK / 128, NEXP), 256>>>(w_down, out_h);
}

// round 12
// speedup vs baseline: 2.0680x; 1.1837x over previous
#include <cuda_runtime.h>
#include <math.h>

#define NTOK 2048
#define DM   1024
#define NH   16
#define NKV  4
#define DHD  64
#define NEXP 8
#define FF   2048
#define CHN  64
#define EPSV 1e-6f

// ---------------- scratch (device globals; no allocation allowed) ----------------
__device__ float g_h1[NTOK * DM];
__device__ float g_q[NTOK * NH * DHD];
__device__ float g_k[NTOK * NKV * DHD];
__device__ float g_v[NTOK * NKV * DHD];
__device__ float g_oh[NTOK * NH * DHD];
__device__ float g_o[NTOK * DM];
__device__ float g_ctrl[NTOK * CHN];
__device__ float g_co[NTOK * 3 * DM];
__device__ float g_x2[NTOK * DM];
__device__ float g_mid[NTOK * FF];
__device__ int   g_cnt[NEXP];
__device__ int   g_toklist[NEXP * NTOK];
__device__ float g_cosT[NTOK * 32];
__device__ float g_sinT[NTOK * 32];

// ---------------- tf32 helpers ----------------
__device__ __forceinline__ unsigned f2tf(float f) {
    unsigned u;
    asm("cvt.rna.tf32.f32 %0, %1;" : "=r"(u) : "f"(f));
    return u;
}
__device__ __forceinline__ void split_tf(float x, unsigned& hi, unsigned& lo) {
    hi = f2tf(x);
    float r = x - __uint_as_float(hi);
    lo = f2tf(r);
}
__device__ __forceinline__ void mma_tf32(float& c0, float& c1, float& c2, float& c3,
                                         unsigned a0, unsigned a1, unsigned a2, unsigned a3,
                                         unsigned b0, unsigned b1) {
    asm("mma.sync.aligned.m16n8k8.row.col.f32.tf32.tf32.f32 "
        "{%0,%1,%2,%3},{%4,%5,%6,%7},{%8,%9},{%0,%1,%2,%3};"
        : "+f"(c0), "+f"(c1), "+f"(c2), "+f"(c3)
        : "r"(a0), "r"(a1), "r"(a2), "r"(a3), "r"(b0), "r"(b1));
}

// ---------------- rmsnorm over D=1024 ----------------
__global__ void rmsnorm_kernel(const float* __restrict__ x, const float* __restrict__ w,
                               float* __restrict__ out) {
    int n = blockIdx.x;
    int t = threadIdx.x;
    const float4* xr = reinterpret_cast<const float4*>(x + (size_t)n * DM);
    float4 v = xr[t];
    __shared__ float red[256];
    red[t] = v.x * v.x + v.y * v.y + v.z * v.z + v.w * v.w;
    __syncthreads();
    for (int s = 128; s > 0; s >>= 1) {
        if (t < s) red[t] += red[t + s];
        __syncthreads();
    }
    float sc = rsqrtf(red[0] * (1.0f / DM) + EPSV);
    float4 wv = reinterpret_cast<const float4*>(w)[t];
    float4 o = make_float4(v.x * sc * wv.x, v.y * sc * wv.y, v.z * sc * wv.z, v.w * sc * wv.w);
    reinterpret_cast<float4*>(out + (size_t)n * DM)[t] = o;
}

// ---------------- fp32 SIMT GEMM (kept for small ctrl GEMMs) ----------------
__global__ __launch_bounds__(256) void gemm_kernel(
    const float* __restrict__ A1, const float* __restrict__ A2,
    const float* __restrict__ B1, const float* __restrict__ B2,
    const float* __restrict__ bias, float* __restrict__ C,
    int Kd, int Nc, int epi) {
    __shared__ __align__(16) float As[16 * 68];
    __shared__ __align__(16) float Bs[16 * 64];
    int m0 = blockIdx.y * 64, n0 = blockIdx.x * 64;
    int tid = threadIdx.x;
    int tx = tid & 15, ty = tid >> 4;
    float acc[4][4];
#pragma unroll
    for (int i = 0; i < 4; i++)
#pragma unroll
        for (int j = 0; j < 4; j++) acc[i][j] = 0.f;

    int nparts = (A2 != nullptr) ? 2 : 1;
    for (int part = 0; part < nparts; ++part) {
        const float* A = part ? A2 : A1;
        const float* B = part ? B2 : B1;
        for (int kk = 0; kk < Kd; kk += 16) {
            int idx = tid * 4;
            int arow = idx >> 4, ak = idx & 15;
            float4 av = *reinterpret_cast<const float4*>(A + (size_t)(m0 + arow) * Kd + kk + ak);
            As[(ak + 0) * 68 + arow] = av.x;
            As[(ak + 1) * 68 + arow] = av.y;
            As[(ak + 2) * 68 + arow] = av.z;
            As[(ak + 3) * 68 + arow] = av.w;
            int bk = idx >> 6, bn = idx & 63;
            *reinterpret_cast<float4*>(&Bs[bk * 64 + bn]) =
                *reinterpret_cast<const float4*>(B + (size_t)(kk + bk) * Nc + n0 + bn);
            __syncthreads();
#pragma unroll
            for (int k = 0; k < 16; k++) {
                float4 a = *reinterpret_cast<const float4*>(&As[k * 68 + ty * 4]);
                float4 b = *reinterpret_cast<const float4*>(&Bs[k * 64 + tx * 4]);
                float ar[4] = {a.x, a.y, a.z, a.w};
                float br[4] = {b.x, b.y, b.z, b.w};
#pragma unroll
                for (int i = 0; i < 4; i++)
#pragma unroll
                    for (int j = 0; j < 4; j++) acc[i][j] += ar[i] * br[j];
            }
            __syncthreads();
        }
    }
#pragma unroll
    for (int i = 0; i < 4; i++) {
        int row = m0 + ty * 4 + i;
#pragma unroll
        for (int j = 0; j < 4; j++) {
            int col = n0 + tx * 4 + j;
            float v = acc[i][j];
            if (epi >= 1) v += bias[col];
            if (epi == 2) v = v / (1.f + __expf(-v));
            C[(size_t)row * Nc + col] = v;
        }
    }
}

// ================= 3xTF32 tensor-core GEMM (fp32-class precision) =================
struct TcTile {
    unsigned Ah[128 * 20];
    unsigned Al[128 * 20];
    unsigned Bh[64 * 20];
    unsigned Bl[64 * 20];
};

__device__ __forceinline__ void tc3_chunk(TcTile* s, int wm, int wn, int g, int c,
                                          float acc[2][4][4]) {
#pragma unroll
    for (int k8 = 0; k8 < 2; k8++) {
        int k0 = k8 * 8;
        unsigned ah[2][4], al[2][4];
#pragma unroll
        for (int mf = 0; mf < 2; mf++) {
            int rb = wm * 32 + mf * 16;
            ah[mf][0] = s->Ah[(rb + g) * 20 + k0 + c];
            ah[mf][1] = s->Ah[(rb + g + 8) * 20 + k0 + c];
            ah[mf][2] = s->Ah[(rb + g) * 20 + k0 + c + 4];
            ah[mf][3] = s->Ah[(rb + g + 8) * 20 + k0 + c + 4];
            al[mf][0] = s->Al[(rb + g) * 20 + k0 + c];
            al[mf][1] = s->Al[(rb + g + 8) * 20 + k0 + c];
            al[mf][2] = s->Al[(rb + g) * 20 + k0 + c + 4];
            al[mf][3] = s->Al[(rb + g + 8) * 20 + k0 + c + 4];
        }
#pragma unroll
        for (int nt = 0; nt < 4; nt++) {
            int nb = (wn * 32 + nt * 8 + g) * 20 + k0 + c;
            unsigned bh0 = s->Bh[nb], bh1 = s->Bh[nb + 4];
            unsigned bl0 = s->Bl[nb], bl1 = s->Bl[nb + 4];
#pragma unroll
            for (int mf = 0; mf < 2; mf++) {
                mma_tf32(acc[mf][nt][0], acc[mf][nt][1], acc[mf][nt][2], acc[mf][nt][3],
                         ah[mf][0], ah[mf][1], ah[mf][2], ah[mf][3], bh0, bh1);
                mma_tf32(acc[mf][nt][0], acc[mf][nt][1], acc[mf][nt][2], acc[mf][nt][3],
                         ah[mf][0], ah[mf][1], ah[mf][2], ah[mf][3], bl0, bl1);
                mma_tf32(acc[mf][nt][0], acc[mf][nt][1], acc[mf][nt][2], acc[mf][nt][3],
                         al[mf][0], al[mf][1], al[mf][2], al[mf][3], bh0, bh1);
            }
        }
    }
}

__device__ __forceinline__ void tc3_load(TcTile* s, const float* __restrict__ A,
                                         const float* __restrict__ B, int Kd, int Nc,
                                         int m0, int n0, int kk, int tid) {
    int arow = tid >> 1, akc = (tid & 1) * 8;
    const float* ap = A + (size_t)(m0 + arow) * Kd + kk + akc;
    float a[8];
#pragma unroll
    for (int j = 0; j < 8; j += 4) {
        float4 t = *reinterpret_cast<const float4*>(ap + j);
        a[j] = t.x; a[j + 1] = t.y; a[j + 2] = t.z; a[j + 3] = t.w;
    }
    int bn = tid & 63, bk0 = (tid >> 6) * 4;
    const float* bp = B + (size_t)(kk + bk0) * Nc + n0 + bn;
    float b[4];
#pragma unroll
    for (int j = 0; j < 4; j++) b[j] = bp[(size_t)j * Nc];

    __syncthreads();
    unsigned* ah = &s->Ah[arow * 20 + akc];
    unsigned* al = &s->Al[arow * 20 + akc];
#pragma unroll
    for (int j = 0; j < 8; j++) split_tf(a[j], ah[j], al[j]);
    unsigned* bh = &s->Bh[bn * 20 + bk0];
    unsigned* bl = &s->Bl[bn * 20 + bk0];
#pragma unroll
    for (int j = 0; j < 4; j++) split_tf(b[j], bh[j], bl[j]);
    __syncthreads();
}

__global__ __launch_bounds__(256) void gemm3_tc(const float* __restrict__ A,
                                                const float* __restrict__ B,
                                                const float* __restrict__ bias,
                                                float* __restrict__ C, int Kd, int Nc, int epi) {
    __shared__ TcTile s;
    int m0 = blockIdx.y * 128, n0 = blockIdx.x * 64;
    int tid = threadIdx.x;
    int lane = tid & 31, w = tid >> 5;
    int wm = w & 3, wn = w >> 2;
    int g = lane >> 2, c = lane & 3;

    float acc[2][4][4];
#pragma unroll
    for (int mf = 0; mf < 2; mf++)
#pragma unroll
        for (int nt = 0; nt < 4; nt++)
#pragma unroll
            for (int r = 0; r < 4; r++) acc[mf][nt][r] = 0.f;

    for (int kk = 0; kk < Kd; kk += 16) {
        tc3_load(&s, A, B, Kd, Nc, m0, n0, kk, tid);
        tc3_chunk(&s, wm, wn, g, c, acc);
    }

#pragma unroll
    for (int mf = 0; mf < 2; mf++) {
        int r0 = m0 + wm * 32 + mf * 16 + g;
#pragma unroll
        for (int nt = 0; nt < 4; nt++) {
            int col = n0 + wn * 32 + nt * 8 + 2 * c;
#pragma unroll
            for (int half = 0; half < 2; half++) {
                int row = r0 + half * 8;
                float v0 = acc[mf][nt][half * 2 + 0];
                float v1 = acc[mf][nt][half * 2 + 1];
                if (epi >= 1) { v0 += bias[col]; v1 += bias[col + 1]; }
                C[(size_t)row * Nc + col]     = v0;
                C[(size_t)row * Nc + col + 1] = v1;
            }
        }
    }
}

// v projection 3xTF32 (dual-A, ntile_base offsets into the q/k/v tile space)
__global__ __launch_bounds__(256) void qkv3_tc(
    const float* __restrict__ A1, const float* __restrict__ A2,
    const float* __restrict__ wq, const float* __restrict__ wmq,
    const float* __restrict__ wk, const float* __restrict__ wmk,
    const float* __restrict__ wv, const float* __restrict__ wmv, int ntile_base) {
    __shared__ TcTile s;
    int ntile = blockIdx.x + ntile_base;
    int m0 = blockIdx.y * 128;
    const float *B1, *B2;
    float* C;
    int Nc, n0;
    if (ntile < 16)      { B1 = wq; B2 = wmq; C = g_q; Nc = NH * DHD;  n0 = ntile * 64; }
    else if (ntile < 20) { B1 = wk; B2 = wmk; C = g_k; Nc = NKV * DHD; n0 = (ntile - 16) * 64; }
    else                 { B1 = wv; B2 = wmv; C = g_v; Nc = NKV * DHD; n0 = (ntile - 20) * 64; }

    int tid = threadIdx.x;
    int lane = tid & 31, w = tid >> 5;
    int wm = w & 3, wn = w >> 2;
    int g = lane >> 2, c = lane & 3;

    float acc[2][4][4];
#pragma unroll
    for (int mf = 0; mf < 2; mf++)
#pragma unroll
        for (int nt = 0; nt < 4; nt++)
#pragma unroll
            for (int r = 0; r < 4; r++) acc[mf][nt][r] = 0.f;

    for (int part = 0; part < 2; ++part) {
        const float* A = part ? A2 : A1;
        const float* B = part ? B2 : B1;
        for (int kk = 0; kk < DM; kk += 16) {
            tc3_load(&s, A, B, DM, Nc, m0, n0, kk, tid);
            tc3_chunk(&s, wm, wn, g, c, acc);
        }
    }

#pragma unroll
    for (int mf = 0; mf < 2; mf++) {
        int r0 = m0 + wm * 32 + mf * 16 + g;
#pragma unroll
        for (int nt = 0; nt < 4; nt++) {
            int col = n0 + wn * 32 + nt * 8 + 2 * c;
#pragma unroll
            for (int half = 0; half < 2; half++) {
                int row = r0 + half * 8;
                C[(size_t)row * Nc + col]     = acc[mf][nt][half * 2 + 0];
                C[(size_t)row * Nc + col + 1] = acc[mf][nt][half * 2 + 1];
            }
        }
    }
}

// q/k projection, 1xTF32 (score-noise-dominated path; k-chunk 32)
__global__ __launch_bounds__(256) void qk1_tc(
    const float* __restrict__ A1, const float* __restrict__ A2,
    const float* __restrict__ wq, const float* __restrict__ wmq,
    const float* __restrict__ wk, const float* __restrict__ wmk) {
    __shared__ unsigned As[128 * 36];
    __shared__ unsigned Bs[64 * 36];
    int ntile = blockIdx.x;
    int m0 = blockIdx.y * 128;
    const float *B1, *B2;
    float* C;
    int Nc, n0;
    if (ntile < 16) { B1 = wq; B2 = wmq; C = g_q; Nc = NH * DHD;  n0 = ntile * 64; }
    else            { B1 = wk; B2 = wmk; C = g_k; Nc = NKV * DHD; n0 = (ntile - 16) * 64; }

    int tid = threadIdx.x;
    int lane = tid & 31, w = tid >> 5;
    int wm = w & 3, wn = w >> 2;
    int g = lane >> 2, c = lane & 3;
    int arow = tid >> 1, akc = (tid & 1) * 16;
    int bn = tid & 63, bk0 = (tid >> 6) * 8;

    float acc[2][4][4];
#pragma unroll
    for (int mf = 0; mf < 2; mf++)
#pragma unroll
        for (int nt = 0; nt < 4; nt++)
#pragma unroll
            for (int r = 0; r < 4; r++) acc[mf][nt][r] = 0.f;

    for (int part = 0; part < 2; ++part) {
        const float* A = part ? A2 : A1;
        const float* B = part ? B2 : B1;
        for (int kk = 0; kk < DM; kk += 32) {
            float a[16];
            const float* ap = A + (size_t)(m0 + arow) * DM + kk + akc;
#pragma unroll
            for (int j = 0; j < 16; j += 4) {
                float4 t = *reinterpret_cast<const float4*>(ap + j);
                a[j] = t.x; a[j + 1] = t.y; a[j + 2] = t.z; a[j + 3] = t.w;
            }
            float b[8];
            const float* bp = B + (size_t)(kk + bk0) * Nc + n0 + bn;
#pragma unroll
            for (int j = 0; j < 8; j++) b[j] = bp[(size_t)j * Nc];

            __syncthreads();
            unsigned* apd = &As[arow * 36 + akc];
#pragma unroll
            for (int j = 0; j < 16; j++) apd[j] = f2tf(a[j]);
            unsigned* bpd = &Bs[bn * 36 + bk0];
#pragma unroll
            for (int j = 0; j < 8; j++) bpd[j] = f2tf(b[j]);
            __syncthreads();

#pragma unroll
            for (int k8 = 0; k8 < 4; k8++) {
                int k0 = k8 * 8;
                unsigned af[2][4];
#pragma unroll
                for (int mf = 0; mf < 2; mf++) {
                    int rb = wm * 32 + mf * 16;
                    af[mf][0] = As[(rb + g) * 36 + k0 + c];
                    af[mf][1] = As[(rb + g + 8) * 36 + k0 + c];
                    af[mf][2] = As[(rb + g) * 36 + k0 + c + 4];
                    af[mf][3] = As[(rb + g + 8) * 36 + k0 + c + 4];
                }
#pragma unroll
                for (int nt = 0; nt < 4; nt++) {
                    int nb = (wn * 32 + nt * 8 + g) * 36 + k0 + c;
                    unsigned b0 = Bs[nb], b1 = Bs[nb + 4];
                    mma_tf32(acc[0][nt][0], acc[0][nt][1], acc[0][nt][2], acc[0][nt][3],
                             af[0][0], af[0][1], af[0][2], af[0][3], b0, b1);
                    mma_tf32(acc[1][nt][0], acc[1][nt][1], acc[1][nt][2], acc[1][nt][3],
                             af[1][0], af[1][1], af[1][2], af[1][3], b0, b1);
                }
            }
        }
    }

#pragma unroll
    for (int mf = 0; mf < 2; mf++) {
        int r0 = m0 + wm * 32 + mf * 16 + g;
#pragma unroll
        for (int nt = 0; nt < 4; nt++) {
            int col = n0 + wn * 32 + nt * 8 + 2 * c;
#pragma unroll
            for (int half = 0; half < 2; half++) {
                int row = r0 + half * 8;
                C[(size_t)row * Nc + col]     = acc[mf][nt][half * 2 + 0];
                C[(size_t)row * Nc + col + 1] = acc[mf][nt][half * 2 + 1];
            }
        }
    }
}

// ---------------- RoPE tables (one double exp per (pos, i); 65K threads total) --------
__global__ void rope_table_kernel(const int* __restrict__ positions) {
    int idx = blockIdx.x * 64 + threadIdx.x;  // NTOK*32
    int i = idx & 31;
    int n = idx >> 5;
    float pos = (float)positions[n];
    float inv = (float)exp(-((double)(2 * i) / 64.0) * log(10000.0));
    float ang = pos * inv;
    g_cosT[idx] = cosf(ang);
    g_sinT[idx] = sinf(ang);
}

// warp-per-head qk norm + rope (shfl reduction only; table-driven rope)
__global__ void qknorm_rope2_kernel(const float* __restrict__ qw, const float* __restrict__ kw) {
    int n = blockIdx.x;
    int wid = threadIdx.x >> 5;   // 0..19: q heads then k heads
    int lane = threadIdx.x & 31;
    float* ptr;
    const float* wt;
    if (wid < NH) { ptr = g_q + (size_t)n * (NH * DHD) + wid * DHD; wt = qw; }
    else          { ptr = g_k + (size_t)n * (NKV * DHD) + (wid - NH) * DHD; wt = kw; }
    float x1 = ptr[lane];
    float x2 = ptr[lane + 32];
    float ss = x1 * x1 + x2 * x2;
#pragma unroll
    for (int o = 16; o > 0; o >>= 1) ss += __shfl_xor_sync(0xffffffffu, ss, o);
    float sc = rsqrtf(ss * (1.0f / DHD) + EPSV);
    float xn1 = x1 * sc * wt[lane];
    float xn2 = x2 * sc * wt[lane + 32];
    float cc = g_cosT[n * 32 + lane];
    float s  = g_sinT[n * 32 + lane];
    ptr[lane]      = xn1 * cc - xn2 * s;
    ptr[lane + 32] = xn2 * cc + xn1 * s;
}

// ================= tf32 tensor-core flash attention =================
#define ATTN_SMEM ((128 * 68 + 64 * 68 + 64 * 68 + 128 * 68) * 4)

__global__ __launch_bounds__(256) void attn_tc_kernel() {
    extern __shared__ unsigned asm_u[];
    unsigned* Qs = asm_u;
    unsigned* Ks = Qs + 128 * 68;
    unsigned* Vt = Ks + 64 * 68;
    unsigned* Ps = Vt + 64 * 68;

    int h = blockIdx.y;
    int q0 = blockIdx.x * 128;
    int kvh = h >> 2;
    int tid = threadIdx.x;
    int lane = tid & 31, w = tid >> 5;
    int g = lane >> 2, c = lane & 3;
    int qbase = w * 16;

    {
        int row = tid >> 1;
        int d0 = (tid & 1) * 32;
        const float* qp = g_q + ((size_t)(q0 + row) * NH + h) * DHD + d0;
        unsigned* dst = Qs + row * 68 + d0;
#pragma unroll
        for (int j = 0; j < 32; j += 4) {
            float4 t = *reinterpret_cast<const float4*>(qp + j);
            dst[j]     = f2tf(t.x * 0.125f);
            dst[j + 1] = f2tf(t.y * 0.125f);
            dst[j + 2] = f2tf(t.z * 0.125f);
            dst[j + 3] = f2tf(t.w * 0.125f);
        }
    }

    float oacc[8][4];
#pragma unroll
    for (int nt = 0; nt < 8; nt++)
#pragma unroll
        for (int r = 0; r < 4; r++) oacc[nt][r] = 0.f;
    float mrun0 = -1e30f, mrun1 = -1e30f, lrun0 = 0.f, lrun1 = 0.f;

    const int krow = tid >> 2;
    const int kd0 = (tid & 3) * 16;

    for (int kt = 0; kt < NTOK; kt += 64) {
        {
            const float* kp = g_k + ((size_t)(kt + krow) * NKV + kvh) * DHD + kd0;
            unsigned* dst = Ks + krow * 68 + kd0;
#pragma unroll
            for (int j = 0; j < 16; j += 4) {
                float4 t = *reinterpret_cast<const float4*>(kp + j);
                dst[j] = f2tf(t.x); dst[j + 1] = f2tf(t.y);
                dst[j + 2] = f2tf(t.z); dst[j + 3] = f2tf(t.w);
            }
            const float* vp = g_v + ((size_t)(kt + krow) * NKV + kvh) * DHD + kd0;
#pragma unroll
            for (int j = 0; j < 16; j += 4) {
                float4 t = *reinterpret_cast<const float4*>(vp + j);
                Vt[(kd0 + j)     * 68 + krow] = f2tf(t.x);
                Vt[(kd0 + j + 1) * 68 + krow] = f2tf(t.y);
                Vt[(kd0 + j + 2) * 68 + krow] = f2tf(t.z);
                Vt[(kd0 + j + 3) * 68 + krow] = f2tf(t.w);
            }
        }
        __syncthreads();

        float sacc[8][4];
#pragma unroll
        for (int nt = 0; nt < 8; nt++)
#pragma unroll
            for (int r = 0; r < 4; r++) sacc[nt][r] = 0.f;
#pragma unroll
        for (int k8 = 0; k8 < 8; k8++) {
            int k0 = k8 * 8;
            unsigned a0 = Qs[(qbase + g) * 68 + k0 + c];
            unsigned a1 = Qs[(qbase + g + 8) * 68 + k0 + c];
            unsigned a2 = Qs[(qbase + g) * 68 + k0 + c + 4];
            unsigned a3 = Qs[(qbase + g + 8) * 68 + k0 + c + 4];
#pragma unroll
            for (int nt = 0; nt < 8; nt++) {
                int nb = (nt * 8 + g) * 68 + k0 + c;
                mma_tf32(sacc[nt][0], sacc[nt][1], sacc[nt][2], sacc[nt][3],
                         a0, a1, a2, a3, Ks[nb], Ks[nb + 4]);
            }
        }

        float mx0 = -1e30f, mx1 = -1e30f;
#pragma unroll
        for (int nt = 0; nt < 8; nt++) {
            mx0 = fmaxf(mx0, fmaxf(sacc[nt][0], sacc[nt][1]));
            mx1 = fmaxf(mx1, fmaxf(sacc[nt][2], sacc[nt][3]));
        }
        mx0 = fmaxf(mx0, __shfl_xor_sync(0xffffffffu, mx0, 1));
        mx0 = fmaxf(mx0, __shfl_xor_sync(0xffffffffu, mx0, 2));
        mx1 = fmaxf(mx1, __shfl_xor_sync(0xffffffffu, mx1, 1));
        mx1 = fmaxf(mx1, __shfl_xor_sync(0xffffffffu, mx1, 2));
        float mn0 = fmaxf(mrun0, mx0);
        float mn1 = fmaxf(mrun1, mx1);
        float corr0 = __expf(mrun0 - mn0);
        float corr1 = __expf(mrun1 - mn1);
#pragma unroll
        for (int nt = 0; nt < 8; nt++) {
            oacc[nt][0] *= corr0; oacc[nt][1] *= corr0;
            oacc[nt][2] *= corr1; oacc[nt][3] *= corr1;
        }
        float ps0 = 0.f, ps1 = 0.f;
#pragma unroll
        for (int nt = 0; nt < 8; nt++) {
            float p00 = __expf(sacc[nt][0] - mn0);
            float p01 = __expf(sacc[nt][1] - mn0);
            float p10 = __expf(sacc[nt][2] - mn1);
            float p11 = __expf(sacc[nt][3] - mn1);
            ps0 += p00 + p01;
            ps1 += p10 + p11;
            int colb = nt * 8 + 2 * c;
            uint2 v0; v0.x = f2tf(p00); v0.y = f2tf(p01);
            uint2 v1; v1.x = f2tf(p10); v1.y = f2tf(p11);
            *reinterpret_cast<uint2*>(&Ps[(qbase + g) * 68 + colb])     = v0;
            *reinterpret_cast<uint2*>(&Ps[(qbase + g + 8) * 68 + colb]) = v1;
        }
        ps0 += __shfl_xor_sync(0xffffffffu, ps0, 1);
        ps0 += __shfl_xor_sync(0xffffffffu, ps0, 2);
        ps1 += __shfl_xor_sync(0xffffffffu, ps1, 1);
        ps1 += __shfl_xor_sync(0xffffffffu, ps1, 2);
        lrun0 = lrun0 * corr0 + ps0;
        lrun1 = lrun1 * corr1 + ps1;
        mrun0 = mn0;
        mrun1 = mn1;
        __syncwarp();

#pragma unroll
        for (int k8 = 0; k8 < 8; k8++) {
            int k0 = k8 * 8;
            unsigned a0 = Ps[(qbase + g) * 68 + k0 + c];
            unsigned a1 = Ps[(qbase + g + 8) * 68 + k0 + c];
            unsigned a2 = Ps[(qbase + g) * 68 + k0 + c + 4];
            unsigned a3 = Ps[(qbase + g + 8) * 68 + k0 + c + 4];
#pragma unroll
            for (int nt = 0; nt < 8; nt++) {
                int nb = (nt * 8 + g) * 68 + k0 + c;
                mma_tf32(oacc[nt][0], oacc[nt][1], oacc[nt][2], oacc[nt][3],
                         a0, a1, a2, a3, Vt[nb], Vt[nb + 4]);
            }
        }
        __syncthreads();
    }

    float rl0 = 1.f / lrun0;
    float rl1 = 1.f / lrun1;
    float* o0 = g_oh + ((size_t)(q0 + qbase + g) * NH + h) * DHD;
    float* o1 = g_oh + ((size_t)(q0 + qbase + g + 8) * NH + h) * DHD;
#pragma unroll
    for (int nt = 0; nt < 8; nt++) {
        int colb = nt * 8 + 2 * c;
        *reinterpret_cast<float2*>(o0 + colb) = make_float2(oacc[nt][0] * rl0, oacc[nt][1] * rl0);
        *reinterpret_cast<float2*>(o1 + colb) = make_float2(oacc[nt][2] * rl1, oacc[nt][3] * rl1);
    }
}

// ---------------- control dynamics elementwise ----------------
__global__ void dynamics_kernel(const float* __restrict__ hidden, const float* __restrict__ velocity,
                                const float* __restrict__ mu, float* __restrict__ out_h2,
                                float* __restrict__ out_vn) {
    int idx = blockIdx.x * 256 + threadIdx.x;
    int n = idx >> 10;
    int d = idx & 1023;
    const float* co = g_co + (size_t)n * 3 * DM;
    float ar = co[d], br = co[DM + d], gr = co[2 * DM + d];
    float alpha = 1.f / (1.f + expf(-ar));
    float sp = fmaxf(br, 0.f) + log1pf(expf(-fabsf(br)));
    float beta = fminf(sp, 2.f);
    float gate = 1.f / (1.f + expf(-gr));
    float o = g_o[idx], mv = mu[idx], vel = velocity[idx];
    float vn = alpha * vel - beta * (o - mv);
    vn = fminf(fmaxf(vn, -10.f), 10.f);
    out_h2[idx] = hidden[idx] + o + 0.1f * gate * vn;
    out_vn[idx] = vn;
}

// ---------------- router ----------------
__global__ void zero_cnt_kernel() {
    if (threadIdx.x < NEXP) g_cnt[threadIdx.x] = 0;
}

__global__ void router_kernel(const float* __restrict__ mu, const int* __restrict__ token_ids,
                              const float* __restrict__ Wr) {
    int tid = threadIdx.x;
    int tl = tid >> 3, e = tid & 7;
    int n = blockIdx.x * 32 + tl;
    const float* mr = mu + (size_t)n * DM;
    float s = 0.f;
    for (int d = 0; d < DM; d++) s += mr[d] * Wr[d * NEXP + e];
    __shared__ float lg[32][8];
    lg[tl][e] = s;
    __syncthreads();
    if (e == 0) {
        int base = token_ids[n] % NEXP;
        float best = -1e30f;
        int bi = 0;
#pragma unroll
        for (int j = 0; j < 8; j++) {
            float c = lg[tl][j] + (j == base ? 10.0f : 0.0f);
            if (c > best) { best = c; bi = j; }
        }
        int slot = atomicAdd(&g_cnt[bi], 1);
        g_toklist[bi * NTOK + slot] = n;
    }
}

// ================= 1x tf32 tensor-core MoE =================
__global__ __launch_bounds__(256) void moe_gateup_tc(const float* __restrict__ X,
                                                     const float* __restrict__ Wg,
                                                     const float* __restrict__ Wu) {
    int e = blockIdx.z;
    int count = g_cnt[e];
    int m0 = blockIdx.y * 128;
    if (m0 >= count) return;
    int f0 = blockIdx.x * 64;

    __shared__ int toks[128];
    __shared__ unsigned As[128 * 36];
    __shared__ unsigned Bg[64 * 36];
    __shared__ unsigned Bu[64 * 36];

    int tid = threadIdx.x;
    int lane = tid & 31, w = tid >> 5;
    int wm = w & 3, wn = w >> 2;
    int g = lane >> 2, c = lane & 3;

    if (tid < 128) toks[tid] = (m0 + tid < count) ? g_toklist[e * NTOK + m0 + tid] : -1;
    __syncthreads();

    const float* WgE = Wg + (size_t)e * DM * FF;
    const float* WuE = Wu + (size_t)e * DM * FF;

    int arow = tid >> 1, akc = (tid & 1) * 16;
    int bn = tid & 63, bk0 = (tid >> 6) * 8;
    int tokA = toks[arow];
    const float* Aptr = (tokA >= 0) ? X + (size_t)tokA * DM + akc : X;

    float acg[2][4][4], acu[2][4][4];
#pragma unroll
    for (int mf = 0; mf < 2; mf++)
#pragma unroll
        for (int nt = 0; nt < 4; nt++)
#pragma unroll
            for (int r = 0; r < 4; r++) { acg[mf][nt][r] = 0.f; acu[mf][nt][r] = 0.f; }

    for (int kk = 0; kk < DM; kk += 32) {
        float a[16];
        if (tokA >= 0) {
#pragma unroll
            for (int j = 0; j < 16; j += 4) {
                float4 t = *reinterpret_cast<const float4*>(Aptr + kk + j);
                a[j] = t.x; a[j + 1] = t.y; a[j + 2] = t.z; a[j + 3] = t.w;
            }
        } else {
#pragma unroll
            for (int j = 0; j < 16; j++) a[j] = 0.f;
        }
        float bg[8], bu[8];
        const float* bgp = WgE + (size_t)(kk + bk0) * FF + f0 + bn;
        const float* bup = WuE + (size_t)(kk + bk0) * FF + f0 + bn;
#pragma unroll
        for (int j = 0; j < 8; j++) { bg[j] = bgp[(size_t)j * FF]; bu[j] = bup[(size_t)j * FF]; }

        __syncthreads();
        unsigned* ap = &As[arow * 36 + akc];
#pragma unroll
        for (int j = 0; j < 16; j++) ap[j] = f2tf(a[j]);
        unsigned* gp = &Bg[bn * 36 + bk0];
        unsigned* up = &Bu[bn * 36 + bk0];
#pragma unroll
        for (int j = 0; j < 8; j++) { gp[j] = f2tf(bg[j]); up[j] = f2tf(bu[j]); }
        __syncthreads();

#pragma unroll
        for (int k8 = 0; k8 < 4; k8++) {
            int k0 = k8 * 8;
            unsigned af[2][4];
#pragma unroll
            for (int mf = 0; mf < 2; mf++) {
                int rb = wm * 32 + mf * 16;
                af[mf][0] = As[(rb + g) * 36 + k0 + c];
                af[mf][1] = As[(rb + g + 8) * 36 + k0 + c];
                af[mf][2] = As[(rb + g) * 36 + k0 + c + 4];
                af[mf][3] = As[(rb + g + 8) * 36 + k0 + c + 4];
            }
#pragma unroll
            for (int nt = 0; nt < 4; nt++) {
                int nb = (wn * 32 + nt * 8 + g) * 36 + k0 + c;
                unsigned b0 = Bg[nb], b1 = Bg[nb + 4];
                mma_tf32(acg[0][nt][0], acg[0][nt][1], acg[0][nt][2], acg[0][nt][3],
                         af[0][0], af[0][1], af[0][2], af[0][3], b0, b1);
                mma_tf32(acg[1][nt][0], acg[1][nt][1], acg[1][nt][2], acg[1][nt][3],
                         af[1][0], af[1][1], af[1][2], af[1][3], b0, b1);
                unsigned u0 = Bu[nb], u1 = Bu[nb + 4];
                mma_tf32(acu[0][nt][0], acu[0][nt][1], acu[0][nt][2], acu[0][nt][3],
                         af[0][0], af[0][1], af[0][2], af[0][3], u0, u1);
                mma_tf32(acu[1][nt][0], acu[1][nt][1], acu[1][nt][2], acu[1][nt][3],
                         af[1][0], af[1][1], af[1][2], af[1][3], u0, u1);
            }
        }
    }

#pragma unroll
    for (int mf = 0; mf < 2; mf++) {
        int r0 = wm * 32 + mf * 16 + g;
        int t0 = toks[r0], t1 = toks[r0 + 8];
#pragma unroll
        for (int nt = 0; nt < 4; nt++) {
            int col = f0 + wn * 32 + nt * 8 + 2 * c;
            if (t0 >= 0) {
                float gv = acg[mf][nt][0], uv = acu[mf][nt][0];
                g_mid[(size_t)t0 * FF + col] = (gv / (1.f + __expf(-gv))) * uv;
                gv = acg[mf][nt][1]; uv = acu[mf][nt][1];
                g_mid[(size_t)t0 * FF + col + 1] = (gv / (1.f + __expf(-gv))) * uv;
            }
            if (t1 >= 0) {
                float gv = acg[mf][nt][2], uv = acu[mf][nt][2];
                g_mid[(size_t)t1 * FF + col] = (gv / (1.f + __expf(-gv))) * uv;
                gv = acg[mf][nt][3]; uv = acu[mf][nt][3];
                g_mid[(size_t)t1 * FF + col + 1] = (gv / (1.f + __expf(-gv))) * uv;
            }
        }
    }
}

__global__ __launch_bounds__(256) void moe_down_tc(const float* __restrict__ Wd,
                                                   float* __restrict__ out) {
    int e = blockIdx.z;
    int count = g_cnt[e];
    int m0 = blockIdx.y * 128;
    if (m0 >= count) return;
    int d0 = blockIdx.x * 64;

    __shared__ int toks[128];
    __shared__ unsigned As[128 * 36];
    __shared__ unsigned Bs[64 * 36];

    int tid = threadIdx.x;
    int lane = tid & 31, w = tid >> 5;
    int wm = w & 3, wn = w >> 2;
    int g = lane >> 2, c = lane & 3;

    if (tid < 128) toks[tid] = (m0 + tid < count) ? g_toklist[e * NTOK + m0 + tid] : -1;
    __syncthreads();

    const float* WdE = Wd + (size_t)e * FF * DM;
    int arow = tid >> 1, akc = (tid & 1) * 16;
    int bn = tid & 63, bk0 = (tid >> 6) * 8;
    int tokA = toks[arow];
    const float* Aptr = (tokA >= 0) ? g_mid + (size_t)tokA * FF + akc : g_mid;

    float acc[2][4][4];
#pragma unroll
    for (int mf = 0; mf < 2; mf++)
#pragma unroll
        for (int nt = 0; nt < 4; nt++)
#pragma unroll
            for (int r = 0; r < 4; r++) acc[mf][nt][r] = 0.f;

    for (int kk = 0; kk < FF; kk += 32) {
        float a[16];
        if (tokA >= 0) {
#pragma unroll
            for (int j = 0; j < 16; j += 4) {
                float4 t = *reinterpret_cast<const float4*>(Aptr + kk + j);
                a[j] = t.x; a[j + 1] = t.y; a[j + 2] = t.z; a[j + 3] = t.w;
            }
        } else {
#pragma unroll
            for (int j = 0; j < 16; j++) a[j] = 0.f;
        }
        float b[8];
        const float* bp = WdE + (size_t)(kk + bk0) * DM + d0 + bn;
#pragma unroll
        for (int j = 0; j < 8; j++) b[j] = bp[(size_t)j * DM];

        __syncthreads();
        unsigned* ap = &As[arow * 36 + akc];
#pragma unroll
        for (int j = 0; j < 16; j++) ap[j] = f2tf(a[j]);
        unsigned* bpp = &Bs[bn * 36 + bk0];
#pragma unroll
        for (int j = 0; j < 8; j++) bpp[j] = f2tf(b[j]);
        __syncthreads();

#pragma unroll
        for (int k8 = 0; k8 < 4; k8++) {
            int k0 = k8 * 8;
            unsigned af[2][4];
#pragma unroll
            for (int mf = 0; mf < 2; mf++) {
                int rb = wm * 32 + mf * 16;
                af[mf][0] = As[(rb + g) * 36 + k0 + c];
                af[mf][1] = As[(rb + g + 8) * 36 + k0 + c];
                af[mf][2] = As[(rb + g) * 36 + k0 + c + 4];
                af[mf][3] = As[(rb + g + 8) * 36 + k0 + c + 4];
            }
#pragma unroll
            for (int nt = 0; nt < 4; nt++) {
                int nb = (wn * 32 + nt * 8 + g) * 36 + k0 + c;
                unsigned b0 = Bs[nb], b1 = Bs[nb + 4];
                mma_tf32(acc[0][nt][0], acc[0][nt][1], acc[0][nt][2], acc[0][nt][3],
                         af[0][0], af[0][1], af[0][2], af[0][3], b0, b1);
                mma_tf32(acc[1][nt][0], acc[1][nt][1], acc[1][nt][2], acc[1][nt][3],
                         af[1][0], af[1][1], af[1][2], af[1][3], b0, b1);
            }
        }
    }

#pragma unroll
    for (int mf = 0; mf < 2; mf++) {
        int r0 = wm * 32 + mf * 16 + g;
        int t0 = toks[r0], t1 = toks[r0 + 8];
#pragma unroll
        for (int nt = 0; nt < 4; nt++) {
            int col = d0 + wn * 32 + nt * 8 + 2 * c;
            if (t0 >= 0) {
                out[(size_t)t0 * DM + col]     += acc[mf][nt][0];
                out[(size_t)t0 * DM + col + 1] += acc[mf][nt][1];
            }
            if (t1 >= 0) {
                out[(size_t)t1 * DM + col]     += acc[mf][nt][2];
                out[(size_t)t1 * DM + col + 1] += acc[mf][nt][3];
            }
        }
    }
}

// ---------------- host orchestration ----------------
extern "C" void kernel_launch(void* const* d_in, const int* in_sizes, int n_in,
                              void* d_out, int out_size) {
    const float* hidden     = (const float*)d_in[0];
    const int*   positions  = (const int*)d_in[1];
    const float* velocity   = (const float*)d_in[2];
    const int*   token_ids  = (const int*)d_in[3];
    const float* mu_prev    = (const float*)d_in[4];
    const float* ln1_w      = (const float*)d_in[5];
    const float* ln2_w      = (const float*)d_in[6];
    const float* wq         = (const float*)d_in[7];
    const float* wk         = (const float*)d_in[8];
    const float* wv         = (const float*)d_in[9];
    const float* wo_w       = (const float*)d_in[10];
    const float* w_mu_q     = (const float*)d_in[11];
    const float* w_mu_k     = (const float*)d_in[12];
    const float* w_mu_v     = (const float*)d_in[13];
    const float* qnorm_w    = (const float*)d_in[14];
    const float* knorm_w    = (const float*)d_in[15];
    const float* dyn_mu     = (const float*)d_in[16];
    const float* dyn_proj   = (const float*)d_in[17];
    const float* ctrl_in_w  = (const float*)d_in[18];
    const float* ctrl_in_b  = (const float*)d_in[19];
    const float* ctrl_out_w = (const float*)d_in[20];
    const float* ctrl_out_b = (const float*)d_in[21];
    const float* mu_router  = (const float*)d_in[22];
    const float* w_gate     = (const float*)d_in[23];
    const float* w_up       = (const float*)d_in[24];
    const float* w_down     = (const float*)d_in[25];

    float* out    = (float*)d_out;
    float* out_h  = out;
    float* out_vn = out + (size_t)NTOK * DM;
    float* out_mu = out + 2 * (size_t)NTOK * DM;

    float *p_h1, *p_oh, *p_o, *p_ctrl, *p_co, *p_x2;
    cudaGetSymbolAddress((void**)&p_h1, g_h1);
    cudaGetSymbolAddress((void**)&p_oh, g_oh);
    cudaGetSymbolAddress((void**)&p_o, g_o);
    cudaGetSymbolAddress((void**)&p_ctrl, g_ctrl);
    cudaGetSymbolAddress((void**)&p_co, g_co);
    cudaGetSymbolAddress((void**)&p_x2, g_x2);

    cudaFuncSetAttribute(attn_tc_kernel, cudaFuncAttributeMaxDynamicSharedMemorySize, ATTN_SMEM);

    // 0. rope tables (only needs positions)
    rope_table_kernel<<<(NTOK * 32) / 64, 64>>>(positions);

    // 1. h = rmsnorm(hidden, ln1_w)
    rmsnorm_kernel<<<NTOK, 256>>>(hidden, ln1_w, p_h1);

    // 2a. q/k projection (1xTF32 — score noise dominated by attention tf32 anyway)
    qk1_tc<<<dim3(20, NTOK / 128), 256>>>(p_h1, mu_prev, wq, w_mu_q, wk, w_mu_k);
    // 2b. v projection (3xTF32 — v noise passes to o at full strength)
    qkv3_tc<<<dim3(4, NTOK / 128), 256>>>(p_h1, mu_prev, wq, w_mu_q, wk, w_mu_k,
                                          wv, w_mu_v, 20);

    // 3. per-head rmsnorm + RoPE (warp-per-head, table-driven)
    qknorm_rope2_kernel<<<NTOK, (NH + NKV) * 32>>>(qnorm_w, knorm_w);

    // 4. tensor-core flash attention
    attn_tc_kernel<<<dim3(NTOK / 128, NH), 256, ATTN_SMEM>>>();

    // 5. o = oh @ wo (3xTF32)
    gemm3_tc<<<dim3(DM / 64, NTOK / 128), 256>>>(p_oh, wo_w, nullptr, p_o, NH * DHD, DM, 0);

    // 6. mu_cur = dyn_mu + o @ dyn_mu_proj_w (3xTF32)
    gemm3_tc<<<dim3(DM / 64, NTOK / 128), 256>>>(p_o, dyn_proj, dyn_mu, out_mu, DM, DM, 1);

    // 7. ctrl = silu([o | velocity] @ ctrl_in_w + b)
    gemm_kernel<<<dim3(CHN / 64, NTOK / 64), 256>>>(p_o, velocity, ctrl_in_w,
                                                    ctrl_in_w + (size_t)DM * CHN, ctrl_in_b,
                                                    p_ctrl, DM, CHN, 2);

    // 8. co = ctrl @ ctrl_out_w + ctrl_out_b
    gemm_kernel<<<dim3((3 * DM) / 64, NTOK / 64), 256>>>(p_ctrl, nullptr, ctrl_out_w, nullptr,
                                                         ctrl_out_b, p_co, CHN, 3 * DM, 1);

    // 9. dynamics
    dynamics_kernel<<<(NTOK * DM) / 256, 256>>>(hidden, velocity, out_mu, out_h, out_vn);

    // 10. x = rmsnorm(hidden2, ln2_w)
    rmsnorm_kernel<<<NTOK, 256>>>(out_h, ln2_w, p_x2);

    // 11. routing
    zero_cnt_kernel<<<1, 32>>>();
    router_kernel<<<NTOK / 32, 256>>>(out_mu, token_ids, mu_router);

    // 12. MoE (1x tf32 tensor cores — diluted error path)
    moe_gateup_tc<<<dim3(FF / 64, NTOK / 128, NEXP), 256>>>(p_x2, w_gate, w_up);
    moe_down_tc<<<dim3(DM / 64, NTOK / 128, NEXP), 256>>>(w_down, out_h);
}

// round 13
// speedup vs baseline: 2.7424x; 1.3261x over previous
#include <cuda_runtime.h>
#include <math.h>

#define NTOK 2048
#define DM   1024
#define NH   16
#define NKV  4
#define DHD  64
#define NEXP 8
#define FF   2048
#define CHN  64
#define EPSV 1e-6f
#define CSPLIT 8

// ---------------- scratch (device globals; no allocation allowed) ----------------
__device__ float g_h1[NTOK * DM];
__device__ float g_q[NTOK * NH * DHD];
__device__ float g_k[NTOK * NKV * DHD];
__device__ float g_v[NTOK * NKV * DHD];
__device__ float g_oh[NTOK * NH * DHD];
__device__ float g_o[NTOK * DM];
__device__ float g_ctrl[NTOK * CHN];
__device__ float g_ctrlp[CSPLIT * NTOK * CHN];
__device__ float g_co[NTOK * 3 * DM];
__device__ float g_x2[NTOK * DM];
__device__ float g_mid[NTOK * FF];
__device__ int   g_cnt[NEXP];
__device__ int   g_toklist[NEXP * NTOK];
__device__ float g_cosT[NTOK * 32];
__device__ float g_sinT[NTOK * 32];

// ---------------- tf32 helpers ----------------
__device__ __forceinline__ unsigned f2tf(float f) {
    unsigned u;
    asm("cvt.rna.tf32.f32 %0, %1;" : "=r"(u) : "f"(f));
    return u;
}
__device__ __forceinline__ void split_tf(float x, unsigned& hi, unsigned& lo) {
    hi = f2tf(x);
    float r = x - __uint_as_float(hi);
    lo = f2tf(r);
}
__device__ __forceinline__ void mma_tf32(float& c0, float& c1, float& c2, float& c3,
                                         unsigned a0, unsigned a1, unsigned a2, unsigned a3,
                                         unsigned b0, unsigned b1) {
    asm("mma.sync.aligned.m16n8k8.row.col.f32.tf32.tf32.f32 "
        "{%0,%1,%2,%3},{%4,%5,%6,%7},{%8,%9},{%0,%1,%2,%3};"
        : "+f"(c0), "+f"(c1), "+f"(c2), "+f"(c3)
        : "r"(a0), "r"(a1), "r"(a2), "r"(a3), "r"(b0), "r"(b1));
}

// ---------------- rmsnorm over D=1024 ----------------
__global__ void rmsnorm_kernel(const float* __restrict__ x, const float* __restrict__ w,
                               float* __restrict__ out) {
    int n = blockIdx.x;
    int t = threadIdx.x;
    const float4* xr = reinterpret_cast<const float4*>(x + (size_t)n * DM);
    float4 v = xr[t];
    __shared__ float red[256];
    red[t] = v.x * v.x + v.y * v.y + v.z * v.z + v.w * v.w;
    __syncthreads();
    for (int s = 128; s > 0; s >>= 1) {
        if (t < s) red[t] += red[t + s];
        __syncthreads();
    }
    float sc = rsqrtf(red[0] * (1.0f / DM) + EPSV);
    float4 wv = reinterpret_cast<const float4*>(w)[t];
    float4 o = make_float4(v.x * sc * wv.x, v.y * sc * wv.y, v.z * sc * wv.z, v.w * sc * wv.w);
    reinterpret_cast<float4*>(out + (size_t)n * DM)[t] = o;
}

// ================= shared 1xTF32 tile compute (128x64 tile, k-chunk 32) =================
__device__ __forceinline__ void tc1_mma_block(const unsigned* As, const unsigned* Bs,
                                              int wm, int wn, int g, int c,
                                              float acc[2][4][4]) {
#pragma unroll
    for (int k8 = 0; k8 < 4; k8++) {
        int k0 = k8 * 8;
        unsigned af[2][4];
#pragma unroll
        for (int mf = 0; mf < 2; mf++) {
            int rb = wm * 32 + mf * 16;
            af[mf][0] = As[(rb + g) * 36 + k0 + c];
            af[mf][1] = As[(rb + g + 8) * 36 + k0 + c];
            af[mf][2] = As[(rb + g) * 36 + k0 + c + 4];
            af[mf][3] = As[(rb + g + 8) * 36 + k0 + c + 4];
        }
#pragma unroll
        for (int nt = 0; nt < 4; nt++) {
            int nb = (wn * 32 + nt * 8 + g) * 36 + k0 + c;
            unsigned b0 = Bs[nb], b1 = Bs[nb + 4];
            mma_tf32(acc[0][nt][0], acc[0][nt][1], acc[0][nt][2], acc[0][nt][3],
                     af[0][0], af[0][1], af[0][2], af[0][3], b0, b1);
            mma_tf32(acc[1][nt][0], acc[1][nt][1], acc[1][nt][2], acc[1][nt][3],
                     af[1][0], af[1][1], af[1][2], af[1][3], b0, b1);
        }
    }
}

// ---------------- fused qkv, 1xTF32: ntile 0..15 q, 16..19 k, 20..23 v ----------------
__global__ __launch_bounds__(256) void qkv1_tc(
    const float* __restrict__ A1, const float* __restrict__ A2,
    const float* __restrict__ wq, const float* __restrict__ wmq,
    const float* __restrict__ wk, const float* __restrict__ wmk,
    const float* __restrict__ wv, const float* __restrict__ wmv) {
    __shared__ unsigned As[128 * 36];
    __shared__ unsigned Bs[64 * 36];
    int ntile = blockIdx.x;
    int m0 = blockIdx.y * 128;
    const float *B1, *B2;
    float* C;
    int Nc, n0;
    if (ntile < 16)      { B1 = wq; B2 = wmq; C = g_q; Nc = NH * DHD;  n0 = ntile * 64; }
    else if (ntile < 20) { B1 = wk; B2 = wmk; C = g_k; Nc = NKV * DHD; n0 = (ntile - 16) * 64; }
    else                 { B1 = wv; B2 = wmv; C = g_v; Nc = NKV * DHD; n0 = (ntile - 20) * 64; }

    int tid = threadIdx.x;
    int lane = tid & 31, w = tid >> 5;
    int wm = w & 3, wn = w >> 2;
    int g = lane >> 2, c = lane & 3;
    int arow = tid >> 1, akc = (tid & 1) * 16;
    int bn = tid & 63, bk0 = (tid >> 6) * 8;

    float acc[2][4][4];
#pragma unroll
    for (int mf = 0; mf < 2; mf++)
#pragma unroll
        for (int nt = 0; nt < 4; nt++)
#pragma unroll
            for (int r = 0; r < 4; r++) acc[mf][nt][r] = 0.f;

    for (int part = 0; part < 2; ++part) {
        const float* A = part ? A2 : A1;
        const float* B = part ? B2 : B1;
        for (int kk = 0; kk < DM; kk += 32) {
            float a[16];
            const float* ap = A + (size_t)(m0 + arow) * DM + kk + akc;
#pragma unroll
            for (int j = 0; j < 16; j += 4) {
                float4 t = *reinterpret_cast<const float4*>(ap + j);
                a[j] = t.x; a[j + 1] = t.y; a[j + 2] = t.z; a[j + 3] = t.w;
            }
            float b[8];
            const float* bp = B + (size_t)(kk + bk0) * Nc + n0 + bn;
#pragma unroll
            for (int j = 0; j < 8; j++) b[j] = bp[(size_t)j * Nc];

            __syncthreads();
            unsigned* apd = &As[arow * 36 + akc];
#pragma unroll
            for (int j = 0; j < 16; j++) apd[j] = f2tf(a[j]);
            unsigned* bpd = &Bs[bn * 36 + bk0];
#pragma unroll
            for (int j = 0; j < 8; j++) bpd[j] = f2tf(b[j]);
            __syncthreads();

            tc1_mma_block(As, Bs, wm, wn, g, c, acc);
        }
    }

#pragma unroll
    for (int mf = 0; mf < 2; mf++) {
        int r0 = m0 + wm * 32 + mf * 16 + g;
#pragma unroll
        for (int nt = 0; nt < 4; nt++) {
            int col = n0 + wn * 32 + nt * 8 + 2 * c;
#pragma unroll
            for (int half = 0; half < 2; half++) {
                int row = r0 + half * 8;
                C[(size_t)row * Nc + col]     = acc[mf][nt][half * 2 + 0];
                C[(size_t)row * Nc + col + 1] = acc[mf][nt][half * 2 + 1];
            }
        }
    }
}

// ---------------- dense 1xTF32 GEMM: C = A@B [+bias]; grid (Nc/64, rows/128) -------
__global__ __launch_bounds__(256) void gemm1_tc(const float* __restrict__ A,
                                                const float* __restrict__ B,
                                                const float* __restrict__ bias,
                                                float* __restrict__ C, int Kd, int Nc, int epi) {
    __shared__ unsigned As[128 * 36];
    __shared__ unsigned Bs[64 * 36];
    int m0 = blockIdx.y * 128, n0 = blockIdx.x * 64;
    int tid = threadIdx.x;
    int lane = tid & 31, w = tid >> 5;
    int wm = w & 3, wn = w >> 2;
    int g = lane >> 2, c = lane & 3;
    int arow = tid >> 1, akc = (tid & 1) * 16;
    int bn = tid & 63, bk0 = (tid >> 6) * 8;

    float acc[2][4][4];
#pragma unroll
    for (int mf = 0; mf < 2; mf++)
#pragma unroll
        for (int nt = 0; nt < 4; nt++)
#pragma unroll
            for (int r = 0; r < 4; r++) acc[mf][nt][r] = 0.f;

    for (int kk = 0; kk < Kd; kk += 32) {
        float a[16];
        const float* ap = A + (size_t)(m0 + arow) * Kd + kk + akc;
#pragma unroll
        for (int j = 0; j < 16; j += 4) {
            float4 t = *reinterpret_cast<const float4*>(ap + j);
            a[j] = t.x; a[j + 1] = t.y; a[j + 2] = t.z; a[j + 3] = t.w;
        }
        float b[8];
        const float* bp = B + (size_t)(kk + bk0) * Nc + n0 + bn;
#pragma unroll
        for (int j = 0; j < 8; j++) b[j] = bp[(size_t)j * Nc];

        __syncthreads();
        unsigned* apd = &As[arow * 36 + akc];
#pragma unroll
        for (int j = 0; j < 16; j++) apd[j] = f2tf(a[j]);
        unsigned* bpd = &Bs[bn * 36 + bk0];
#pragma unroll
        for (int j = 0; j < 8; j++) bpd[j] = f2tf(b[j]);
        __syncthreads();

        tc1_mma_block(As, Bs, wm, wn, g, c, acc);
    }

#pragma unroll
    for (int mf = 0; mf < 2; mf++) {
        int r0 = m0 + wm * 32 + mf * 16 + g;
#pragma unroll
        for (int nt = 0; nt < 4; nt++) {
            int col = n0 + wn * 32 + nt * 8 + 2 * c;
#pragma unroll
            for (int half = 0; half < 2; half++) {
                int row = r0 + half * 8;
                float v0 = acc[mf][nt][half * 2 + 0];
                float v1 = acc[mf][nt][half * 2 + 1];
                if (epi >= 1) { v0 += bias[col]; v1 += bias[col + 1]; }
                C[(size_t)row * Nc + col]     = v0;
                C[(size_t)row * Nc + col + 1] = v1;
            }
        }
    }
}

// ---------------- ctrl_in split-K 1xTF32: partial[sp] = [o|vel] @ Wc over k-slice ------
__global__ __launch_bounds__(256) void ctrlin_tc(const float* __restrict__ o,
                                                 const float* __restrict__ vel,
                                                 const float* __restrict__ Wc) {
    __shared__ unsigned As[128 * 36];
    __shared__ unsigned Bs[64 * 36];
    int sp = blockIdx.x;                  // 0..7, 256 k each
    int m0 = blockIdx.y * 128;
    int kbase = sp * 256;
    const float* A = (kbase < DM) ? o : vel;
    int acol = (kbase < DM) ? kbase : kbase - DM;
    const float* B = Wc + (size_t)kbase * CHN;

    int tid = threadIdx.x;
    int lane = tid & 31, w = tid >> 5;
    int wm = w & 3, wn = w >> 2;
    int g = lane >> 2, c = lane & 3;
    int arow = tid >> 1, akc = (tid & 1) * 16;
    int bn = tid & 63, bk0 = (tid >> 6) * 8;

    float acc[2][4][4];
#pragma unroll
    for (int mf = 0; mf < 2; mf++)
#pragma unroll
        for (int nt = 0; nt < 4; nt++)
#pragma unroll
            for (int r = 0; r < 4; r++) acc[mf][nt][r] = 0.f;

    for (int kk = 0; kk < 256; kk += 32) {
        float a[16];
        const float* ap = A + (size_t)(m0 + arow) * DM + acol + kk + akc;
#pragma unroll
        for (int j = 0; j < 16; j += 4) {
            float4 t = *reinterpret_cast<const float4*>(ap + j);
            a[j] = t.x; a[j + 1] = t.y; a[j + 2] = t.z; a[j + 3] = t.w;
        }
        float b[8];
        const float* bp = B + (size_t)(kk + bk0) * CHN + bn;
#pragma unroll
        for (int j = 0; j < 8; j++) b[j] = bp[(size_t)j * CHN];

        __syncthreads();
        unsigned* apd = &As[arow * 36 + akc];
#pragma unroll
        for (int j = 0; j < 16; j++) apd[j] = f2tf(a[j]);
        unsigned* bpd = &Bs[bn * 36 + bk0];
#pragma unroll
        for (int j = 0; j < 8; j++) bpd[j] = f2tf(b[j]);
        __syncthreads();

        tc1_mma_block(As, Bs, wm, wn, g, c, acc);
    }

    float* P = g_ctrlp + (size_t)sp * NTOK * CHN;
#pragma unroll
    for (int mf = 0; mf < 2; mf++) {
        int r0 = m0 + wm * 32 + mf * 16 + g;
#pragma unroll
        for (int nt = 0; nt < 4; nt++) {
            int col = wn * 32 + nt * 8 + 2 * c;
#pragma unroll
            for (int half = 0; half < 2; half++) {
                int row = r0 + half * 8;
                P[(size_t)row * CHN + col]     = acc[mf][nt][half * 2 + 0];
                P[(size_t)row * CHN + col + 1] = acc[mf][nt][half * 2 + 1];
            }
        }
    }
}

// combine ctrl partials: silu(sum + bias) -> g_ctrl  (fixed-order sum: deterministic)
__global__ void ctrl_combine_kernel(const float* __restrict__ bias) {
    int idx = blockIdx.x * 256 + threadIdx.x;  // NTOK*CHN
    int col = idx & (CHN - 1);
    float s = bias[col];
#pragma unroll
    for (int sp = 0; sp < CSPLIT; sp++) s += g_ctrlp[(size_t)sp * NTOK * CHN + idx];
    g_ctrl[idx] = s / (1.f + __expf(-s));
}

// ================= 3xTF32 tensor-core GEMM (kept for wo: o-path precision) =================
struct TcTile {
    unsigned Ah[128 * 20];
    unsigned Al[128 * 20];
    unsigned Bh[64 * 20];
    unsigned Bl[64 * 20];
};

__device__ __forceinline__ void tc3_chunk(TcTile* s, int wm, int wn, int g, int c,
                                          float acc[2][4][4]) {
#pragma unroll
    for (int k8 = 0; k8 < 2; k8++) {
        int k0 = k8 * 8;
        unsigned ah[2][4], al[2][4];
#pragma unroll
        for (int mf = 0; mf < 2; mf++) {
            int rb = wm * 32 + mf * 16;
            ah[mf][0] = s->Ah[(rb + g) * 20 + k0 + c];
            ah[mf][1] = s->Ah[(rb + g + 8) * 20 + k0 + c];
            ah[mf][2] = s->Ah[(rb + g) * 20 + k0 + c + 4];
            ah[mf][3] = s->Ah[(rb + g + 8) * 20 + k0 + c + 4];
            al[mf][0] = s->Al[(rb + g) * 20 + k0 + c];
            al[mf][1] = s->Al[(rb + g + 8) * 20 + k0 + c];
            al[mf][2] = s->Al[(rb + g) * 20 + k0 + c + 4];
            al[mf][3] = s->Al[(rb + g + 8) * 20 + k0 + c + 4];
        }
#pragma unroll
        for (int nt = 0; nt < 4; nt++) {
            int nb = (wn * 32 + nt * 8 + g) * 20 + k0 + c;
            unsigned bh0 = s->Bh[nb], bh1 = s->Bh[nb + 4];
            unsigned bl0 = s->Bl[nb], bl1 = s->Bl[nb + 4];
#pragma unroll
            for (int mf = 0; mf < 2; mf++) {
                mma_tf32(acc[mf][nt][0], acc[mf][nt][1], acc[mf][nt][2], acc[mf][nt][3],
                         ah[mf][0], ah[mf][1], ah[mf][2], ah[mf][3], bh0, bh1);
                mma_tf32(acc[mf][nt][0], acc[mf][nt][1], acc[mf][nt][2], acc[mf][nt][3],
                         ah[mf][0], ah[mf][1], ah[mf][2], ah[mf][3], bl0, bl1);
                mma_tf32(acc[mf][nt][0], acc[mf][nt][1], acc[mf][nt][2], acc[mf][nt][3],
                         al[mf][0], al[mf][1], al[mf][2], al[mf][3], bh0, bh1);
            }
        }
    }
}

__device__ __forceinline__ void tc3_load(TcTile* s, const float* __restrict__ A,
                                         const float* __restrict__ B, int Kd, int Nc,
                                         int m0, int n0, int kk, int tid) {
    int arow = tid >> 1, akc = (tid & 1) * 8;
    const float* ap = A + (size_t)(m0 + arow) * Kd + kk + akc;
    float a[8];
#pragma unroll
    for (int j = 0; j < 8; j += 4) {
        float4 t = *reinterpret_cast<const float4*>(ap + j);
        a[j] = t.x; a[j + 1] = t.y; a[j + 2] = t.z; a[j + 3] = t.w;
    }
    int bn = tid & 63, bk0 = (tid >> 6) * 4;
    const float* bp = B + (size_t)(kk + bk0) * Nc + n0 + bn;
    float b[4];
#pragma unroll
    for (int j = 0; j < 4; j++) b[j] = bp[(size_t)j * Nc];

    __syncthreads();
    unsigned* ah = &s->Ah[arow * 20 + akc];
    unsigned* al = &s->Al[arow * 20 + akc];
#pragma unroll
    for (int j = 0; j < 8; j++) split_tf(a[j], ah[j], al[j]);
    unsigned* bh = &s->Bh[bn * 20 + bk0];
    unsigned* bl = &s->Bl[bn * 20 + bk0];
#pragma unroll
    for (int j = 0; j < 4; j++) split_tf(b[j], bh[j], bl[j]);
    __syncthreads();
}

__global__ __launch_bounds__(256) void gemm3_tc(const float* __restrict__ A,
                                                const float* __restrict__ B,
                                                const float* __restrict__ bias,
                                                float* __restrict__ C, int Kd, int Nc, int epi) {
    __shared__ TcTile s;
    int m0 = blockIdx.y * 128, n0 = blockIdx.x * 64;
    int tid = threadIdx.x;
    int lane = tid & 31, w = tid >> 5;
    int wm = w & 3, wn = w >> 2;
    int g = lane >> 2, c = lane & 3;

    float acc[2][4][4];
#pragma unroll
    for (int mf = 0; mf < 2; mf++)
#pragma unroll
        for (int nt = 0; nt < 4; nt++)
#pragma unroll
            for (int r = 0; r < 4; r++) acc[mf][nt][r] = 0.f;

    for (int kk = 0; kk < Kd; kk += 16) {
        tc3_load(&s, A, B, Kd, Nc, m0, n0, kk, tid);
        tc3_chunk(&s, wm, wn, g, c, acc);
    }

#pragma unroll
    for (int mf = 0; mf < 2; mf++) {
        int r0 = m0 + wm * 32 + mf * 16 + g;
#pragma unroll
        for (int nt = 0; nt < 4; nt++) {
            int col = n0 + wn * 32 + nt * 8 + 2 * c;
#pragma unroll
            for (int half = 0; half < 2; half++) {
                int row = r0 + half * 8;
                float v0 = acc[mf][nt][half * 2 + 0];
                float v1 = acc[mf][nt][half * 2 + 1];
                if (epi >= 1) { v0 += bias[col]; v1 += bias[col + 1]; }
                C[(size_t)row * Nc + col]     = v0;
                C[(size_t)row * Nc + col + 1] = v1;
            }
        }
    }
}

// ---------------- RoPE tables ----------------
__global__ void rope_table_kernel(const int* __restrict__ positions) {
    int idx = blockIdx.x * 64 + threadIdx.x;  // NTOK*32
    int i = idx & 31;
    int n = idx >> 5;
    float pos = (float)positions[n];
    float inv = (float)exp(-((double)(2 * i) / 64.0) * log(10000.0));
    float ang = pos * inv;
    g_cosT[idx] = cosf(ang);
    g_sinT[idx] = sinf(ang);
}

// warp-per-head qk norm + rope
__global__ void qknorm_rope2_kernel(const float* __restrict__ qw, const float* __restrict__ kw) {
    int n = blockIdx.x;
    int wid = threadIdx.x >> 5;
    int lane = threadIdx.x & 31;
    float* ptr;
    const float* wt;
    if (wid < NH) { ptr = g_q + (size_t)n * (NH * DHD) + wid * DHD; wt = qw; }
    else          { ptr = g_k + (size_t)n * (NKV * DHD) + (wid - NH) * DHD; wt = kw; }
    float x1 = ptr[lane];
    float x2 = ptr[lane + 32];
    float ss = x1 * x1 + x2 * x2;
#pragma unroll
    for (int o = 16; o > 0; o >>= 1) ss += __shfl_xor_sync(0xffffffffu, ss, o);
    float sc = rsqrtf(ss * (1.0f / DHD) + EPSV);
    float xn1 = x1 * sc * wt[lane];
    float xn2 = x2 * sc * wt[lane + 32];
    float cc = g_cosT[n * 32 + lane];
    float s  = g_sinT[n * 32 + lane];
    ptr[lane]      = xn1 * cc - xn2 * s;
    ptr[lane + 32] = xn2 * cc + xn1 * s;
}

// ================= tf32 tensor-core flash attention =================
#define ATTN_SMEM ((128 * 68 + 64 * 68 + 64 * 68 + 128 * 68) * 4)

__global__ __launch_bounds__(256) void attn_tc_kernel() {
    extern __shared__ unsigned asm_u[];
    unsigned* Qs = asm_u;
    unsigned* Ks = Qs + 128 * 68;
    unsigned* Vt = Ks + 64 * 68;
    unsigned* Ps = Vt + 64 * 68;

    int h = blockIdx.y;
    int q0 = blockIdx.x * 128;
    int kvh = h >> 2;
    int tid = threadIdx.x;
    int lane = tid & 31, w = tid >> 5;
    int g = lane >> 2, c = lane & 3;
    int qbase = w * 16;

    {
        int row = tid >> 1;
        int d0 = (tid & 1) * 32;
        const float* qp = g_q + ((size_t)(q0 + row) * NH + h) * DHD + d0;
        unsigned* dst = Qs + row * 68 + d0;
#pragma unroll
        for (int j = 0; j < 32; j += 4) {
            float4 t = *reinterpret_cast<const float4*>(qp + j);
            dst[j]     = f2tf(t.x * 0.125f);
            dst[j + 1] = f2tf(t.y * 0.125f);
            dst[j + 2] = f2tf(t.z * 0.125f);
            dst[j + 3] = f2tf(t.w * 0.125f);
        }
    }

    float oacc[8][4];
#pragma unroll
    for (int nt = 0; nt < 8; nt++)
#pragma unroll
        for (int r = 0; r < 4; r++) oacc[nt][r] = 0.f;
    float mrun0 = -1e30f, mrun1 = -1e30f, lrun0 = 0.f, lrun1 = 0.f;

    const int krow = tid >> 2;
    const int kd0 = (tid & 3) * 16;

    for (int kt = 0; kt < NTOK; kt += 64) {
        {
            const float* kp = g_k + ((size_t)(kt + krow) * NKV + kvh) * DHD + kd0;
            unsigned* dst = Ks + krow * 68 + kd0;
#pragma unroll
            for (int j = 0; j < 16; j += 4) {
                float4 t = *reinterpret_cast<const float4*>(kp + j);
                dst[j] = f2tf(t.x); dst[j + 1] = f2tf(t.y);
                dst[j + 2] = f2tf(t.z); dst[j + 3] = f2tf(t.w);
            }
            const float* vp = g_v + ((size_t)(kt + krow) * NKV + kvh) * DHD + kd0;
#pragma unroll
            for (int j = 0; j < 16; j += 4) {
                float4 t = *reinterpret_cast<const float4*>(vp + j);
                Vt[(kd0 + j)     * 68 + krow] = f2tf(t.x);
                Vt[(kd0 + j + 1) * 68 + krow] = f2tf(t.y);
                Vt[(kd0 + j + 2) * 68 + krow] = f2tf(t.z);
                Vt[(kd0 + j + 3) * 68 + krow] = f2tf(t.w);
            }
        }
        __syncthreads();

        float sacc[8][4];
#pragma unroll
        for (int nt = 0; nt < 8; nt++)
#pragma unroll
            for (int r = 0; r < 4; r++) sacc[nt][r] = 0.f;
#pragma unroll
        for (int k8 = 0; k8 < 8; k8++) {
            int k0 = k8 * 8;
            unsigned a0 = Qs[(qbase + g) * 68 + k0 + c];
            unsigned a1 = Qs[(qbase + g + 8) * 68 + k0 + c];
            unsigned a2 = Qs[(qbase + g) * 68 + k0 + c + 4];
            unsigned a3 = Qs[(qbase + g + 8) * 68 + k0 + c + 4];
#pragma unroll
            for (int nt = 0; nt < 8; nt++) {
                int nb = (nt * 8 + g) * 68 + k0 + c;
                mma_tf32(sacc[nt][0], sacc[nt][1], sacc[nt][2], sacc[nt][3],
                         a0, a1, a2, a3, Ks[nb], Ks[nb + 4]);
            }
        }

        float mx0 = -1e30f, mx1 = -1e30f;
#pragma unroll
        for (int nt = 0; nt < 8; nt++) {
            mx0 = fmaxf(mx0, fmaxf(sacc[nt][0], sacc[nt][1]));
            mx1 = fmaxf(mx1, fmaxf(sacc[nt][2], sacc[nt][3]));
        }
        mx0 = fmaxf(mx0, __shfl_xor_sync(0xffffffffu, mx0, 1));
        mx0 = fmaxf(mx0, __shfl_xor_sync(0xffffffffu, mx0, 2));
        mx1 = fmaxf(mx1, __shfl_xor_sync(0xffffffffu, mx1, 1));
        mx1 = fmaxf(mx1, __shfl_xor_sync(0xffffffffu, mx1, 2));
        float mn0 = fmaxf(mrun0, mx0);
        float mn1 = fmaxf(mrun1, mx1);
        float corr0 = __expf(mrun0 - mn0);
        float corr1 = __expf(mrun1 - mn1);
#pragma unroll
        for (int nt = 0; nt < 8; nt++) {
            oacc[nt][0] *= corr0; oacc[nt][1] *= corr0;
            oacc[nt][2] *= corr1; oacc[nt][3] *= corr1;
        }
        float ps0 = 0.f, ps1 = 0.f;
#pragma unroll
        for (int nt = 0; nt < 8; nt++) {
            float p00 = __expf(sacc[nt][0] - mn0);
            float p01 = __expf(sacc[nt][1] - mn0);
            float p10 = __expf(sacc[nt][2] - mn1);
            float p11 = __expf(sacc[nt][3] - mn1);
            ps0 += p00 + p01;
            ps1 += p10 + p11;
            int colb = nt * 8 + 2 * c;
            uint2 v0; v0.x = f2tf(p00); v0.y = f2tf(p01);
            uint2 v1; v1.x = f2tf(p10); v1.y = f2tf(p11);
            *reinterpret_cast<uint2*>(&Ps[(qbase + g) * 68 + colb])     = v0;
            *reinterpret_cast<uint2*>(&Ps[(qbase + g + 8) * 68 + colb]) = v1;
        }
        ps0 += __shfl_xor_sync(0xffffffffu, ps0, 1);
        ps0 += __shfl_xor_sync(0xffffffffu, ps0, 2);
        ps1 += __shfl_xor_sync(0xffffffffu, ps1, 1);
        ps1 += __shfl_xor_sync(0xffffffffu, ps1, 2);
        lrun0 = lrun0 * corr0 + ps0;
        lrun1 = lrun1 * corr1 + ps1;
        mrun0 = mn0;
        mrun1 = mn1;
        __syncwarp();

#pragma unroll
        for (int k8 = 0; k8 < 8; k8++) {
            int k0 = k8 * 8;
            unsigned a0 = Ps[(qbase + g) * 68 + k0 + c];
            unsigned a1 = Ps[(qbase + g + 8) * 68 + k0 + c];
            unsigned a2 = Ps[(qbase + g) * 68 + k0 + c + 4];
            unsigned a3 = Ps[(qbase + g + 8) * 68 + k0 + c + 4];
#pragma unroll
            for (int nt = 0; nt < 8; nt++) {
                int nb = (nt * 8 + g) * 68 + k0 + c;
                mma_tf32(oacc[nt][0], oacc[nt][1], oacc[nt][2], oacc[nt][3],
                         a0, a1, a2, a3, Vt[nb], Vt[nb + 4]);
            }
        }
        __syncthreads();
    }

    float rl0 = 1.f / lrun0;
    float rl1 = 1.f / lrun1;
    float* o0 = g_oh + ((size_t)(q0 + qbase + g) * NH + h) * DHD;
    float* o1 = g_oh + ((size_t)(q0 + qbase + g + 8) * NH + h) * DHD;
#pragma unroll
    for (int nt = 0; nt < 8; nt++) {
        int colb = nt * 8 + 2 * c;
        *reinterpret_cast<float2*>(o0 + colb) = make_float2(oacc[nt][0] * rl0, oacc[nt][1] * rl0);
        *reinterpret_cast<float2*>(o1 + colb) = make_float2(oacc[nt][2] * rl1, oacc[nt][3] * rl1);
    }
}

// ---------------- control dynamics elementwise ----------------
__global__ void dynamics_kernel(const float* __restrict__ hidden, const float* __restrict__ velocity,
                                const float* __restrict__ mu, float* __restrict__ out_h2,
                                float* __restrict__ out_vn) {
    int idx = blockIdx.x * 256 + threadIdx.x;
    int n = idx >> 10;
    int d = idx & 1023;
    const float* co = g_co + (size_t)n * 3 * DM;
    float ar = co[d], br = co[DM + d], gr = co[2 * DM + d];
    float alpha = 1.f / (1.f + expf(-ar));
    float sp = fmaxf(br, 0.f) + log1pf(expf(-fabsf(br)));
    float beta = fminf(sp, 2.f);
    float gate = 1.f / (1.f + expf(-gr));
    float o = g_o[idx], mv = mu[idx], vel = velocity[idx];
    float vn = alpha * vel - beta * (o - mv);
    vn = fminf(fmaxf(vn, -10.f), 10.f);
    out_h2[idx] = hidden[idx] + o + 0.1f * gate * vn;
    out_vn[idx] = vn;
}

// ---------------- router ----------------
__global__ void zero_cnt_kernel() {
    if (threadIdx.x < NEXP) g_cnt[threadIdx.x] = 0;
}

__global__ void router_kernel(const float* __restrict__ mu, const int* __restrict__ token_ids,
                              const float* __restrict__ Wr) {
    int tid = threadIdx.x;
    int tl = tid >> 3, e = tid & 7;
    int n = blockIdx.x * 32 + tl;
    const float* mr = mu + (size_t)n * DM;
    float s = 0.f;
    for (int d = 0; d < DM; d++) s += mr[d] * Wr[d * NEXP + e];
    __shared__ float lg[32][8];
    lg[tl][e] = s;
    __syncthreads();
    if (e == 0) {
        int base = token_ids[n] % NEXP;
        float best = -1e30f;
        int bi = 0;
#pragma unroll
        for (int j = 0; j < 8; j++) {
            float c = lg[tl][j] + (j == base ? 10.0f : 0.0f);
            if (c > best) { best = c; bi = j; }
        }
        int slot = atomicAdd(&g_cnt[bi], 1);
        g_toklist[bi * NTOK + slot] = n;
    }
}

// ================= 1x tf32 tensor-core MoE =================
__global__ __launch_bounds__(256) void moe_gateup_tc(const float* __restrict__ X,
                                                     const float* __restrict__ Wg,
                                                     const float* __restrict__ Wu) {
    int e = blockIdx.z;
    int count = g_cnt[e];
    int m0 = blockIdx.y * 128;
    if (m0 >= count) return;
    int f0 = blockIdx.x * 64;

    __shared__ int toks[128];
    __shared__ unsigned As[128 * 36];
    __shared__ unsigned Bg[64 * 36];
    __shared__ unsigned Bu[64 * 36];

    int tid = threadIdx.x;
    int lane = tid & 31, w = tid >> 5;
    int wm = w & 3, wn = w >> 2;
    int g = lane >> 2, c = lane & 3;

    if (tid < 128) toks[tid] = (m0 + tid < count) ? g_toklist[e * NTOK + m0 + tid] : -1;
    __syncthreads();

    const float* WgE = Wg + (size_t)e * DM * FF;
    const float* WuE = Wu + (size_t)e * DM * FF;

    int arow = tid >> 1, akc = (tid & 1) * 16;
    int bn = tid & 63, bk0 = (tid >> 6) * 8;
    int tokA = toks[arow];
    const float* Aptr = (tokA >= 0) ? X + (size_t)tokA * DM + akc : X;

    float acg[2][4][4], acu[2][4][4];
#pragma unroll
    for (int mf = 0; mf < 2; mf++)
#pragma unroll
        for (int nt = 0; nt < 4; nt++)
#pragma unroll
            for (int r = 0; r < 4; r++) { acg[mf][nt][r] = 0.f; acu[mf][nt][r] = 0.f; }

    for (int kk = 0; kk < DM; kk += 32) {
        float a[16];
        if (tokA >= 0) {
#pragma unroll
            for (int j = 0; j < 16; j += 4) {
                float4 t = *reinterpret_cast<const float4*>(Aptr + kk + j);
                a[j] = t.x; a[j + 1] = t.y; a[j + 2] = t.z; a[j + 3] = t.w;
            }
        } else {
#pragma unroll
            for (int j = 0; j < 16; j++) a[j] = 0.f;
        }
        float bg[8], bu[8];
        const float* bgp = WgE + (size_t)(kk + bk0) * FF + f0 + bn;
        const float* bup = WuE + (size_t)(kk + bk0) * FF + f0 + bn;
#pragma unroll
        for (int j = 0; j < 8; j++) { bg[j] = bgp[(size_t)j * FF]; bu[j] = bup[(size_t)j * FF]; }

        __syncthreads();
        unsigned* ap = &As[arow * 36 + akc];
#pragma unroll
        for (int j = 0; j < 16; j++) ap[j] = f2tf(a[j]);
        unsigned* gp = &Bg[bn * 36 + bk0];
        unsigned* up = &Bu[bn * 36 + bk0];
#pragma unroll
        for (int j = 0; j < 8; j++) { gp[j] = f2tf(bg[j]); up[j] = f2tf(bu[j]); }
        __syncthreads();

#pragma unroll
        for (int k8 = 0; k8 < 4; k8++) {
            int k0 = k8 * 8;
            unsigned af[2][4];
#pragma unroll
            for (int mf = 0; mf < 2; mf++) {
                int rb = wm * 32 + mf * 16;
                af[mf][0] = As[(rb + g) * 36 + k0 + c];
                af[mf][1] = As[(rb + g + 8) * 36 + k0 + c];
                af[mf][2] = As[(rb + g) * 36 + k0 + c + 4];
                af[mf][3] = As[(rb + g + 8) * 36 + k0 + c + 4];
            }
#pragma unroll
            for (int nt = 0; nt < 4; nt++) {
                int nb = (wn * 32 + nt * 8 + g) * 36 + k0 + c;
                unsigned b0 = Bg[nb], b1 = Bg[nb + 4];
                mma_tf32(acg[0][nt][0], acg[0][nt][1], acg[0][nt][2], acg[0][nt][3],
                         af[0][0], af[0][1], af[0][2], af[0][3], b0, b1);
                mma_tf32(acg[1][nt][0], acg[1][nt][1], acg[1][nt][2], acg[1][nt][3],
                         af[1][0], af[1][1], af[1][2], af[1][3], b0, b1);
                unsigned u0 = Bu[nb], u1 = Bu[nb + 4];
                mma_tf32(acu[0][nt][0], acu[0][nt][1], acu[0][nt][2], acu[0][nt][3],
                         af[0][0], af[0][1], af[0][2], af[0][3], u0, u1);
                mma_tf32(acu[1][nt][0], acu[1][nt][1], acu[1][nt][2], acu[1][nt][3],
                         af[1][0], af[1][1], af[1][2], af[1][3], u0, u1);
            }
        }
    }

#pragma unroll
    for (int mf = 0; mf < 2; mf++) {
        int r0 = wm * 32 + mf * 16 + g;
        int t0 = toks[r0], t1 = toks[r0 + 8];
#pragma unroll
        for (int nt = 0; nt < 4; nt++) {
            int col = f0 + wn * 32 + nt * 8 + 2 * c;
            if (t0 >= 0) {
                float gv = acg[mf][nt][0], uv = acu[mf][nt][0];
                g_mid[(size_t)t0 * FF + col] = (gv / (1.f + __expf(-gv))) * uv;
                gv = acg[mf][nt][1]; uv = acu[mf][nt][1];
                g_mid[(size_t)t0 * FF + col + 1] = (gv / (1.f + __expf(-gv))) * uv;
            }
            if (t1 >= 0) {
                float gv = acg[mf][nt][2], uv = acu[mf][nt][2];
                g_mid[(size_t)t1 * FF + col] = (gv / (1.f + __expf(-gv))) * uv;
                gv = acg[mf][nt][3]; uv = acu[mf][nt][3];
                g_mid[(size_t)t1 * FF + col + 1] = (gv / (1.f + __expf(-gv))) * uv;
            }
        }
    }
}

__global__ __launch_bounds__(256) void moe_down_tc(const float* __restrict__ Wd,
                                                   float* __restrict__ out) {
    int e = blockIdx.z;
    int count = g_cnt[e];
    int m0 = blockIdx.y * 128;
    if (m0 >= count) return;
    int d0 = blockIdx.x * 64;

    __shared__ int toks[128];
    __shared__ unsigned As[128 * 36];
    __shared__ unsigned Bs[64 * 36];

    int tid = threadIdx.x;
    int lane = tid & 31, w = tid >> 5;
    int wm = w & 3, wn = w >> 2;
    int g = lane >> 2, c = lane & 3;

    if (tid < 128) toks[tid] = (m0 + tid < count) ? g_toklist[e * NTOK + m0 + tid] : -1;
    __syncthreads();

    const float* WdE = Wd + (size_t)e * FF * DM;
    int arow = tid >> 1, akc = (tid & 1) * 16;
    int bn = tid & 63, bk0 = (tid >> 6) * 8;
    int tokA = toks[arow];
    const float* Aptr = (tokA >= 0) ? g_mid + (size_t)tokA * FF + akc : g_mid;

    float acc[2][4][4];
#pragma unroll
    for (int mf = 0; mf < 2; mf++)
#pragma unroll
        for (int nt = 0; nt < 4; nt++)
#pragma unroll
            for (int r = 0; r < 4; r++) acc[mf][nt][r] = 0.f;

    for (int kk = 0; kk < FF; kk += 32) {
        float a[16];
        if (tokA >= 0) {
#pragma unroll
            for (int j = 0; j < 16; j += 4) {
                float4 t = *reinterpret_cast<const float4*>(Aptr + kk + j);
                a[j] = t.x; a[j + 1] = t.y; a[j + 2] = t.z; a[j + 3] = t.w;
            }
        } else {
#pragma unroll
            for (int j = 0; j < 16; j++) a[j] = 0.f;
        }
        float b[8];
        const float* bp = WdE + (size_t)(kk + bk0) * DM + d0 + bn;
#pragma unroll
        for (int j = 0; j < 8; j++) b[j] = bp[(size_t)j * DM];

        __syncthreads();
        unsigned* ap = &As[arow * 36 + akc];
#pragma unroll
        for (int j = 0; j < 16; j++) ap[j] = f2tf(a[j]);
        unsigned* bpp = &Bs[bn * 36 + bk0];
#pragma unroll
        for (int j = 0; j < 8; j++) bpp[j] = f2tf(b[j]);
        __syncthreads();

#pragma unroll
        for (int k8 = 0; k8 < 4; k8++) {
            int k0 = k8 * 8;
            unsigned af[2][4];
#pragma unroll
            for (int mf = 0; mf < 2; mf++) {
                int rb = wm * 32 + mf * 16;
                af[mf][0] = As[(rb + g) * 36 + k0 + c];
                af[mf][1] = As[(rb + g + 8) * 36 + k0 + c];
                af[mf][2] = As[(rb + g) * 36 + k0 + c + 4];
                af[mf][3] = As[(rb + g + 8) * 36 + k0 + c + 4];
            }
#pragma unroll
            for (int nt = 0; nt < 4; nt++) {
                int nb = (wn * 32 + nt * 8 + g) * 36 + k0 + c;
                unsigned b0 = Bs[nb], b1 = Bs[nb + 4];
                mma_tf32(acc[0][nt][0], acc[0][nt][1], acc[0][nt][2], acc[0][nt][3],
                         af[0][0], af[0][1], af[0][2], af[0][3], b0, b1);
                mma_tf32(acc[1][nt][0], acc[1][nt][1], acc[1][nt][2], acc[1][nt][3],
                         af[1][0], af[1][1], af[1][2], af[1][3], b0, b1);
            }
        }
    }

#pragma unroll
    for (int mf = 0; mf < 2; mf++) {
        int r0 = wm * 32 + mf * 16 + g;
        int t0 = toks[r0], t1 = toks[r0 + 8];
#pragma unroll
        for (int nt = 0; nt < 4; nt++) {
            int col = d0 + wn * 32 + nt * 8 + 2 * c;
            if (t0 >= 0) {
                out[(size_t)t0 * DM + col]     += acc[mf][nt][0];
                out[(size_t)t0 * DM + col + 1] += acc[mf][nt][1];
            }
            if (t1 >= 0) {
                out[(size_t)t1 * DM + col]     += acc[mf][nt][2];
                out[(size_t)t1 * DM + col + 1] += acc[mf][nt][3];
            }
        }
    }
}

// ---------------- host orchestration ----------------
extern "C" void kernel_launch(void* const* d_in, const int* in_sizes, int n_in,
                              void* d_out, int out_size) {
    const float* hidden     = (const float*)d_in[0];
    const int*   positions  = (const int*)d_in[1];
    const float* velocity   = (const float*)d_in[2];
    const int*   token_ids  = (const int*)d_in[3];
    const float* mu_prev    = (const float*)d_in[4];
    const float* ln1_w      = (const float*)d_in[5];
    const float* ln2_w      = (const float*)d_in[6];
    const float* wq         = (const float*)d_in[7];
    const float* wk         = (const float*)d_in[8];
    const float* wv         = (const float*)d_in[9];
    const float* wo_w       = (const float*)d_in[10];
    const float* w_mu_q     = (const float*)d_in[11];
    const float* w_mu_k     = (const float*)d_in[12];
    const float* w_mu_v     = (const float*)d_in[13];
    const float* qnorm_w    = (const float*)d_in[14];
    const float* knorm_w    = (const float*)d_in[15];
    const float* dyn_mu     = (const float*)d_in[16];
    const float* dyn_proj   = (const float*)d_in[17];
    const float* ctrl_in_w  = (const float*)d_in[18];
    const float* ctrl_in_b  = (const float*)d_in[19];
    const float* ctrl_out_w = (const float*)d_in[20];
    const float* ctrl_out_b = (const float*)d_in[21];
    const float* mu_router  = (const float*)d_in[22];
    const float* w_gate     = (const float*)d_in[23];
    const float* w_up       = (const float*)d_in[24];
    const float* w_down     = (const float*)d_in[25];

    float* out    = (float*)d_out;
    float* out_h  = out;
    float* out_vn = out + (size_t)NTOK * DM;
    float* out_mu = out + 2 * (size_t)NTOK * DM;

    float *p_h1, *p_oh, *p_o, *p_ctrl, *p_co, *p_x2;
    cudaGetSymbolAddress((void**)&p_h1, g_h1);
    cudaGetSymbolAddress((void**)&p_oh, g_oh);
    cudaGetSymbolAddress((void**)&p_o, g_o);
    cudaGetSymbolAddress((void**)&p_ctrl, g_ctrl);
    cudaGetSymbolAddress((void**)&p_co, g_co);
    cudaGetSymbolAddress((void**)&p_x2, g_x2);

    cudaFuncSetAttribute(attn_tc_kernel, cudaFuncAttributeMaxDynamicSharedMemorySize, ATTN_SMEM);

    // 0. rope tables
    rope_table_kernel<<<(NTOK * 32) / 64, 64>>>(positions);

    // 1. h = rmsnorm(hidden, ln1_w)
    rmsnorm_kernel<<<NTOK, 256>>>(hidden, ln1_w, p_h1);

    // 2. fully fused qkv, 1xTF32 (384 blocks)
    qkv1_tc<<<dim3(24, NTOK / 128), 256>>>(p_h1, mu_prev, wq, w_mu_q, wk, w_mu_k, wv, w_mu_v);

    // 3. per-head rmsnorm + RoPE
    qknorm_rope2_kernel<<<NTOK, (NH + NKV) * 32>>>(qnorm_w, knorm_w);

    // 4. tensor-core flash attention
    attn_tc_kernel<<<dim3(NTOK / 128, NH), 256, ATTN_SMEM>>>();

    // 5. o = oh @ wo (3xTF32: o-path precision protected)
    gemm3_tc<<<dim3(DM / 64, NTOK / 128), 256>>>(p_oh, wo_w, nullptr, p_o, NH * DHD, DM, 0);

    // 6. mu_cur = dyn_mu + o @ dyn_mu_proj_w (1xTF32 — mu_cur is tiny in global norm)
    gemm1_tc<<<dim3(DM / 64, NTOK / 128), 256>>>(p_o, dyn_proj, dyn_mu, out_mu, DM, DM, 1);

    // 7. ctrl = silu([o|velocity] @ ctrl_in_w + b): split-K tc + deterministic combine
    ctrlin_tc<<<dim3(CSPLIT, NTOK / 128), 256>>>(p_o, velocity, ctrl_in_w);
    ctrl_combine_kernel<<<(NTOK * CHN) / 256, 256>>>(ctrl_in_b);

    // 8. co = ctrl @ ctrl_out_w + ctrl_out_b (1xTF32, K=64)
    gemm1_tc<<<dim3((3 * DM) / 64, NTOK / 128), 256>>>(p_ctrl, ctrl_out_w, ctrl_out_b,
                                                       p_co, CHN, 3 * DM, 1);

    // 9. dynamics
    dynamics_kernel<<<(NTOK * DM) / 256, 256>>>(hidden, velocity, out_mu, out_h, out_vn);

    // 10. x = rmsnorm(hidden2, ln2_w)
    rmsnorm_kernel<<<NTOK, 256>>>(out_h, ln2_w, p_x2);

    // 11. routing
    zero_cnt_kernel<<<1, 32>>>();
    router_kernel<<<NTOK / 32, 256>>>(out_mu, token_ids, mu_router);

    // 12. MoE (1x tf32 tensor cores)
    moe_gateup_tc<<<dim3(FF / 64, NTOK / 128, NEXP), 256>>>(p_x2, w_gate, w_up);
    moe_down_tc<<<dim3(DM / 64, NTOK / 128, NEXP), 256>>>(w_down, out_h);
}

// round 14
// speedup vs baseline: 2.8242x; 1.0298x over previous
#include <cuda_runtime.h>
#include <math.h>

#define NTOK 2048
#define DM   1024
#define NH   16
#define NKV  4
#define DHD  64
#define NEXP 8
#define FF   2048
#define CHN  64
#define EPSV 1e-6f
#define CSPLIT 8

// ---------------- scratch (device globals; no allocation allowed) ----------------
__device__ float g_h1[NTOK * DM];
__device__ float g_q[NTOK * NH * DHD];
__device__ float g_k[NTOK * NKV * DHD];
__device__ float g_v[NTOK * NKV * DHD];
__device__ float g_oh[NTOK * NH * DHD];
__device__ float g_o[NTOK * DM];
__device__ float g_ctrl[NTOK * CHN];
__device__ float g_ctrlp[CSPLIT * NTOK * CHN];
__device__ float g_co[NTOK * 3 * DM];
__device__ float g_x2[NTOK * DM];
__device__ float g_mid[NTOK * FF];
__device__ int   g_cnt[NEXP];
__device__ int   g_toklist[NEXP * NTOK];
__device__ float g_cosT[NTOK * 32];
__device__ float g_sinT[NTOK * 32];

// ---------------- tf32 helpers ----------------
__device__ __forceinline__ unsigned f2tf(float f) {
    unsigned u;
    asm("cvt.rna.tf32.f32 %0, %1;" : "=r"(u) : "f"(f));
    return u;
}
__device__ __forceinline__ void split_tf(float x, unsigned& hi, unsigned& lo) {
    hi = f2tf(x);
    float r = x - __uint_as_float(hi);
    lo = f2tf(r);
}
__device__ __forceinline__ void mma_tf32(float& c0, float& c1, float& c2, float& c3,
                                         unsigned a0, unsigned a1, unsigned a2, unsigned a3,
                                         unsigned b0, unsigned b1) {
    asm("mma.sync.aligned.m16n8k8.row.col.f32.tf32.tf32.f32 "
        "{%0,%1,%2,%3},{%4,%5,%6,%7},{%8,%9},{%0,%1,%2,%3};"
        : "+f"(c0), "+f"(c1), "+f"(c2), "+f"(c3)
        : "r"(a0), "r"(a1), "r"(a2), "r"(a3), "r"(b0), "r"(b1));
}

// ---------------- rmsnorm over D=1024 ----------------
__global__ void rmsnorm_kernel(const float* __restrict__ x, const float* __restrict__ w,
                               float* __restrict__ out) {
    int n = blockIdx.x;
    int t = threadIdx.x;
    const float4* xr = reinterpret_cast<const float4*>(x + (size_t)n * DM);
    float4 v = xr[t];
    __shared__ float red[256];
    red[t] = v.x * v.x + v.y * v.y + v.z * v.z + v.w * v.w;
    __syncthreads();
    for (int s = 128; s > 0; s >>= 1) {
        if (t < s) red[t] += red[t + s];
        __syncthreads();
    }
    float sc = rsqrtf(red[0] * (1.0f / DM) + EPSV);
    float4 wv = reinterpret_cast<const float4*>(w)[t];
    float4 o = make_float4(v.x * sc * wv.x, v.y * sc * wv.y, v.z * sc * wv.z, v.w * sc * wv.w);
    reinterpret_cast<float4*>(out + (size_t)n * DM)[t] = o;
}

// ================= shared 1xTF32 tile compute (128x64 tile, k-chunk 32) =================
__device__ __forceinline__ void tc1_mma_block(const unsigned* As, const unsigned* Bs,
                                              int wm, int wn, int g, int c,
                                              float acc[2][4][4]) {
#pragma unroll
    for (int k8 = 0; k8 < 4; k8++) {
        int k0 = k8 * 8;
        unsigned af[2][4];
#pragma unroll
        for (int mf = 0; mf < 2; mf++) {
            int rb = wm * 32 + mf * 16;
            af[mf][0] = As[(rb + g) * 36 + k0 + c];
            af[mf][1] = As[(rb + g + 8) * 36 + k0 + c];
            af[mf][2] = As[(rb + g) * 36 + k0 + c + 4];
            af[mf][3] = As[(rb + g + 8) * 36 + k0 + c + 4];
        }
#pragma unroll
        for (int nt = 0; nt < 4; nt++) {
            int nb = (wn * 32 + nt * 8 + g) * 36 + k0 + c;
            unsigned b0 = Bs[nb], b1 = Bs[nb + 4];
            mma_tf32(acc[0][nt][0], acc[0][nt][1], acc[0][nt][2], acc[0][nt][3],
                     af[0][0], af[0][1], af[0][2], af[0][3], b0, b1);
            mma_tf32(acc[1][nt][0], acc[1][nt][1], acc[1][nt][2], acc[1][nt][3],
                     af[1][0], af[1][1], af[1][2], af[1][3], b0, b1);
        }
    }
}

// ---------------- fused qkv, 1xTF32, SW-PIPELINED: ntile 0..15 q, 16..19 k, 20..23 v ----
__global__ __launch_bounds__(256) void qkv1_tc(
    const float* __restrict__ A1, const float* __restrict__ A2,
    const float* __restrict__ wq, const float* __restrict__ wmq,
    const float* __restrict__ wk, const float* __restrict__ wmk,
    const float* __restrict__ wv, const float* __restrict__ wmv) {
    __shared__ unsigned As[128 * 36];
    __shared__ unsigned Bs[64 * 36];
    int ntile = blockIdx.x;
    int m0 = blockIdx.y * 128;
    const float *B1, *B2;
    float* C;
    int Nc, n0;
    if (ntile < 16)      { B1 = wq; B2 = wmq; C = g_q; Nc = NH * DHD;  n0 = ntile * 64; }
    else if (ntile < 20) { B1 = wk; B2 = wmk; C = g_k; Nc = NKV * DHD; n0 = (ntile - 16) * 64; }
    else                 { B1 = wv; B2 = wmv; C = g_v; Nc = NKV * DHD; n0 = (ntile - 20) * 64; }

    int tid = threadIdx.x;
    int lane = tid & 31, w = tid >> 5;
    int wm = w & 3, wn = w >> 2;
    int g = lane >> 2, c = lane & 3;
    int arow = tid >> 1, akc = (tid & 1) * 16;
    int bn = tid & 63, bk0 = (tid >> 6) * 8;

    float acc[2][4][4];
#pragma unroll
    for (int mf = 0; mf < 2; mf++)
#pragma unroll
        for (int nt = 0; nt < 4; nt++)
#pragma unroll
            for (int r = 0; r < 4; r++) acc[mf][nt][r] = 0.f;

    float a[16], b[8];
    // prologue load (kt = 0, part 0)
    {
        const float* ap = A1 + (size_t)(m0 + arow) * DM + akc;
#pragma unroll
        for (int j = 0; j < 16; j += 4) {
            float4 t = *reinterpret_cast<const float4*>(ap + j);
            a[j] = t.x; a[j + 1] = t.y; a[j + 2] = t.z; a[j + 3] = t.w;
        }
        const float* bp = B1 + (size_t)bk0 * Nc + n0 + bn;
#pragma unroll
        for (int j = 0; j < 8; j++) b[j] = bp[(size_t)j * Nc];
    }

    const int total = 2 * DM;
    for (int kt = 0; kt < total; kt += 32) {
        __syncthreads();
        unsigned* apd = &As[arow * 36 + akc];
#pragma unroll
        for (int j = 0; j < 16; j++) apd[j] = f2tf(a[j]);
        unsigned* bpd = &Bs[bn * 36 + bk0];
#pragma unroll
        for (int j = 0; j < 8; j++) bpd[j] = f2tf(b[j]);
        __syncthreads();

        int nx = kt + 32;
        if (nx < total) {
            const float* A = (nx < DM) ? A1 : A2;
            const float* B = (nx < DM) ? B1 : B2;
            int kk = (nx < DM) ? nx : nx - DM;
            const float* ap = A + (size_t)(m0 + arow) * DM + kk + akc;
#pragma unroll
            for (int j = 0; j < 16; j += 4) {
                float4 t = *reinterpret_cast<const float4*>(ap + j);
                a[j] = t.x; a[j + 1] = t.y; a[j + 2] = t.z; a[j + 3] = t.w;
            }
            const float* bp = B + (size_t)(kk + bk0) * Nc + n0 + bn;
#pragma unroll
            for (int j = 0; j < 8; j++) b[j] = bp[(size_t)j * Nc];
        }

        tc1_mma_block(As, Bs, wm, wn, g, c, acc);
    }

#pragma unroll
    for (int mf = 0; mf < 2; mf++) {
        int r0 = m0 + wm * 32 + mf * 16 + g;
#pragma unroll
        for (int nt = 0; nt < 4; nt++) {
            int col = n0 + wn * 32 + nt * 8 + 2 * c;
#pragma unroll
            for (int half = 0; half < 2; half++) {
                int row = r0 + half * 8;
                C[(size_t)row * Nc + col]     = acc[mf][nt][half * 2 + 0];
                C[(size_t)row * Nc + col + 1] = acc[mf][nt][half * 2 + 1];
            }
        }
    }
}

// ---------------- dense 1xTF32 GEMM, SW-PIPELINED: C = A@B [+bias] ----------------
__global__ __launch_bounds__(256) void gemm1_tc(const float* __restrict__ A,
                                                const float* __restrict__ B,
                                                const float* __restrict__ bias,
                                                float* __restrict__ C, int Kd, int Nc, int epi) {
    __shared__ unsigned As[128 * 36];
    __shared__ unsigned Bs[64 * 36];
    int m0 = blockIdx.y * 128, n0 = blockIdx.x * 64;
    int tid = threadIdx.x;
    int lane = tid & 31, w = tid >> 5;
    int wm = w & 3, wn = w >> 2;
    int g = lane >> 2, c = lane & 3;
    int arow = tid >> 1, akc = (tid & 1) * 16;
    int bn = tid & 63, bk0 = (tid >> 6) * 8;

    float acc[2][4][4];
#pragma unroll
    for (int mf = 0; mf < 2; mf++)
#pragma unroll
        for (int nt = 0; nt < 4; nt++)
#pragma unroll
            for (int r = 0; r < 4; r++) acc[mf][nt][r] = 0.f;

    float a[16], b[8];
    {
        const float* ap = A + (size_t)(m0 + arow) * Kd + akc;
#pragma unroll
        for (int j = 0; j < 16; j += 4) {
            float4 t = *reinterpret_cast<const float4*>(ap + j);
            a[j] = t.x; a[j + 1] = t.y; a[j + 2] = t.z; a[j + 3] = t.w;
        }
        const float* bp = B + (size_t)bk0 * Nc + n0 + bn;
#pragma unroll
        for (int j = 0; j < 8; j++) b[j] = bp[(size_t)j * Nc];
    }

    for (int kk = 0; kk < Kd; kk += 32) {
        __syncthreads();
        unsigned* apd = &As[arow * 36 + akc];
#pragma unroll
        for (int j = 0; j < 16; j++) apd[j] = f2tf(a[j]);
        unsigned* bpd = &Bs[bn * 36 + bk0];
#pragma unroll
        for (int j = 0; j < 8; j++) bpd[j] = f2tf(b[j]);
        __syncthreads();

        int nx = kk + 32;
        if (nx < Kd) {
            const float* ap = A + (size_t)(m0 + arow) * Kd + nx + akc;
#pragma unroll
            for (int j = 0; j < 16; j += 4) {
                float4 t = *reinterpret_cast<const float4*>(ap + j);
                a[j] = t.x; a[j + 1] = t.y; a[j + 2] = t.z; a[j + 3] = t.w;
            }
            const float* bp = B + (size_t)(nx + bk0) * Nc + n0 + bn;
#pragma unroll
            for (int j = 0; j < 8; j++) b[j] = bp[(size_t)j * Nc];
        }

        tc1_mma_block(As, Bs, wm, wn, g, c, acc);
    }

#pragma unroll
    for (int mf = 0; mf < 2; mf++) {
        int r0 = m0 + wm * 32 + mf * 16 + g;
#pragma unroll
        for (int nt = 0; nt < 4; nt++) {
            int col = n0 + wn * 32 + nt * 8 + 2 * c;
#pragma unroll
            for (int half = 0; half < 2; half++) {
                int row = r0 + half * 8;
                float v0 = acc[mf][nt][half * 2 + 0];
                float v1 = acc[mf][nt][half * 2 + 1];
                if (epi >= 1) { v0 += bias[col]; v1 += bias[col + 1]; }
                C[(size_t)row * Nc + col]     = v0;
                C[(size_t)row * Nc + col + 1] = v1;
            }
        }
    }
}

// ---------------- ctrl_in split-K 1xTF32, SW-PIPELINED ----------------
__global__ __launch_bounds__(256) void ctrlin_tc(const float* __restrict__ o,
                                                 const float* __restrict__ vel,
                                                 const float* __restrict__ Wc) {
    __shared__ unsigned As[128 * 36];
    __shared__ unsigned Bs[64 * 36];
    int sp = blockIdx.x;
    int m0 = blockIdx.y * 128;
    int kbase = sp * 256;
    const float* A = (kbase < DM) ? o : vel;
    int acol = (kbase < DM) ? kbase : kbase - DM;
    const float* B = Wc + (size_t)kbase * CHN;

    int tid = threadIdx.x;
    int lane = tid & 31, w = tid >> 5;
    int wm = w & 3, wn = w >> 2;
    int g = lane >> 2, c = lane & 3;
    int arow = tid >> 1, akc = (tid & 1) * 16;
    int bn = tid & 63, bk0 = (tid >> 6) * 8;

    float acc[2][4][4];
#pragma unroll
    for (int mf = 0; mf < 2; mf++)
#pragma unroll
        for (int nt = 0; nt < 4; nt++)
#pragma unroll
            for (int r = 0; r < 4; r++) acc[mf][nt][r] = 0.f;

    float a[16], b[8];
    {
        const float* ap = A + (size_t)(m0 + arow) * DM + acol + akc;
#pragma unroll
        for (int j = 0; j < 16; j += 4) {
            float4 t = *reinterpret_cast<const float4*>(ap + j);
            a[j] = t.x; a[j + 1] = t.y; a[j + 2] = t.z; a[j + 3] = t.w;
        }
        const float* bp = B + (size_t)bk0 * CHN + bn;
#pragma unroll
        for (int j = 0; j < 8; j++) b[j] = bp[(size_t)j * CHN];
    }

    for (int kk = 0; kk < 256; kk += 32) {
        __syncthreads();
        unsigned* apd = &As[arow * 36 + akc];
#pragma unroll
        for (int j = 0; j < 16; j++) apd[j] = f2tf(a[j]);
        unsigned* bpd = &Bs[bn * 36 + bk0];
#pragma unroll
        for (int j = 0; j < 8; j++) bpd[j] = f2tf(b[j]);
        __syncthreads();

        int nx = kk + 32;
        if (nx < 256) {
            const float* ap = A + (size_t)(m0 + arow) * DM + acol + nx + akc;
#pragma unroll
            for (int j = 0; j < 16; j += 4) {
                float4 t = *reinterpret_cast<const float4*>(ap + j);
                a[j] = t.x; a[j + 1] = t.y; a[j + 2] = t.z; a[j + 3] = t.w;
            }
            const float* bp = B + (size_t)(nx + bk0) * CHN + bn;
#pragma unroll
            for (int j = 0; j < 8; j++) b[j] = bp[(size_t)j * CHN];
        }

        tc1_mma_block(As, Bs, wm, wn, g, c, acc);
    }

    float* P = g_ctrlp + (size_t)sp * NTOK * CHN;
#pragma unroll
    for (int mf = 0; mf < 2; mf++) {
        int r0 = m0 + wm * 32 + mf * 16 + g;
#pragma unroll
        for (int nt = 0; nt < 4; nt++) {
            int col = wn * 32 + nt * 8 + 2 * c;
#pragma unroll
            for (int half = 0; half < 2; half++) {
                int row = r0 + half * 8;
                P[(size_t)row * CHN + col]     = acc[mf][nt][half * 2 + 0];
                P[(size_t)row * CHN + col + 1] = acc[mf][nt][half * 2 + 1];
            }
        }
    }
}

// combine ctrl partials (fixed order: deterministic)
__global__ void ctrl_combine_kernel(const float* __restrict__ bias) {
    int idx = blockIdx.x * 256 + threadIdx.x;
    int col = idx & (CHN - 1);
    float s = bias[col];
#pragma unroll
    for (int sp = 0; sp < CSPLIT; sp++) s += g_ctrlp[(size_t)sp * NTOK * CHN + idx];
    g_ctrl[idx] = s / (1.f + __expf(-s));
}

// ================= 3xTF32 tensor-core GEMM (wo only), SW-PIPELINED =================
struct TcTile {
    unsigned Ah[128 * 20];
    unsigned Al[128 * 20];
    unsigned Bh[64 * 20];
    unsigned Bl[64 * 20];
};

__device__ __forceinline__ void tc3_chunk(TcTile* s, int wm, int wn, int g, int c,
                                          float acc[2][4][4]) {
#pragma unroll
    for (int k8 = 0; k8 < 2; k8++) {
        int k0 = k8 * 8;
        unsigned ah[2][4], al[2][4];
#pragma unroll
        for (int mf = 0; mf < 2; mf++) {
            int rb = wm * 32 + mf * 16;
            ah[mf][0] = s->Ah[(rb + g) * 20 + k0 + c];
            ah[mf][1] = s->Ah[(rb + g + 8) * 20 + k0 + c];
            ah[mf][2] = s->Ah[(rb + g) * 20 + k0 + c + 4];
            ah[mf][3] = s->Ah[(rb + g + 8) * 20 + k0 + c + 4];
            al[mf][0] = s->Al[(rb + g) * 20 + k0 + c];
            al[mf][1] = s->Al[(rb + g + 8) * 20 + k0 + c];
            al[mf][2] = s->Al[(rb + g) * 20 + k0 + c + 4];
            al[mf][3] = s->Al[(rb + g + 8) * 20 + k0 + c + 4];
        }
#pragma unroll
        for (int nt = 0; nt < 4; nt++) {
            int nb = (wn * 32 + nt * 8 + g) * 20 + k0 + c;
            unsigned bh0 = s->Bh[nb], bh1 = s->Bh[nb + 4];
            unsigned bl0 = s->Bl[nb], bl1 = s->Bl[nb + 4];
#pragma unroll
            for (int mf = 0; mf < 2; mf++) {
                mma_tf32(acc[mf][nt][0], acc[mf][nt][1], acc[mf][nt][2], acc[mf][nt][3],
                         ah[mf][0], ah[mf][1], ah[mf][2], ah[mf][3], bh0, bh1);
                mma_tf32(acc[mf][nt][0], acc[mf][nt][1], acc[mf][nt][2], acc[mf][nt][3],
                         ah[mf][0], ah[mf][1], ah[mf][2], ah[mf][3], bl0, bl1);
                mma_tf32(acc[mf][nt][0], acc[mf][nt][1], acc[mf][nt][2], acc[mf][nt][3],
                         al[mf][0], al[mf][1], al[mf][2], al[mf][3], bh0, bh1);
            }
        }
    }
}

__global__ __launch_bounds__(256) void gemm3_tc(const float* __restrict__ A,
                                                const float* __restrict__ B,
                                                const float* __restrict__ bias,
                                                float* __restrict__ C, int Kd, int Nc, int epi) {
    __shared__ TcTile s;
    int m0 = blockIdx.y * 128, n0 = blockIdx.x * 64;
    int tid = threadIdx.x;
    int lane = tid & 31, w = tid >> 5;
    int wm = w & 3, wn = w >> 2;
    int g = lane >> 2, c = lane & 3;
    int arow = tid >> 1, akc = (tid & 1) * 8;
    int bn = tid & 63, bk0 = (tid >> 6) * 4;

    float acc[2][4][4];
#pragma unroll
    for (int mf = 0; mf < 2; mf++)
#pragma unroll
        for (int nt = 0; nt < 4; nt++)
#pragma unroll
            for (int r = 0; r < 4; r++) acc[mf][nt][r] = 0.f;

    float a[8], b[4];
    {
        const float* ap = A + (size_t)(m0 + arow) * Kd + akc;
#pragma unroll
        for (int j = 0; j < 8; j += 4) {
            float4 t = *reinterpret_cast<const float4*>(ap + j);
            a[j] = t.x; a[j + 1] = t.y; a[j + 2] = t.z; a[j + 3] = t.w;
        }
        const float* bp = B + (size_t)bk0 * Nc + n0 + bn;
#pragma unroll
        for (int j = 0; j < 4; j++) b[j] = bp[(size_t)j * Nc];
    }

    for (int kk = 0; kk < Kd; kk += 16) {
        __syncthreads();
        unsigned* ah = &s.Ah[arow * 20 + akc];
        unsigned* al = &s.Al[arow * 20 + akc];
#pragma unroll
        for (int j = 0; j < 8; j++) split_tf(a[j], ah[j], al[j]);
        unsigned* bh = &s.Bh[bn * 20 + bk0];
        unsigned* bl = &s.Bl[bn * 20 + bk0];
#pragma unroll
        for (int j = 0; j < 4; j++) split_tf(b[j], bh[j], bl[j]);
        __syncthreads();

        int nx = kk + 16;
        if (nx < Kd) {
            const float* ap = A + (size_t)(m0 + arow) * Kd + nx + akc;
#pragma unroll
            for (int j = 0; j < 8; j += 4) {
                float4 t = *reinterpret_cast<const float4*>(ap + j);
                a[j] = t.x; a[j + 1] = t.y; a[j + 2] = t.z; a[j + 3] = t.w;
            }
            const float* bp = B + (size_t)(nx + bk0) * Nc + n0 + bn;
#pragma unroll
            for (int j = 0; j < 4; j++) b[j] = bp[(size_t)j * Nc];
        }

        tc3_chunk(&s, wm, wn, g, c, acc);
    }

#pragma unroll
    for (int mf = 0; mf < 2; mf++) {
        int r0 = m0 + wm * 32 + mf * 16 + g;
#pragma unroll
        for (int nt = 0; nt < 4; nt++) {
            int col = n0 + wn * 32 + nt * 8 + 2 * c;
#pragma unroll
            for (int half = 0; half < 2; half++) {
                int row = r0 + half * 8;
                float v0 = acc[mf][nt][half * 2 + 0];
                float v1 = acc[mf][nt][half * 2 + 1];
                if (epi >= 1) { v0 += bias[col]; v1 += bias[col + 1]; }
                C[(size_t)row * Nc + col]     = v0;
                C[(size_t)row * Nc + col + 1] = v1;
            }
        }
    }
}

// ---------------- RoPE tables ----------------
__global__ void rope_table_kernel(const int* __restrict__ positions) {
    int idx = blockIdx.x * 64 + threadIdx.x;
    int i = idx & 31;
    int n = idx >> 5;
    float pos = (float)positions[n];
    float inv = (float)exp(-((double)(2 * i) / 64.0) * log(10000.0));
    float ang = pos * inv;
    g_cosT[idx] = cosf(ang);
    g_sinT[idx] = sinf(ang);
}

// warp-per-head qk norm + rope
__global__ void qknorm_rope2_kernel(const float* __restrict__ qw, const float* __restrict__ kw) {
    int n = blockIdx.x;
    int wid = threadIdx.x >> 5;
    int lane = threadIdx.x & 31;
    float* ptr;
    const float* wt;
    if (wid < NH) { ptr = g_q + (size_t)n * (NH * DHD) + wid * DHD; wt = qw; }
    else          { ptr = g_k + (size_t)n * (NKV * DHD) + (wid - NH) * DHD; wt = kw; }
    float x1 = ptr[lane];
    float x2 = ptr[lane + 32];
    float ss = x1 * x1 + x2 * x2;
#pragma unroll
    for (int o = 16; o > 0; o >>= 1) ss += __shfl_xor_sync(0xffffffffu, ss, o);
    float sc = rsqrtf(ss * (1.0f / DHD) + EPSV);
    float xn1 = x1 * sc * wt[lane];
    float xn2 = x2 * sc * wt[lane + 32];
    float cc = g_cosT[n * 32 + lane];
    float s  = g_sinT[n * 32 + lane];
    ptr[lane]      = xn1 * cc - xn2 * s;
    ptr[lane + 32] = xn2 * cc + xn1 * s;
}

// ================= tf32 tensor-core flash attention =================
#define ATTN_SMEM ((128 * 68 + 64 * 68 + 64 * 68 + 128 * 68) * 4)

__global__ __launch_bounds__(256) void attn_tc_kernel() {
    extern __shared__ unsigned asm_u[];
    unsigned* Qs = asm_u;
    unsigned* Ks = Qs + 128 * 68;
    unsigned* Vt = Ks + 64 * 68;
    unsigned* Ps = Vt + 64 * 68;

    int h = blockIdx.y;
    int q0 = blockIdx.x * 128;
    int kvh = h >> 2;
    int tid = threadIdx.x;
    int lane = tid & 31, w = tid >> 5;
    int g = lane >> 2, c = lane & 3;
    int qbase = w * 16;

    {
        int row = tid >> 1;
        int d0 = (tid & 1) * 32;
        const float* qp = g_q + ((size_t)(q0 + row) * NH + h) * DHD + d0;
        unsigned* dst = Qs + row * 68 + d0;
#pragma unroll
        for (int j = 0; j < 32; j += 4) {
            float4 t = *reinterpret_cast<const float4*>(qp + j);
            dst[j]     = f2tf(t.x * 0.125f);
            dst[j + 1] = f2tf(t.y * 0.125f);
            dst[j + 2] = f2tf(t.z * 0.125f);
            dst[j + 3] = f2tf(t.w * 0.125f);
        }
    }

    float oacc[8][4];
#pragma unroll
    for (int nt = 0; nt < 8; nt++)
#pragma unroll
        for (int r = 0; r < 4; r++) oacc[nt][r] = 0.f;
    float mrun0 = -1e30f, mrun1 = -1e30f, lrun0 = 0.f, lrun1 = 0.f;

    const int krow = tid >> 2;
    const int kd0 = (tid & 3) * 16;

    for (int kt = 0; kt < NTOK; kt += 64) {
        {
            const float* kp = g_k + ((size_t)(kt + krow) * NKV + kvh) * DHD + kd0;
            unsigned* dst = Ks + krow * 68 + kd0;
#pragma unroll
            for (int j = 0; j < 16; j += 4) {
                float4 t = *reinterpret_cast<const float4*>(kp + j);
                dst[j] = f2tf(t.x); dst[j + 1] = f2tf(t.y);
                dst[j + 2] = f2tf(t.z); dst[j + 3] = f2tf(t.w);
            }
            const float* vp = g_v + ((size_t)(kt + krow) * NKV + kvh) * DHD + kd0;
#pragma unroll
            for (int j = 0; j < 16; j += 4) {
                float4 t = *reinterpret_cast<const float4*>(vp + j);
                Vt[(kd0 + j)     * 68 + krow] = f2tf(t.x);
                Vt[(kd0 + j + 1) * 68 + krow] = f2tf(t.y);
                Vt[(kd0 + j + 2) * 68 + krow] = f2tf(t.z);
                Vt[(kd0 + j + 3) * 68 + krow] = f2tf(t.w);
            }
        }
        __syncthreads();

        float sacc[8][4];
#pragma unroll
        for (int nt = 0; nt < 8; nt++)
#pragma unroll
            for (int r = 0; r < 4; r++) sacc[nt][r] = 0.f;
#pragma unroll
        for (int k8 = 0; k8 < 8; k8++) {
            int k0 = k8 * 8;
            unsigned a0 = Qs[(qbase + g) * 68 + k0 + c];
            unsigned a1 = Qs[(qbase + g + 8) * 68 + k0 + c];
            unsigned a2 = Qs[(qbase + g) * 68 + k0 + c + 4];
            unsigned a3 = Qs[(qbase + g + 8) * 68 + k0 + c + 4];
#pragma unroll
            for (int nt = 0; nt < 8; nt++) {
                int nb = (nt * 8 + g) * 68 + k0 + c;
                mma_tf32(sacc[nt][0], sacc[nt][1], sacc[nt][2], sacc[nt][3],
                         a0, a1, a2, a3, Ks[nb], Ks[nb + 4]);
            }
        }

        float mx0 = -1e30f, mx1 = -1e30f;
#pragma unroll
        for (int nt = 0; nt < 8; nt++) {
            mx0 = fmaxf(mx0, fmaxf(sacc[nt][0], sacc[nt][1]));
            mx1 = fmaxf(mx1, fmaxf(sacc[nt][2], sacc[nt][3]));
        }
        mx0 = fmaxf(mx0, __shfl_xor_sync(0xffffffffu, mx0, 1));
        mx0 = fmaxf(mx0, __shfl_xor_sync(0xffffffffu, mx0, 2));
        mx1 = fmaxf(mx1, __shfl_xor_sync(0xffffffffu, mx1, 1));
        mx1 = fmaxf(mx1, __shfl_xor_sync(0xffffffffu, mx1, 2));
        float mn0 = fmaxf(mrun0, mx0);
        float mn1 = fmaxf(mrun1, mx1);
        float corr0 = __expf(mrun0 - mn0);
        float corr1 = __expf(mrun1 - mn1);
#pragma unroll
        for (int nt = 0; nt < 8; nt++) {
            oacc[nt][0] *= corr0; oacc[nt][1] *= corr0;
            oacc[nt][2] *= corr1; oacc[nt][3] *= corr1;
        }
        float ps0 = 0.f, ps1 = 0.f;
#pragma unroll
        for (int nt = 0; nt < 8; nt++) {
            float p00 = __expf(sacc[nt][0] - mn0);
            float p01 = __expf(sacc[nt][1] - mn0);
            float p10 = __expf(sacc[nt][2] - mn1);
            float p11 = __expf(sacc[nt][3] - mn1);
            ps0 += p00 + p01;
            ps1 += p10 + p11;
            int colb = nt * 8 + 2 * c;
            uint2 v0; v0.x = f2tf(p00); v0.y = f2tf(p01);
            uint2 v1; v1.x = f2tf(p10); v1.y = f2tf(p11);
            *reinterpret_cast<uint2*>(&Ps[(qbase + g) * 68 + colb])     = v0;
            *reinterpret_cast<uint2*>(&Ps[(qbase + g + 8) * 68 + colb]) = v1;
        }
        ps0 += __shfl_xor_sync(0xffffffffu, ps0, 1);
        ps0 += __shfl_xor_sync(0xffffffffu, ps0, 2);
        ps1 += __shfl_xor_sync(0xffffffffu, ps1, 1);
        ps1 += __shfl_xor_sync(0xffffffffu, ps1, 2);
        lrun0 = lrun0 * corr0 + ps0;
        lrun1 = lrun1 * corr1 + ps1;
        mrun0 = mn0;
        mrun1 = mn1;
        __syncwarp();

#pragma unroll
        for (int k8 = 0; k8 < 8; k8++) {
            int k0 = k8 * 8;
            unsigned a0 = Ps[(qbase + g) * 68 + k0 + c];
            unsigned a1 = Ps[(qbase + g + 8) * 68 + k0 + c];
            unsigned a2 = Ps[(qbase + g) * 68 + k0 + c + 4];
            unsigned a3 = Ps[(qbase + g + 8) * 68 + k0 + c + 4];
#pragma unroll
            for (int nt = 0; nt < 8; nt++) {
                int nb = (nt * 8 + g) * 68 + k0 + c;
                mma_tf32(oacc[nt][0], oacc[nt][1], oacc[nt][2], oacc[nt][3],
                         a0, a1, a2, a3, Vt[nb], Vt[nb + 4]);
            }
        }
        __syncthreads();
    }

    float rl0 = 1.f / lrun0;
    float rl1 = 1.f / lrun1;
    float* o0 = g_oh + ((size_t)(q0 + qbase + g) * NH + h) * DHD;
    float* o1 = g_oh + ((size_t)(q0 + qbase + g + 8) * NH + h) * DHD;
#pragma unroll
    for (int nt = 0; nt < 8; nt++) {
        int colb = nt * 8 + 2 * c;
        *reinterpret_cast<float2*>(o0 + colb) = make_float2(oacc[nt][0] * rl0, oacc[nt][1] * rl0);
        *reinterpret_cast<float2*>(o1 + colb) = make_float2(oacc[nt][2] * rl1, oacc[nt][3] * rl1);
    }
}

// ---------------- control dynamics elementwise ----------------
__global__ void dynamics_kernel(const float* __restrict__ hidden, const float* __restrict__ velocity,
                                const float* __restrict__ mu, float* __restrict__ out_h2,
                                float* __restrict__ out_vn) {
    int idx = blockIdx.x * 256 + threadIdx.x;
    int n = idx >> 10;
    int d = idx & 1023;
    const float* co = g_co + (size_t)n * 3 * DM;
    float ar = co[d], br = co[DM + d], gr = co[2 * DM + d];
    float alpha = 1.f / (1.f + expf(-ar));
    float sp = fmaxf(br, 0.f) + log1pf(expf(-fabsf(br)));
    float beta = fminf(sp, 2.f);
    float gate = 1.f / (1.f + expf(-gr));
    float o = g_o[idx], mv = mu[idx], vel = velocity[idx];
    float vn = alpha * vel - beta * (o - mv);
    vn = fminf(fmaxf(vn, -10.f), 10.f);
    out_h2[idx] = hidden[idx] + o + 0.1f * gate * vn;
    out_vn[idx] = vn;
}

// ---------------- router (UNCHANGED: summation order is routing-critical) ----------------
__global__ void zero_cnt_kernel() {
    if (threadIdx.x < NEXP) g_cnt[threadIdx.x] = 0;
}

__global__ void router_kernel(const float* __restrict__ mu, const int* __restrict__ token_ids,
                              const float* __restrict__ Wr) {
    int tid = threadIdx.x;
    int tl = tid >> 3, e = tid & 7;
    int n = blockIdx.x * 32 + tl;
    const float* mr = mu + (size_t)n * DM;
    float s = 0.f;
    for (int d = 0; d < DM; d++) s += mr[d] * Wr[d * NEXP + e];
    __shared__ float lg[32][8];
    lg[tl][e] = s;
    __syncthreads();
    if (e == 0) {
        int base = token_ids[n] % NEXP;
        float best = -1e30f;
        int bi = 0;
#pragma unroll
        for (int j = 0; j < 8; j++) {
            float c = lg[tl][j] + (j == base ? 10.0f : 0.0f);
            if (c > best) { best = c; bi = j; }
        }
        int slot = atomicAdd(&g_cnt[bi], 1);
        g_toklist[bi * NTOK + slot] = n;
    }
}

// ================= 1x tf32 tensor-core MoE, SW-PIPELINED =================
__global__ __launch_bounds__(256) void moe_gateup_tc(const float* __restrict__ X,
                                                     const float* __restrict__ Wg,
                                                     const float* __restrict__ Wu) {
    int e = blockIdx.z;
    int count = g_cnt[e];
    int m0 = blockIdx.y * 128;
    if (m0 >= count) return;
    int f0 = blockIdx.x * 64;

    __shared__ int toks[128];
    __shared__ unsigned As[128 * 36];
    __shared__ unsigned Bg[64 * 36];
    __shared__ unsigned Bu[64 * 36];

    int tid = threadIdx.x;
    int lane = tid & 31, w = tid >> 5;
    int wm = w & 3, wn = w >> 2;
    int g = lane >> 2, c = lane & 3;

    if (tid < 128) toks[tid] = (m0 + tid < count) ? g_toklist[e * NTOK + m0 + tid] : -1;
    __syncthreads();

    const float* WgE = Wg + (size_t)e * DM * FF;
    const float* WuE = Wu + (size_t)e * DM * FF;

    int arow = tid >> 1, akc = (tid & 1) * 16;
    int bn = tid & 63, bk0 = (tid >> 6) * 8;
    int tokA = toks[arow];
    const float* Aptr = (tokA >= 0) ? X + (size_t)tokA * DM + akc : X;

    float acg[2][4][4], acu[2][4][4];
#pragma unroll
    for (int mf = 0; mf < 2; mf++)
#pragma unroll
        for (int nt = 0; nt < 4; nt++)
#pragma unroll
            for (int r = 0; r < 4; r++) { acg[mf][nt][r] = 0.f; acu[mf][nt][r] = 0.f; }

    float a[16], bg[8], bu[8];
    // prologue load kk = 0
    {
        if (tokA >= 0) {
#pragma unroll
            for (int j = 0; j < 16; j += 4) {
                float4 t = *reinterpret_cast<const float4*>(Aptr + j);
                a[j] = t.x; a[j + 1] = t.y; a[j + 2] = t.z; a[j + 3] = t.w;
            }
        } else {
#pragma unroll
            for (int j = 0; j < 16; j++) a[j] = 0.f;
        }
        const float* bgp = WgE + (size_t)bk0 * FF + f0 + bn;
        const float* bup = WuE + (size_t)bk0 * FF + f0 + bn;
#pragma unroll
        for (int j = 0; j < 8; j++) { bg[j] = bgp[(size_t)j * FF]; bu[j] = bup[(size_t)j * FF]; }
    }

    for (int kk = 0; kk < DM; kk += 32) {
        __syncthreads();
        unsigned* ap = &As[arow * 36 + akc];
#pragma unroll
        for (int j = 0; j < 16; j++) ap[j] = f2tf(a[j]);
        unsigned* gp = &Bg[bn * 36 + bk0];
        unsigned* up = &Bu[bn * 36 + bk0];
#pragma unroll
        for (int j = 0; j < 8; j++) { gp[j] = f2tf(bg[j]); up[j] = f2tf(bu[j]); }
        __syncthreads();

        int nx = kk + 32;
        if (nx < DM) {
            if (tokA >= 0) {
#pragma unroll
                for (int j = 0; j < 16; j += 4) {
                    float4 t = *reinterpret_cast<const float4*>(Aptr + nx + j);
                    a[j] = t.x; a[j + 1] = t.y; a[j + 2] = t.z; a[j + 3] = t.w;
                }
            }
            const float* bgp = WgE + (size_t)(nx + bk0) * FF + f0 + bn;
            const float* bup = WuE + (size_t)(nx + bk0) * FF + f0 + bn;
#pragma unroll
            for (int j = 0; j < 8; j++) { bg[j] = bgp[(size_t)j * FF]; bu[j] = bup[(size_t)j * FF]; }
        }

#pragma unroll
        for (int k8 = 0; k8 < 4; k8++) {
            int k0 = k8 * 8;
            unsigned af[2][4];
#pragma unroll
            for (int mf = 0; mf < 2; mf++) {
                int rb = wm * 32 + mf * 16;
                af[mf][0] = As[(rb + g) * 36 + k0 + c];
                af[mf][1] = As[(rb + g + 8) * 36 + k0 + c];
                af[mf][2] = As[(rb + g) * 36 + k0 + c + 4];
                af[mf][3] = As[(rb + g + 8) * 36 + k0 + c + 4];
            }
#pragma unroll
            for (int nt = 0; nt < 4; nt++) {
                int nb = (wn * 32 + nt * 8 + g) * 36 + k0 + c;
                unsigned b0 = Bg[nb], b1 = Bg[nb + 4];
                mma_tf32(acg[0][nt][0], acg[0][nt][1], acg[0][nt][2], acg[0][nt][3],
                         af[0][0], af[0][1], af[0][2], af[0][3], b0, b1);
                mma_tf32(acg[1][nt][0], acg[1][nt][1], acg[1][nt][2], acg[1][nt][3],
                         af[1][0], af[1][1], af[1][2], af[1][3], b0, b1);
                unsigned u0 = Bu[nb], u1 = Bu[nb + 4];
                mma_tf32(acu[0][nt][0], acu[0][nt][1], acu[0][nt][2], acu[0][nt][3],
                         af[0][0], af[0][1], af[0][2], af[0][3], u0, u1);
                mma_tf32(acu[1][nt][0], acu[1][nt][1], acu[1][nt][2], acu[1][nt][3],
                         af[1][0], af[1][1], af[1][2], af[1][3], u0, u1);
            }
        }
    }

#pragma unroll
    for (int mf = 0; mf < 2; mf++) {
        int r0 = wm * 32 + mf * 16 + g;
        int t0 = toks[r0], t1 = toks[r0 + 8];
#pragma unroll
        for (int nt = 0; nt < 4; nt++) {
            int col = f0 + wn * 32 + nt * 8 + 2 * c;
            if (t0 >= 0) {
                float gv = acg[mf][nt][0], uv = acu[mf][nt][0];
                g_mid[(size_t)t0 * FF + col] = (gv / (1.f + __expf(-gv))) * uv;
                gv = acg[mf][nt][1]; uv = acu[mf][nt][1];
                g_mid[(size_t)t0 * FF + col + 1] = (gv / (1.f + __expf(-gv))) * uv;
            }
            if (t1 >= 0) {
                float gv = acg[mf][nt][2], uv = acu[mf][nt][2];
                g_mid[(size_t)t1 * FF + col] = (gv / (1.f + __expf(-gv))) * uv;
                gv = acg[mf][nt][3]; uv = acu[mf][nt][3];
                g_mid[(size_t)t1 * FF + col + 1] = (gv / (1.f + __expf(-gv))) * uv;
            }
        }
    }
}

__global__ __launch_bounds__(256) void moe_down_tc(const float* __restrict__ Wd,
                                                   float* __restrict__ out) {
    int e = blockIdx.z;
    int count = g_cnt[e];
    int m0 = blockIdx.y * 128;
    if (m0 >= count) return;
    int d0 = blockIdx.x * 64;

    __shared__ int toks[128];
    __shared__ unsigned As[128 * 36];
    __shared__ unsigned Bs[64 * 36];

    int tid = threadIdx.x;
    int lane = tid & 31, w = tid >> 5;
    int wm = w & 3, wn = w >> 2;
    int g = lane >> 2, c = lane & 3;

    if (tid < 128) toks[tid] = (m0 + tid < count) ? g_toklist[e * NTOK + m0 + tid] : -1;
    __syncthreads();

    const float* WdE = Wd + (size_t)e * FF * DM;
    int arow = tid >> 1, akc = (tid & 1) * 16;
    int bn = tid & 63, bk0 = (tid >> 6) * 8;
    int tokA = toks[arow];
    const float* Aptr = (tokA >= 0) ? g_mid + (size_t)tokA * FF + akc : g_mid;

    float acc[2][4][4];
#pragma unroll
    for (int mf = 0; mf < 2; mf++)
#pragma unroll
        for (int nt = 0; nt < 4; nt++)
#pragma unroll
            for (int r = 0; r < 4; r++) acc[mf][nt][r] = 0.f;

    float a[16], b[8];
    {
        if (tokA >= 0) {
#pragma unroll
            for (int j = 0; j < 16; j += 4) {
                float4 t = *reinterpret_cast<const float4*>(Aptr + j);
                a[j] = t.x; a[j + 1] = t.y; a[j + 2] = t.z; a[j + 3] = t.w;
            }
        } else {
#pragma unroll
            for (int j = 0; j < 16; j++) a[j] = 0.f;
        }
        const float* bp = WdE + (size_t)bk0 * DM + d0 + bn;
#pragma unroll
        for (int j = 0; j < 8; j++) b[j] = bp[(size_t)j * DM];
    }

    for (int kk = 0; kk < FF; kk += 32) {
        __syncthreads();
        unsigned* ap = &As[arow * 36 + akc];
#pragma unroll
        for (int j = 0; j < 16; j++) ap[j] = f2tf(a[j]);
        unsigned* bpp = &Bs[bn * 36 + bk0];
#pragma unroll
        for (int j = 0; j < 8; j++) bpp[j] = f2tf(b[j]);
        __syncthreads();

        int nx = kk + 32;
        if (nx < FF) {
            if (tokA >= 0) {
#pragma unroll
                for (int j = 0; j < 16; j += 4) {
                    float4 t = *reinterpret_cast<const float4*>(Aptr + nx + j);
                    a[j] = t.x; a[j + 1] = t.y; a[j + 2] = t.z; a[j + 3] = t.w;
                }
            }
            const float* bp = WdE + (size_t)(nx + bk0) * DM + d0 + bn;
#pragma unroll
            for (int j = 0; j < 8; j++) b[j] = bp[(size_t)j * DM];
        }

#pragma unroll
        for (int k8 = 0; k8 < 4; k8++) {
            int k0 = k8 * 8;
            unsigned af[2][4];
#pragma unroll
            for (int mf = 0; mf < 2; mf++) {
                int rb = wm * 32 + mf * 16;
                af[mf][0] = As[(rb + g) * 36 + k0 + c];
                af[mf][1] = As[(rb + g + 8) * 36 + k0 + c];
                af[mf][2] = As[(rb + g) * 36 + k0 + c + 4];
                af[mf][3] = As[(rb + g + 8) * 36 + k0 + c + 4];
            }
#pragma unroll
            for (int nt = 0; nt < 4; nt++) {
                int nb = (wn * 32 + nt * 8 + g) * 36 + k0 + c;
                unsigned b0 = Bs[nb], b1 = Bs[nb + 4];
                mma_tf32(acc[0][nt][0], acc[0][nt][1], acc[0][nt][2], acc[0][nt][3],
                         af[0][0], af[0][1], af[0][2], af[0][3], b0, b1);
                mma_tf32(acc[1][nt][0], acc[1][nt][1], acc[1][nt][2], acc[1][nt][3],
                         af[1][0], af[1][1], af[1][2], af[1][3], b0, b1);
            }
        }
    }

#pragma unroll
    for (int mf = 0; mf < 2; mf++) {
        int r0 = wm * 32 + mf * 16 + g;
        int t0 = toks[r0], t1 = toks[r0 + 8];
#pragma unroll
        for (int nt = 0; nt < 4; nt++) {
            int col = d0 + wn * 32 + nt * 8 + 2 * c;
            if (t0 >= 0) {
                out[(size_t)t0 * DM + col]     += acc[mf][nt][0];
                out[(size_t)t0 * DM + col + 1] += acc[mf][nt][1];
            }
            if (t1 >= 0) {
                out[(size_t)t1 * DM + col]     += acc[mf][nt][2];
                out[(size_t)t1 * DM + col + 1] += acc[mf][nt][3];
            }
        }
    }
}

// ---------------- host orchestration ----------------
extern "C" void kernel_launch(void* const* d_in, const int* in_sizes, int n_in,
                              void* d_out, int out_size) {
    const float* hidden     = (const float*)d_in[0];
    const int*   positions  = (const int*)d_in[1];
    const float* velocity   = (const float*)d_in[2];
    const int*   token_ids  = (const int*)d_in[3];
    const float* mu_prev    = (const float*)d_in[4];
    const float* ln1_w      = (const float*)d_in[5];
    const float* ln2_w      = (const float*)d_in[6];
    const float* wq         = (const float*)d_in[7];
    const float* wk         = (const float*)d_in[8];
    const float* wv         = (const float*)d_in[9];
    const float* wo_w       = (const float*)d_in[10];
    const float* w_mu_q     = (const float*)d_in[11];
    const float* w_mu_k     = (const float*)d_in[12];
    const float* w_mu_v     = (const float*)d_in[13];
    const float* qnorm_w    = (const float*)d_in[14];
    const float* knorm_w    = (const float*)d_in[15];
    const float* dyn_mu     = (const float*)d_in[16];
    const float* dyn_proj   = (const float*)d_in[17];
    const float* ctrl_in_w  = (const float*)d_in[18];
    const float* ctrl_in_b  = (const float*)d_in[19];
    const float* ctrl_out_w = (const float*)d_in[20];
    const float* ctrl_out_b = (const float*)d_in[21];
    const float* mu_router  = (const float*)d_in[22];
    const float* w_gate     = (const float*)d_in[23];
    const float* w_up       = (const float*)d_in[24];
    const float* w_down     = (const float*)d_in[25];

    float* out    = (float*)d_out;
    float* out_h  = out;
    float* out_vn = out + (size_t)NTOK * DM;
    float* out_mu = out + 2 * (size_t)NTOK * DM;

    float *p_h1, *p_oh, *p_o, *p_ctrl, *p_co, *p_x2;
    cudaGetSymbolAddress((void**)&p_h1, g_h1);
    cudaGetSymbolAddress((void**)&p_oh, g_oh);
    cudaGetSymbolAddress((void**)&p_o, g_o);
    cudaGetSymbolAddress((void**)&p_ctrl, g_ctrl);
    cudaGetSymbolAddress((void**)&p_co, g_co);
    cudaGetSymbolAddress((void**)&p_x2, g_x2);

    cudaFuncSetAttribute(attn_tc_kernel, cudaFuncAttributeMaxDynamicSharedMemorySize, ATTN_SMEM);

    // 0. rope tables
    rope_table_kernel<<<(NTOK * 32) / 64, 64>>>(positions);

    // 1. h = rmsnorm(hidden, ln1_w)
    rmsnorm_kernel<<<NTOK, 256>>>(hidden, ln1_w, p_h1);

    // 2. fully fused qkv, 1xTF32 pipelined
    qkv1_tc<<<dim3(24, NTOK / 128), 256>>>(p_h1, mu_prev, wq, w_mu_q, wk, w_mu_k, wv, w_mu_v);

    // 3. per-head rmsnorm + RoPE
    qknorm_rope2_kernel<<<NTOK, (NH + NKV) * 32>>>(qnorm_w, knorm_w);

    // 4. tensor-core flash attention
    attn_tc_kernel<<<dim3(NTOK / 128, NH), 256, ATTN_SMEM>>>();

    // 5. o = oh @ wo (3xTF32 pipelined: o-path precision protected)
    gemm3_tc<<<dim3(DM / 64, NTOK / 128), 256>>>(p_oh, wo_w, nullptr, p_o, NH * DHD, DM, 0);

    // 6. mu_cur = dyn_mu + o @ dyn_mu_proj_w (1xTF32 pipelined)
    gemm1_tc<<<dim3(DM / 64, NTOK / 128), 256>>>(p_o, dyn_proj, dyn_mu, out_mu, DM, DM, 1);

    // 7. ctrl: split-K tc pipelined + deterministic combine
    ctrlin_tc<<<dim3(CSPLIT, NTOK / 128), 256>>>(p_o, velocity, ctrl_in_w);
    ctrl_combine_kernel<<<(NTOK * CHN) / 256, 256>>>(ctrl_in_b);

    // 8. co = ctrl @ ctrl_out_w + ctrl_out_b
    gemm1_tc<<<dim3((3 * DM) / 64, NTOK / 128), 256>>>(p_ctrl, ctrl_out_w, ctrl_out_b,
                                                       p_co, CHN, 3 * DM, 1);

    // 9. dynamics
    dynamics_kernel<<<(NTOK * DM) / 256, 256>>>(hidden, velocity, out_mu, out_h, out_vn);

    // 10. x = rmsnorm(hidden2, ln2_w)
    rmsnorm_kernel<<<NTOK, 256>>>(out_h, ln2_w, p_x2);

    // 11. routing (summation order frozen — routing-critical)
    zero_cnt_kernel<<<1, 32>>>();
    router_kernel<<<NTOK / 32, 256>>>(out_mu, token_ids, mu_router);

    // 12. MoE (1x tf32 pipelined)
    moe_gateup_tc<<<dim3(FF / 64, NTOK / 128, NEXP), 256>>>(p_x2, w_gate, w_up);
    moe_down_tc<<<dim3(DM / 64, NTOK / 128, NEXP), 256>>>(w_down, out_h);
}